// round 8
// baseline (speedup 1.0000x reference)
#include <cuda_runtime.h>
#include <math.h>

#define NT   4096
#define NAr  4096
#define NSr  1024
#define NALL 9216
#define FEAT 128
#define COM  64
#define MPD  64
#define NCLS 3
#define CAP  128   // max nnz per adjacency row (expected ~20, p=0.005)

// ---------------- static device scratch (no allocations allowed) -------------
__device__ float g_big[7ll * NT * NT];

// XN buffers hold transposed normalized features: XNt[k][row], ld = N
#define OFF_XN0   0
#define OFF_XN1   (OFF_XN0  + NT*256)
#define OFF_XN2   (OFF_XN1  + NT*256)
#define OFF_XN3   (OFF_XN2  + NT*256)
#define OFF_XN4   (OFF_XN3  + NT*256)
#define OFF_SIMS  (OFF_XN4  + NT*256)       // 1024*1024
#define OFF_FPA   (OFF_SIMS + NSr*NSr)      // 4096*128
#define OFF_FPS   (OFF_FPA  + NT*FEAT)      // 4096*128
#define OFF_THA   (OFF_FPS  + NT*FEAT)      // 4096*64
#define OFF_THS   (OFF_THA  + NT*COM)       // 4096*64
#define OFF_SWA   (OFF_THS  + NT*COM)       // 4096*64
#define OFF_SWS   (OFF_SWA  + NT*COM)       // 1024*64
#define OFF_H0    (OFF_SWS  + NSr*COM)      // 4096*64
#define OFF_X1    (OFF_H0   + NT*COM)       // 4096*64
#define OFF_H2    (OFF_X1   + NT*COM)       // 4096*3
#define OFF_CS    (OFF_H2   + NT*NCLS)      // 7*4096
#define OFF_COEF  (OFF_CS   + 7*NT)         // 7*4096
#define OFF_CT0   (OFF_COEF + 7*NT)         // 4096
#define OFF_CT    (OFF_CT0  + NT)           // 4096
#define OFF_ROWP  (OFF_CT   + NT)           // 4096*4
#define OFF_CSP   (OFF_ROWP + 4*NT)         // 7*32*4096
#define OFF_SPART (OFF_CSP  + 7*32*NT)      // 8*4096*64
#define SMALL_TOT (OFF_SPART + 8*NT*64)
__device__ float g_small[SMALL_TOT];

#define OFF_IDXA 0
#define OFF_CNTA (OFF_IDXA + NT*CAP)
#define OFF_IDXS (OFF_CNTA + NT)
#define OFF_CNTS (OFF_IDXS + NT*CAP)
#define IBUF_TOT (OFF_CNTS + NT)
__device__ int g_ibuf[IBUF_TOT];

// ---------------- packed f32x2 helpers (bit-identical IEEE fp32 per lane) ----
typedef unsigned long long u64t;

__device__ __forceinline__ u64t bcast2(float a)
{
    u64t r;
    asm("mov.b64 %0, {%1, %1};" : "=l"(r) : "r"(__float_as_uint(a)));
    return r;
}
__device__ __forceinline__ void fma2(u64t& acc, u64t a, u64t b)
{
    asm("fma.rn.f32x2 %0, %1, %2, %0;" : "+l"(acc) : "l"(a), "l"(b));
}
__device__ __forceinline__ float2 unpack2(u64t v)
{
    unsigned int lo, hi;
    asm("mov.b64 {%0, %1}, %2;" : "=r"(lo), "=r"(hi) : "l"(v));
    return make_float2(__uint_as_float(lo), __uint_as_float(hi));
}

// ---------------- cp.async helpers ----------------
__device__ __forceinline__ void cp16(unsigned int dst, const void* src)
{
    asm volatile("cp.async.cg.shared.global [%0], [%1], 16;" :: "r"(dst), "l"(src));
}
__device__ __forceinline__ void cp_commit() { asm volatile("cp.async.commit_group;"); }
__device__ __forceinline__ void cp_wait0()  { asm volatile("cp.async.wait_group 0;" ::: "memory"); }

// ---------------- kernels ----------------------------------------------------

// Per-head weighted + L2-row-normalized features, stored TRANSPOSED:
// dst[(h*D+d)*N + row]. Values bit-identical to the row-major variant.
__global__ void prep_norm_T_kernel(const float* __restrict__ src, const float* __restrict__ w,
                                   float* __restrict__ dst, int N, int D, int H)
{
    __shared__ float tile[32][257];
    int row0 = blockIdx.x * 32;
    int wp = threadIdx.x >> 5, lane = threadIdx.x & 31;
    int HD = H * D;
    for (int r = wp; r < 32; r += 8) {
        int row = row0 + r;
        for (int h = 0; h < H; h++) {
            float ss = 0.f;
            for (int d = lane; d < D; d += 32) {
                float v = src[(size_t)row * D + d] * w[h * D + d];
                ss += v * v;
            }
            #pragma unroll
            for (int o = 16; o; o >>= 1) ss += __shfl_xor_sync(0xffffffffu, ss, o);
            float inv = 1.f / fmaxf(sqrtf(ss), 1e-12f);
            for (int d = lane; d < D; d += 32)
                tile[r][h * D + d] = src[(size_t)row * D + d] * w[h * D + d] * inv;
        }
    }
    __syncthreads();
    for (int d = wp; d < HD; d += 8)
        dst[(size_t)d * N + row0 + lane] = tile[lane][d];
}

__device__ __forceinline__ float thrf(float v, float scale, float th)
{
    v *= scale;
    return (v < th) ? 0.f : v;
}

// Batched C = threshold(scale * X @ X^T) from TRANSPOSED X (Xt[k][row], ld=N).
// blockIdx.y selects pointer set. Triangular grid over blockIdx.x.
// cp.async double-buffered smem; f32x2 FMA; 3 CTAs/SM target.
// Each thread copies 2x16B per operand per stage -> full 16x128 tile (8KB).
__global__ void __launch_bounds__(256, 3)
simgemm_kernel(const float* __restrict__ Xt0, float* __restrict__ C0, float* __restrict__ cs0,
               const float* __restrict__ Xt1, float* __restrict__ C1, float* __restrict__ cs1,
               int N, int K, float scale, float th, int nBlk)
{
    const float* Xt    = blockIdx.y ? Xt1 : Xt0;
    float* C           = blockIdx.y ? C1  : C0;
    float* csPart      = blockIdx.y ? cs1 : cs0;

    int idx = blockIdx.x;
    float nb2 = nBlk + 0.5f;
    int by = (int)(nb2 - sqrtf(fmaxf(nb2 * nb2 - 2.0f * idx, 0.f)));
    if (by < 0) by = 0;
    if (by > nBlk - 1) by = nBlk - 1;
    while (by > 0 && (by * nBlk - (by * (by - 1)) / 2) > idx) by--;
    while (((by + 1) * nBlk - ((by + 1) * by) / 2) <= idx) by++;
    int bx = by + (idx - (by * nBlk - (by * (by - 1)) / 2));

    const int m0 = by * 128, n0 = bx * 128;

    __shared__ float As[2][16][128];
    __shared__ float Bs[2][16][128];

    const int tid = threadIdx.x;
    const int kk  = tid >> 4;            // 0..15 : k-row within stage
    const int cc  = tid & 15;            // 0..15 : 16B chunk (covers floats 0..63; +64 for upper half)
    const int wrp = tid >> 5;
    const int ln  = tid & 31;
    const int ty  = ((wrp >> 1) << 2) | (ln >> 3);   // 0..15
    const int tx  = ((wrp & 1) << 3) | (ln & 7);     // 0..15
    const int ry  = ty << 3;
    const int rx  = tx << 3;

    unsigned int sA = (unsigned int)__cvta_generic_to_shared(&As[0][0][0]);
    unsigned int sB = (unsigned int)__cvta_generic_to_shared(&Bs[0][0][0]);
    const unsigned int dOff = (kk * 128 + 4 * cc) * 4;
    const float* srcA = Xt + (size_t)kk * N + m0 + 4 * cc;
    const float* srcB = Xt + (size_t)kk * N + n0 + 4 * cc;
    const size_t stepK = (size_t)16 * N;

    u64t acc2[8][4];
    #pragma unroll
    for (int i = 0; i < 8; i++)
        #pragma unroll
        for (int j = 0; j < 4; j++) acc2[i][j] = 0ull;

#define ISSUE(bf, s) {                                                          \
    const float* _a = srcA + (size_t)(s) * stepK;                               \
    const float* _b = srcB + (size_t)(s) * stepK;                               \
    cp16(sA + (bf) * 8192 + dOff,       _a);                                    \
    cp16(sA + (bf) * 8192 + dOff + 256, _a + 64);                               \
    cp16(sB + (bf) * 8192 + dOff,       _b);                                    \
    cp16(sB + (bf) * 8192 + dOff + 256, _b + 64);                               \
    cp_commit(); }

#define COMPUTE(bf) {                                                           \
    _Pragma("unroll")                                                           \
    for (int k = 0; k < 16; k++) {                                              \
        float4 av0 = *(const float4*)&As[bf][k][ry];                            \
        float4 av1 = *(const float4*)&As[bf][k][ry + 4];                        \
        float4 bv0 = *(const float4*)&Bs[bf][k][rx];                            \
        float4 bv1 = *(const float4*)&Bs[bf][k][rx + 4];                        \
        u64t bp[4];                                                             \
        bp[0] = ((const u64t*)&bv0)[0]; bp[1] = ((const u64t*)&bv0)[1];         \
        bp[2] = ((const u64t*)&bv1)[0]; bp[3] = ((const u64t*)&bv1)[1];         \
        float a[8] = {av0.x,av0.y,av0.z,av0.w,av1.x,av1.y,av1.z,av1.w};         \
        _Pragma("unroll")                                                       \
        for (int i = 0; i < 8; i++) {                                           \
            u64t ai = bcast2(a[i]);                                             \
            fma2(acc2[i][0], ai, bp[0]);                                        \
            fma2(acc2[i][1], ai, bp[1]);                                        \
            fma2(acc2[i][2], ai, bp[2]);                                        \
            fma2(acc2[i][3], ai, bp[3]);                                        \
        }                                                                       \
    } }

    const int S = K >> 4;
    ISSUE(0, 0);
    cp_wait0();
    __syncthreads();
    int buf = 0;
    for (int s = 1; s < S; s++) {
        ISSUE(buf ^ 1, s);
        COMPUTE(buf);
        cp_wait0();
        __syncthreads();
        buf ^= 1;
    }
    COMPUTE(buf);

#undef ISSUE
#undef COMPUTE

    float acc[8][8];
    #pragma unroll
    for (int i = 0; i < 8; i++)
        #pragma unroll
        for (int jp = 0; jp < 4; jp++) {
            float2 v = unpack2(acc2[i][jp]);
            acc[i][2 * jp + 0] = thrf(v.x, scale, th);
            acc[i][2 * jp + 1] = thrf(v.y, scale, th);
        }

    #pragma unroll
    for (int i = 0; i < 8; i++) {
        #pragma unroll
        for (int j = 0; j < 8; j += 4) {
            float4 v = make_float4(acc[i][j], acc[i][j+1], acc[i][j+2], acc[i][j+3]);
            *(float4*)(C + (size_t)(m0 + ry + i) * N + (n0 + rx + j)) = v;
        }
    }
    if (bx > by) {
        #pragma unroll
        for (int j = 0; j < 8; j++) {
            #pragma unroll
            for (int i = 0; i < 8; i += 4) {
                float4 v = make_float4(acc[i][j], acc[i+1][j], acc[i+2][j], acc[i+3][j]);
                *(float4*)(C + (size_t)(n0 + rx + j) * N + (m0 + ry + i)) = v;
            }
        }
    }

    if (csPart) {
        __syncthreads();
        float* red = (float*)As;
        #pragma unroll
        for (int jj = 0; jj < 8; jj++) {
            float s = 0.f;
            #pragma unroll
            for (int i = 0; i < 8; i++) s += acc[i][jj];
            red[ty * 128 + rx + jj] = s;
        }
        __syncthreads();
        if (tid < 128) {
            float s = 0.f;
            #pragma unroll
            for (int p = 0; p < 16; p++) s += red[p * 128 + tid];
            csPart[(size_t)by * N + n0 + tid] = s;
        }
        if (bx > by) {
            __syncthreads();
            #pragma unroll
            for (int ii = 0; ii < 8; ii++) {
                float s = 0.f;
                #pragma unroll
                for (int j = 0; j < 8; j++) s += acc[ii][j];
                red[tx * 128 + ry + ii] = s;
            }
            __syncthreads();
            if (tid < 128) {
                float s = 0.f;
                #pragma unroll
                for (int p = 0; p < 16; p++) s += red[p * 128 + tid];
                csPart[(size_t)bx * N + m0 + tid] = s;
            }
        }
    }
}

// Deterministic ballot-compacted nonzero index list; 4 warps scan disjoint
// segments, merged in segment order (same ascending result as 1-warp scan).
__global__ void build_idx_kernel(const float* __restrict__ adj, int col_off, int NR,
                                 int* __restrict__ idx, int* __restrict__ cnt)
{
    __shared__ int sidx[4][CAP];
    __shared__ int scnt[4];
    int i = blockIdx.x;
    const float* r = adj + (size_t)i * NALL + col_off;
    int w = threadIdx.x >> 5, lane = threadIdx.x & 31;
    int seg = NR >> 2;
    int b0  = w * seg;
    int count = 0;
    for (int base = b0; base < b0 + seg; base += 32) {
        float v = r[base + lane];
        unsigned m = __ballot_sync(0xffffffffu, v != 0.f);
        int pre = __popc(m & ((1u << lane) - 1u));
        if (v != 0.f && (count + pre) < CAP) sidx[w][count + pre] = base + lane;
        count += __popc(m);
    }
    if (lane == 0) scnt[w] = min(count, CAP);
    __syncthreads();
    int myoff = 0, tot = 0;
    #pragma unroll
    for (int p = 0; p < 4; p++) {
        if (p < w) myoff += scnt[p];
        tot += scnt[p];
    }
    for (int t = lane; t < scnt[w]; t += 32) {
        int pos = myoff + t;
        if (pos < CAP) idx[(size_t)i * CAP + pos] = sidx[w][t];
    }
    if (threadIdx.x == 0) cnt[i] = min(tot, CAP);
}

__global__ void gather_sum_kernel(const float* __restrict__ src, int lds,
                                  const int* __restrict__ idx, const int* __restrict__ cnt,
                                  float* __restrict__ out, int ldo)
{
    int i = blockIdx.y;
    int j = ((blockIdx.x * blockDim.x + threadIdx.x) << 2);
    int c = cnt[i];
    const int* ip = idx + (size_t)i * CAP;
    float4 s = make_float4(0.f, 0.f, 0.f, 0.f);
    for (int t = 0; t < c; t++) {
        float4 v = *(const float4*)(src + (size_t)ip[t] * lds + j);
        s.x += v.x; s.y += v.y; s.z += v.z; s.w += v.w;
    }
    *(float4*)(out + (size_t)i * ldo + j) = s;
}

__global__ void gather64b_kernel(const float* __restrict__ src,
                                 const int* __restrict__ idx, const int* __restrict__ cnt,
                                 const float* __restrict__ bias, float* __restrict__ out)
{
    int i = blockIdx.x;
    int c = threadIdx.x;
    int n = cnt[i];
    const int* ip = idx + (size_t)i * CAP;
    float s = 0.f;
    for (int t = 0; t < n; t++) s += src[(size_t)ip[t] * 64 + c];
    out[(size_t)i * 64 + c] = s + bias[c];
}

// C[M,64] = A[M,K] @ B[K,64] (+bias) (optional relu)
__global__ void __launch_bounds__(256)
gemm_n64_kernel(const float* __restrict__ A, const float* __restrict__ B,
                const float* __restrict__ bias, float* __restrict__ C,
                int M, int K, int relu)
{
    __shared__ float As[32][64];
    __shared__ float Bs[32][64];
    int tid = threadIdx.x;
    int m0  = blockIdx.x * 64;
    int ar  = tid >> 3;
    int ac  = (tid & 7) << 2;
    int br  = tid >> 4;
    int bc  = (tid & 15) << 2;
    int wrp = tid >> 5, ln = tid & 31;
    int ty  = ((wrp >> 1) << 2) | (ln >> 3);
    int tx  = ((wrp & 1) << 3) | (ln & 7);

    u64t acc2[4][2];
    #pragma unroll
    for (int i = 0; i < 4; i++) { acc2[i][0] = 0ull; acc2[i][1] = 0ull; }

    for (int k0 = 0; k0 < K; k0 += 32) {
        float4 a0 = *(const float4*)(A + (size_t)(m0 + ar)      * K + k0 + ac);
        float4 a1 = *(const float4*)(A + (size_t)(m0 + ar + 32) * K + k0 + ac);
        float4 b0 = *(const float4*)(B + (size_t)(k0 + br)      * 64 + bc);
        float4 b1 = *(const float4*)(B + (size_t)(k0 + br + 16) * 64 + bc);
        __syncthreads();
        As[ac+0][ar]    = a0.x; As[ac+1][ar]    = a0.y; As[ac+2][ar]    = a0.z; As[ac+3][ar]    = a0.w;
        As[ac+0][ar+32] = a1.x; As[ac+1][ar+32] = a1.y; As[ac+2][ar+32] = a1.z; As[ac+3][ar+32] = a1.w;
        *(float4*)&Bs[br][bc]      = b0;
        *(float4*)&Bs[br + 16][bc] = b1;
        __syncthreads();
        #pragma unroll
        for (int k = 0; k < 32; k++) {
            float4 av = *(const float4*)&As[k][ty << 2];
            float4 bv = *(const float4*)&Bs[k][tx << 2];
            u64t bp0 = ((const u64t*)&bv)[0], bp1 = ((const u64t*)&bv)[1];
            float a[4] = {av.x, av.y, av.z, av.w};
            #pragma unroll
            for (int i = 0; i < 4; i++) {
                u64t ai = bcast2(a[i]);
                fma2(acc2[i][0], ai, bp0);
                fma2(acc2[i][1], ai, bp1);
            }
        }
    }
    int r = m0 + (ty << 2), c = tx << 2;
    #pragma unroll
    for (int i = 0; i < 4; i++) {
        float2 v0 = unpack2(acc2[i][0]);
        float2 v1 = unpack2(acc2[i][1]);
        float vv[4] = {v0.x, v0.y, v1.x, v1.y};
        #pragma unroll
        for (int j = 0; j < 4; j++) {
            float v = vv[j] + (bias ? bias[c + j] : 0.f);
            if (relu) v = fmaxf(v, 0.f);
            C[(size_t)(r + i) * 64 + c + j] = v;
        }
    }
}

// split-K variant: grid (M/64, S)
__global__ void __launch_bounds__(256)
gemm_n64_splitk_kernel(const float* __restrict__ A, const float* __restrict__ B,
                       float* __restrict__ part, int M, int K, int Kc)
{
    __shared__ float As[32][64];
    __shared__ float Bs[32][64];
    int tid = threadIdx.x;
    int m0  = blockIdx.x * 64;
    int s   = blockIdx.y;
    int kb  = s * Kc, ke = kb + Kc;
    int ar  = tid >> 3;
    int ac  = (tid & 7) << 2;
    int br  = tid >> 4;
    int bc  = (tid & 15) << 2;
    int wrp = tid >> 5, ln = tid & 31;
    int ty  = ((wrp >> 1) << 2) | (ln >> 3);
    int tx  = ((wrp & 1) << 3) | (ln & 7);

    u64t acc2[4][2];
    #pragma unroll
    for (int i = 0; i < 4; i++) { acc2[i][0] = 0ull; acc2[i][1] = 0ull; }

    for (int k0 = kb; k0 < ke; k0 += 32) {
        float4 a0 = *(const float4*)(A + (size_t)(m0 + ar)      * K + k0 + ac);
        float4 a1 = *(const float4*)(A + (size_t)(m0 + ar + 32) * K + k0 + ac);
        float4 b0 = *(const float4*)(B + (size_t)(k0 + br)      * 64 + bc);
        float4 b1 = *(const float4*)(B + (size_t)(k0 + br + 16) * 64 + bc);
        __syncthreads();
        As[ac+0][ar]    = a0.x; As[ac+1][ar]    = a0.y; As[ac+2][ar]    = a0.z; As[ac+3][ar]    = a0.w;
        As[ac+0][ar+32] = a1.x; As[ac+1][ar+32] = a1.y; As[ac+2][ar+32] = a1.z; As[ac+3][ar+32] = a1.w;
        *(float4*)&Bs[br][bc]      = b0;
        *(float4*)&Bs[br + 16][bc] = b1;
        __syncthreads();
        #pragma unroll
        for (int k = 0; k < 32; k++) {
            float4 av = *(const float4*)&As[k][ty << 2];
            float4 bv = *(const float4*)&Bs[k][tx << 2];
            u64t bp0 = ((const u64t*)&bv)[0], bp1 = ((const u64t*)&bv)[1];
            float a[4] = {av.x, av.y, av.z, av.w};
            #pragma unroll
            for (int i = 0; i < 4; i++) {
                u64t ai = bcast2(a[i]);
                fma2(acc2[i][0], ai, bp0);
                fma2(acc2[i][1], ai, bp1);
            }
        }
    }
    int r = m0 + (ty << 2), c = tx << 2;
    #pragma unroll
    for (int i = 0; i < 4; i++) {
        float2 v0 = unpack2(acc2[i][0]);
        float2 v1 = unpack2(acc2[i][1]);
        float vv[4] = {v0.x, v0.y, v1.x, v1.y};
        #pragma unroll
        for (int j = 0; j < 4; j++)
            part[(size_t)s * M * 64 + (size_t)(r + i) * 64 + c + j] = vv[j];
    }
}

__global__ void splitk_reduce_kernel(const float* __restrict__ part, const float* __restrict__ bias,
                                     float* __restrict__ C, int M, int S, int relu)
{
    int idx = blockIdx.x * 256 + threadIdx.x;
    if (idx >= M * 64) return;
    float s = 0.f;
    for (int p = 0; p < S; p++) s += part[(size_t)p * M * 64 + idx];
    if (bias) s += bias[idx & 63];
    if (relu) s = fmaxf(s, 0.f);
    C[idx] = s;
}

__global__ void cs_reduce_kernel(const float* __restrict__ CSP, float* __restrict__ CS)
{
    int m = blockIdx.y;
    int j = blockIdx.x * 256 + threadIdx.x;
    float s = 0.f;
    #pragma unroll
    for (int p = 0; p < 32; p++) s += CSP[((size_t)m * 32 + p) * NT + j];
    CS[m * NT + j] = s;
}

__global__ void coefs_kernel(const float* __restrict__ sgw, const float* __restrict__ ffw,
                             const float* __restrict__ f4w,
                             const float* __restrict__ cs, float* __restrict__ coef,
                             float* __restrict__ ct0)
{
    int j = blockIdx.x * 256 + threadIdx.x;
    float m2 = fmaxf(sgw[0], sgw[1]);
    float e0 = expf(sgw[0] - m2), e1 = expf(sgw[1] - m2);
    float sa0 = e0 / (e0 + e1), sa1 = e1 / (e0 + e1);
    float mf = fmaxf(ffw[0], ffw[1]);
    float f0 = expf(ffw[0] - mf), f1 = expf(ffw[1] - mf);
    float fa0 = f0 / (f0 + f1), fa1 = f1 / (f0 + f1);
    float m4 = fmaxf(fmaxf(f4w[0], f4w[1]), fmaxf(f4w[2], f4w[3]));
    float w0 = expf(f4w[0] - m4), w1 = expf(f4w[1] - m4), w2 = expf(f4w[2] - m4), w3 = expf(f4w[3] - m4);
    float ws = w0 + w1 + w2 + w3;
    w0 /= ws; w1 /= ws; w2 /= ws; w3 /= ws;

    float csv[7], cf[7];
    #pragma unroll
    for (int m = 0; m < 7; m++) csv[m] = cs[m * NT + j];
    float uP  = (csv[1] > 0.05f) ? 1.f : 0.f;
    float uQ  = (csv[2] > 0.05f) ? 1.f : 0.f;
    float uFA = (csv[3] > 0.05f) ? 1.f : 0.f;
    float uFS = (csv[4] > 0.05f) ? 1.f : 0.f;
    float uSA = (csv[5] > 0.05f) ? 1.f : 0.f;
    float uSS = (csv[6] > 0.05f) ? 1.f : 0.f;
    float dSem = fmaxf(sa0 * uP  + sa1 * uQ,  1e-12f);
    float dFp  = fmaxf(fa0 * uFA + fa1 * uFS, 1e-12f);
    float dSt  = fmaxf(fa0 * uSA + fa1 * uSS, 1e-12f);

    cf[0] = w0 / fmaxf(csv[0], 1e-12f);
    cf[1] = w1 * sa0 / (fmaxf(csv[1], 1e-12f) * dSem);
    cf[2] = w1 * sa1 / (fmaxf(csv[2], 1e-12f) * dSem);
    cf[3] = w2 * fa0 / (fmaxf(csv[3], 1e-12f) * dFp);
    cf[4] = w2 * fa1 / (fmaxf(csv[4], 1e-12f) * dFp);
    cf[5] = w3 * fa0 / (fmaxf(csv[5], 1e-12f) * dSt);
    cf[6] = w3 * fa1 / (fmaxf(csv[6], 1e-12f) * dSt);

    float c0 = 0.f;
    #pragma unroll
    for (int m = 0; m < 7; m++) { coef[m * NT + j] = cf[m]; c0 += cf[m] * csv[m]; }
    ct0[j] = c0;
}

__global__ void combine_kernel(const float* __restrict__ G,  const float* __restrict__ P,
                               const float* __restrict__ Q,  const float* __restrict__ FA,
                               const float* __restrict__ FS, const float* __restrict__ SA,
                               const float* __restrict__ SS, const float* __restrict__ coef,
                               float* __restrict__ out, float* __restrict__ rowp)
{
    int b = blockIdx.x;
    size_t e = ((size_t)b * 256 + threadIdx.x) << 2;
    int j = (int)(e & (NT - 1));
    float4 r = make_float4(0.f, 0.f, 0.f, 0.f);
#define ACC(buf, m) { float4 v = *(const float4*)((buf) + e);                 \
                      float4 k = *(const float4*)(coef + (m) * NT + j);       \
                      r.x = fmaf(k.x, v.x, r.x); r.y = fmaf(k.y, v.y, r.y);   \
                      r.z = fmaf(k.z, v.z, r.z); r.w = fmaf(k.w, v.w, r.w); }
    ACC(G, 0) ACC(P, 1) ACC(Q, 2) ACC(FA, 3) ACC(FS, 4) ACC(SA, 5) ACC(SS, 6)
#undef ACC
    *(float4*)(out + e) = r;

    float s = r.x + r.y + r.z + r.w;
    #pragma unroll
    for (int o = 16; o; o >>= 1) s += __shfl_xor_sync(0xffffffffu, s, o);
    __shared__ float ws[8];
    int w = threadIdx.x >> 5;
    if ((threadIdx.x & 31) == 0) ws[w] = s;
    __syncthreads();
    if (threadIdx.x == 0) {
        float t = 0.f;
        #pragma unroll
        for (int p = 0; p < 8; p++) t += ws[p];
        rowp[(size_t)(b >> 2) * 4 + (b & 3)] = t;
    }
}

__global__ void ct_final_kernel(const float* __restrict__ ct0, const float* __restrict__ rowp,
                                float* __restrict__ ct)
{
    int j = blockIdx.x * 256 + threadIdx.x;
    ct[j] = ct0[j] + rowp[j * 4 + 0] + rowp[j * 4 + 1] + rowp[j * 4 + 2] + rowp[j * 4 + 3];
}

__global__ void symscale_kernel(float* __restrict__ A, const float* __restrict__ ct)
{
    const int nb = 128;
    int idx = blockIdx.x;
    float nb2 = nb + 0.5f;
    int bi = (int)(nb2 - sqrtf(fmaxf(nb2 * nb2 - 2.0f * idx, 0.f)));
    if (bi < 0) bi = 0;
    if (bi > nb - 1) bi = nb - 1;
    while (bi > 0 && (bi * nb - (bi * (bi - 1)) / 2) > idx) bi--;
    while (((bi + 1) * nb - ((bi + 1) * bi) / 2) <= idx) bi++;
    int bj = bi + (idx - (bi * nb - (bi * (bi - 1)) / 2));

    __shared__ float T1[32][33], T2[32][33];
    int x = threadIdx.x, y0 = threadIdx.y;
    for (int y = y0; y < 32; y += 8) T1[y][x] = A[(size_t)(bi * 32 + y) * NT + bj * 32 + x];
    if (bi != bj)
        for (int y = y0; y < 32; y += 8) T2[y][x] = A[(size_t)(bj * 32 + y) * NT + bi * 32 + x];
    __syncthreads();
    float cj = fmaxf(ct[bj * 32 + x], 1e-12f);
    if (bi == bj) {
        for (int y = y0; y < 32; y += 8)
            A[(size_t)(bi * 32 + y) * NT + bj * 32 + x] = (T1[y][x] + T1[x][y]) / cj;
    } else {
        float ci = fmaxf(ct[bi * 32 + x], 1e-12f);
        for (int y = y0; y < 32; y += 8)
            A[(size_t)(bi * 32 + y) * NT + bj * 32 + x] = (T1[y][x] + T2[x][y]) / cj;
        for (int y = y0; y < 32; y += 8)
            A[(size_t)(bj * 32 + y) * NT + bi * 32 + x] = (T2[y][x] + T1[x][y]) / ci;
    }
}

__global__ void x1w2_kernel(const float* __restrict__ X1, const float* __restrict__ W2,
                            float* __restrict__ H2)
{
    int i = blockIdx.x * 256 + threadIdx.x;
    if (i >= NT) return;
    float s0 = 0.f, s1 = 0.f, s2 = 0.f;
    #pragma unroll 8
    for (int k = 0; k < COM; k++) {
        float x = X1[(size_t)i * COM + k];
        s0 = fmaf(x, W2[k * 3 + 0], s0);
        s1 = fmaf(x, W2[k * 3 + 1], s1);
        s2 = fmaf(x, W2[k * 3 + 2], s2);
    }
    H2[i * 3 + 0] = s0; H2[i * 3 + 1] = s1; H2[i * 3 + 2] = s2;
}

__global__ void logits_kernel(const float* __restrict__ A, const float* __restrict__ H2,
                              const float* __restrict__ b2, float* __restrict__ out)
{
    int i = blockIdx.x, tid = threadIdx.x;
    const float* row = A + (size_t)i * NT;
    float s0 = 0.f, s1 = 0.f, s2 = 0.f;
    for (int k = tid; k < NT; k += 256) {
        float a = row[k];
        s0 = fmaf(a, H2[k * 3 + 0], s0);
        s1 = fmaf(a, H2[k * 3 + 1], s1);
        s2 = fmaf(a, H2[k * 3 + 2], s2);
    }
    #pragma unroll
    for (int o = 16; o; o >>= 1) {
        s0 += __shfl_xor_sync(0xffffffffu, s0, o);
        s1 += __shfl_xor_sync(0xffffffffu, s1, o);
        s2 += __shfl_xor_sync(0xffffffffu, s2, o);
    }
    __shared__ float sh[3][8];
    int w = tid >> 5, l = tid & 31;
    if (l == 0) { sh[0][w] = s0; sh[1][w] = s1; sh[2][w] = s2; }
    __syncthreads();
    if (tid == 0) {
        float x0 = 0.f, x1 = 0.f, x2 = 0.f;
        #pragma unroll
        for (int t = 0; t < 8; t++) { x0 += sh[0][t]; x1 += sh[1][t]; x2 += sh[2][t]; }
        x0 += b2[0]; x1 += b2[1]; x2 += b2[2];
        float m  = fmaxf(x0, fmaxf(x1, x2));
        float ls = logf(expf(x0 - m) + expf(x1 - m) + expf(x2 - m));
        out[i * 3 + 0] = x0 - m - ls;
        out[i * 3 + 1] = x1 - m - ls;
        out[i * 3 + 2] = x2 - m - ls;
    }
}

// ---------------- host orchestration (single stream) -------------------------

extern "C" void kernel_launch(void* const* d_in, const int* in_sizes, int n_in,
                              void* d_out, int out_size)
{
    const float* features  = (const float*)d_in[0];
    const float* adj_ori   = (const float*)d_in[1];
    const float* mp_pap    = (const float*)d_in[2];
    const float* mp_psp    = (const float*)d_in[3];
    const float* fgo_w     = (const float*)d_in[6];
    const float* fpo_w     = (const float*)d_in[7];
    const float* sgg_pap_w = (const float*)d_in[8];
    const float* sgg_psp_w = (const float*)d_in[9];
    const float* sg_agg_w  = (const float*)d_in[10];
    const float* f_agg_f_w = (const float*)d_in[11];
    const float* f_agg_w   = (const float*)d_in[12];
    const float* topo_W_a  = (const float*)d_in[13];
    const float* topo_b_a  = (const float*)d_in[14];
    const float* topo_W_s  = (const float*)d_in[15];
    const float* topo_b_s  = (const float*)d_in[16];
    const float* fgt_w_a   = (const float*)d_in[17];
    const float* fgt_w_s   = (const float*)d_in[18];
    const float* gcn_W1    = (const float*)d_in[19];
    const float* gcn_b1    = (const float*)d_in[20];
    const float* gcn_W2    = (const float*)d_in[21];
    const float* gcn_b2    = (const float*)d_in[22];
    (void)in_sizes; (void)n_in; (void)out_size;

    float* out   = (float*)d_out;
    float* NAdj  = out + (size_t)NT * NCLS;

    float* big = nullptr; float* sm = nullptr; int* ib = nullptr;
    cudaGetSymbolAddress((void**)&big, g_big);
    cudaGetSymbolAddress((void**)&sm,  g_small);
    cudaGetSymbolAddress((void**)&ib,  g_ibuf);

    float* G   = big + 0ll * NT * NT;
    float* P   = big + 1ll * NT * NT;
    float* Q   = big + 2ll * NT * NT;
    float* FAb = big + 3ll * NT * NT;
    float* FSb = big + 4ll * NT * NT;
    float* SAb = big + 5ll * NT * NT;   // sim_r_A, then s_h_A
    float* SSb = big + 6ll * NT * NT;

    float* XN0   = sm + OFF_XN0;
    float* XN1   = sm + OFF_XN1;
    float* XN2   = sm + OFF_XN2;
    float* XN3   = sm + OFF_XN3;
    float* XN4   = sm + OFF_XN4;
    float* SIMS  = sm + OFF_SIMS;
    float* FPA   = sm + OFF_FPA;
    float* FPS   = sm + OFF_FPS;
    float* THA   = sm + OFF_THA;
    float* THS   = sm + OFF_THS;
    float* SWA   = sm + OFF_SWA;
    float* SWS   = sm + OFF_SWS;
    float* H0    = sm + OFF_H0;
    float* X1    = sm + OFF_X1;
    float* H2    = sm + OFF_H2;
    float* CS    = sm + OFF_CS;
    float* COEF  = sm + OFF_COEF;
    float* CT0   = sm + OFF_CT0;
    float* CT    = sm + OFF_CT;
    float* ROWP  = sm + OFF_ROWP;
    float* CSP   = sm + OFF_CSP;
    float* SPART = sm + OFF_SPART;

    int* IDXA = ib + OFF_IDXA; int* CNTA = ib + OFF_CNTA;
    int* IDXS = ib + OFF_IDXS; int* CNTS = ib + OFF_CNTS;

    const int TRI32 = 32 * 33 / 2;   // 528
    const int TRI8  = 8 * 9 / 2;     // 36
    dim3 bSym(32, 8);
    dim3 gSim2(TRI32, 2), gSimS(TRI8, 1);

    // ---- batch 1: g_targ & sim_r_A (both K=256, th=0.1) ----
    prep_norm_T_kernel<<<NT / 32, 256>>>(features, fgo_w, XN0, NT, FEAT, 2);
    prep_norm_T_kernel<<<NT / 32, 256>>>(features + (size_t)NT * FEAT, fgo_w, XN1, NT, FEAT, 2);
    simgemm_kernel<<<gSim2, 256>>>(XN0, G, CSP + 0ll * 32 * NT,
                                   XN1, SAb, nullptr, NT, 256, 0.5f, 0.1f, 32);

    // ---- batch 2: sem_pap & sem_psp (K=128, th=0.1) ----
    prep_norm_T_kernel<<<NT / 32, 256>>>(mp_pap, sgg_pap_w, XN2, NT, MPD, 2);
    prep_norm_T_kernel<<<NT / 32, 256>>>(mp_psp, sgg_psp_w, XN3, NT, MPD, 2);
    simgemm_kernel<<<gSim2, 256>>>(XN2, P, CSP + 1ll * 32 * NT,
                                   XN3, Q, CSP + 2ll * 32 * NT, NT, 128, 0.5f, 0.1f, 32);

    // ---- A-relation topo pieces ----
    build_idx_kernel<<<NT, 128>>>(adj_ori, NT, NAr, IDXA, CNTA);
    gemm_n64_splitk_kernel<<<dim3(NT / 64, 8), 256>>>(SAb, topo_W_a, SPART, NT, NAr, NAr / 8);
    splitk_reduce_kernel<<<(NT * 64) / 256, 256>>>(SPART, nullptr, SWA, NT, 8, 0);
    gather64b_kernel<<<NT, 64>>>(SWA, IDXA, CNTA, topo_b_a, THA);
    gather_sum_kernel<<<dim3(1, NT), 32>>>(features + (size_t)NT * FEAT, FEAT, IDXA, CNTA, FPA, FEAT);

    // ---- S-relation topo pieces ----
    build_idx_kernel<<<NT, 128>>>(adj_ori, NT + NAr, NSr, IDXS, CNTS);
    prep_norm_T_kernel<<<NSr / 32, 256>>>(features + (size_t)(NT + NAr) * FEAT, fgo_w, XN4, NSr, FEAT, 2);
    simgemm_kernel<<<gSimS, 256>>>(XN4, SIMS, nullptr,
                                   nullptr, nullptr, nullptr, NSr, 256, 0.5f, 0.1f, 8);
    gemm_n64_splitk_kernel<<<dim3(NSr / 64, 8), 256>>>(SIMS, topo_W_s, SPART, NSr, NSr, NSr / 8);
    splitk_reduce_kernel<<<(NSr * 64) / 256, 256>>>(SPART, nullptr, SWS, NSr, 8, 0);
    gather64b_kernel<<<NT, 64>>>(SWS, IDXS, CNTS, topo_b_s, THS);
    gather_sum_kernel<<<dim3(1, NT), 32>>>(features + (size_t)(NT + NAr) * FEAT, FEAT, IDXS, CNTS, FPS, FEAT);

    // ---- batch 3: f_h_A & f_h_S (K=256, th=0.2) ----
    prep_norm_T_kernel<<<NT / 32, 256>>>(FPA, fpo_w, XN0, NT, FEAT, 2);
    prep_norm_T_kernel<<<NT / 32, 256>>>(FPS, fpo_w, XN1, NT, FEAT, 2);
    simgemm_kernel<<<gSim2, 256>>>(XN0, FAb, CSP + 3ll * 32 * NT,
                                   XN1, FSb, CSP + 4ll * 32 * NT, NT, 256, 0.5f, 0.2f, 32);

    // ---- batch 4: s_h_A & s_h_S (K=128, th=0.1) ----
    prep_norm_T_kernel<<<NT / 32, 256>>>(THA, fgt_w_a, XN2, NT, COM, 2);
    prep_norm_T_kernel<<<NT / 32, 256>>>(THS, fgt_w_s, XN3, NT, COM, 2);
    simgemm_kernel<<<gSim2, 256>>>(XN2, SAb, CSP + 5ll * 32 * NT,
                                   XN3, SSb, CSP + 6ll * 32 * NT, NT, 128, 0.5f, 0.1f, 32);

    // ---- GCN first half (independent) ----
    gemm_n64_kernel<<<NT / 64, 256>>>(features, gcn_W1, nullptr, H0, NT, FEAT, 0);

    // ---- fused channel attention ----
    cs_reduce_kernel<<<dim3(NT / 256, 7), 256>>>(CSP, CS);
    coefs_kernel<<<NT / 256, 256>>>(sg_agg_w, f_agg_f_w, f_agg_w, CS, COEF, CT0);
    combine_kernel<<<(NT * NT) / 1024, 256>>>(G, P, Q, FAb, FSb, SAb, SSb, COEF, NAdj, ROWP);
    ct_final_kernel<<<NT / 256, 256>>>(CT0, ROWP, CT);
    symscale_kernel<<<128 * 129 / 2, bSym>>>(NAdj, CT);

    // ---- GCN second half ----
    gemm_n64_splitk_kernel<<<dim3(NT / 64, 8), 256>>>(NAdj, H0, SPART, NT, NT, NT / 8);
    splitk_reduce_kernel<<<(NT * 64) / 256, 256>>>(SPART, gcn_b1, X1, NT, 8, 1);
    x1w2_kernel<<<NT / 256, 256>>>(X1, gcn_W2, H2);
    logits_kernel<<<NT, 256>>>(NAdj, H2, gcn_b2, out);
}

// round 9
// speedup vs baseline: 1.1880x; 1.1880x over previous
#include <cuda_runtime.h>
#include <math.h>

#define NT   4096
#define NAr  4096
#define NSr  1024
#define NALL 9216
#define FEAT 128
#define COM  64
#define MPD  64
#define NCLS 3
#define CAP  128   // max nnz per adjacency row (expected ~20, p=0.005)

// ---------------- static device scratch (no allocations allowed) -------------
__device__ float g_big[7ll * NT * NT];

#define OFF_XN0   0
#define OFF_XN1   (OFF_XN0  + NT*256)
#define OFF_XN2   (OFF_XN1  + NT*256)
#define OFF_XN3   (OFF_XN2  + NT*256)
#define OFF_XN4   (OFF_XN3  + NT*256)
#define OFF_SIMS  (OFF_XN4  + NT*256)       // 1024*1024
#define OFF_FPA   (OFF_SIMS + NSr*NSr)      // 4096*128
#define OFF_FPS   (OFF_FPA  + NT*FEAT)      // 4096*128
#define OFF_THA   (OFF_FPS  + NT*FEAT)      // 4096*64
#define OFF_THS   (OFF_THA  + NT*COM)       // 4096*64
#define OFF_SWA   (OFF_THS  + NT*COM)       // 4096*64
#define OFF_SWS   (OFF_SWA  + NT*COM)       // 1024*64
#define OFF_H0    (OFF_SWS  + NSr*COM)      // 4096*64
#define OFF_X1    (OFF_H0   + NT*COM)       // 4096*64
#define OFF_H2    (OFF_X1   + NT*COM)       // 4096*3
#define OFF_CS    (OFF_H2   + NT*NCLS)      // 7*4096
#define OFF_COEF  (OFF_CS   + 7*NT)         // 7*4096
#define OFF_CT0   (OFF_COEF + 7*NT)         // 4096
#define OFF_CT    (OFF_CT0  + NT)           // 4096
#define OFF_ROWP  (OFF_CT   + NT)           // 4096*4
#define OFF_CSP   (OFF_ROWP + 4*NT)         // 7*32*4096
#define OFF_SPART (OFF_CSP  + 7*32*NT)      // 8*4096*64
#define SMALL_TOT (OFF_SPART + 8*NT*64)
__device__ float g_small[SMALL_TOT];

#define OFF_IDXA 0
#define OFF_CNTA (OFF_IDXA + NT*CAP)
#define OFF_IDXS (OFF_CNTA + NT)
#define OFF_CNTS (OFF_IDXS + NT*CAP)
#define IBUF_TOT (OFF_CNTS + NT)
__device__ int g_ibuf[IBUF_TOT];

// ---------------- packed f32x2 helpers (bit-identical IEEE fp32 per lane) ----
typedef unsigned long long u64t;

__device__ __forceinline__ u64t bcast2(float a)
{
    u64t r;
    asm("mov.b64 %0, {%1, %1};" : "=l"(r) : "r"(__float_as_uint(a)));
    return r;
}
__device__ __forceinline__ void fma2(u64t& acc, u64t a, u64t b)
{
    asm("fma.rn.f32x2 %0, %1, %2, %0;" : "+l"(acc) : "l"(a), "l"(b));
}
__device__ __forceinline__ float2 unpack2(u64t v)
{
    unsigned int lo, hi;
    asm("mov.b64 {%0, %1}, %2;" : "=r"(lo), "=r"(hi) : "l"(v));
    return make_float2(__uint_as_float(lo), __uint_as_float(hi));
}

// ---------------- kernels ----------------------------------------------------

// Per-head weighted + L2-row-normalized features: dst[N, H*D] (row-major)
__global__ void prep_norm_kernel(const float* __restrict__ src, const float* __restrict__ w,
                                 float* __restrict__ dst, int N, int D, int H)
{
    int row  = blockIdx.x * (blockDim.x >> 5) + (threadIdx.x >> 5);
    int lane = threadIdx.x & 31;
    if (row >= N) return;
    int HD = H * D;
    for (int h = 0; h < H; h++) {
        float ss = 0.f;
        for (int d = lane; d < D; d += 32) {
            float v = src[(size_t)row * D + d] * w[h * D + d];
            ss += v * v;
        }
        #pragma unroll
        for (int o = 16; o; o >>= 1) ss += __shfl_xor_sync(0xffffffffu, ss, o);
        float inv = 1.f / fmaxf(sqrtf(ss), 1e-12f);
        for (int d = lane; d < D; d += 32)
            dst[(size_t)row * HD + h * D + d] = src[(size_t)row * D + d] * w[h * D + d] * inv;
    }
}

__device__ __forceinline__ float thrf(float v, float scale, float th)
{
    v *= scale;
    return (v < th) ? 0.f : v;
}

// Batched C = threshold(scale * X @ X^T), row-major X[N,K].
// blockIdx.y selects pointer set (two independent problems sharing K/scale/th).
// Triangular grid over blockIdx.x; double-buffered smem; f32x2 FMA; 4x8 warp map.
// Inner loop and per-element accumulation order identical to the round-5 kernel.
__global__ void __launch_bounds__(256, 2)
simgemm_kernel(const float* __restrict__ X0, float* __restrict__ C0, float* __restrict__ cs0,
               const float* __restrict__ X1, float* __restrict__ C1, float* __restrict__ cs1,
               int N, int K, float scale, float th, int nBlk)
{
    const float* X = blockIdx.y ? X1 : X0;
    float* C       = blockIdx.y ? C1 : C0;
    float* csPart  = blockIdx.y ? cs1 : cs0;

    int idx = blockIdx.x;
    float nb2 = nBlk + 0.5f;
    int by = (int)(nb2 - sqrtf(fmaxf(nb2 * nb2 - 2.0f * idx, 0.f)));
    if (by < 0) by = 0;
    if (by > nBlk - 1) by = nBlk - 1;
    while (by > 0 && (by * nBlk - (by * (by - 1)) / 2) > idx) by--;
    while (((by + 1) * nBlk - ((by + 1) * by) / 2) <= idx) by++;
    int bx = by + (idx - (by * nBlk - (by * (by - 1)) / 2));

    const int m0 = by * 128, n0 = bx * 128;

    __shared__ float As[2][16][128];
    __shared__ float Bs[2][16][128];

    const int tid = threadIdx.x;
    const int ldr = tid >> 2;
    const int ldc = (tid & 3) << 2;
    const int wrp = tid >> 5;
    const int ln  = tid & 31;
    const int ty  = ((wrp >> 1) << 2) | (ln >> 3);   // 0..15
    const int tx  = ((wrp & 1) << 3) | (ln & 7);     // 0..15
    const int ry  = ty << 3;
    const int rx  = tx << 3;

    u64t acc2[8][4];
    #pragma unroll
    for (int i = 0; i < 8; i++)
        #pragma unroll
        for (int j = 0; j < 4; j++) acc2[i][j] = 0ull;

    float4 a0, a1, b0, b1;

#define LOADG(k0) {                                                             \
    a0 = *(const float4*)(X + (size_t)(m0 + ldr)      * K + (k0) + ldc);        \
    a1 = *(const float4*)(X + (size_t)(m0 + ldr + 64) * K + (k0) + ldc);        \
    b0 = *(const float4*)(X + (size_t)(n0 + ldr)      * K + (k0) + ldc);        \
    b1 = *(const float4*)(X + (size_t)(n0 + ldr + 64) * K + (k0) + ldc); }

#define STORES(bf) {                                                            \
    As[bf][ldc+0][ldr]    = a0.x; As[bf][ldc+1][ldr]    = a0.y;                 \
    As[bf][ldc+2][ldr]    = a0.z; As[bf][ldc+3][ldr]    = a0.w;                 \
    As[bf][ldc+0][ldr+64] = a1.x; As[bf][ldc+1][ldr+64] = a1.y;                 \
    As[bf][ldc+2][ldr+64] = a1.z; As[bf][ldc+3][ldr+64] = a1.w;                 \
    Bs[bf][ldc+0][ldr]    = b0.x; Bs[bf][ldc+1][ldr]    = b0.y;                 \
    Bs[bf][ldc+2][ldr]    = b0.z; Bs[bf][ldc+3][ldr]    = b0.w;                 \
    Bs[bf][ldc+0][ldr+64] = b1.x; Bs[bf][ldc+1][ldr+64] = b1.y;                 \
    Bs[bf][ldc+2][ldr+64] = b1.z; Bs[bf][ldc+3][ldr+64] = b1.w; }

#define COMPUTE(bf) {                                                           \
    _Pragma("unroll")                                                           \
    for (int k = 0; k < 16; k++) {                                              \
        float4 av0 = *(const float4*)&As[bf][k][ry];                            \
        float4 av1 = *(const float4*)&As[bf][k][ry + 4];                        \
        float4 bv0 = *(const float4*)&Bs[bf][k][rx];                            \
        float4 bv1 = *(const float4*)&Bs[bf][k][rx + 4];                        \
        u64t bp[4];                                                             \
        bp[0] = ((const u64t*)&bv0)[0]; bp[1] = ((const u64t*)&bv0)[1];         \
        bp[2] = ((const u64t*)&bv1)[0]; bp[3] = ((const u64t*)&bv1)[1];         \
        float a[8] = {av0.x,av0.y,av0.z,av0.w,av1.x,av1.y,av1.z,av1.w};         \
        _Pragma("unroll")                                                       \
        for (int i = 0; i < 8; i++) {                                           \
            u64t ai = bcast2(a[i]);                                             \
            fma2(acc2[i][0], ai, bp[0]);                                        \
            fma2(acc2[i][1], ai, bp[1]);                                        \
            fma2(acc2[i][2], ai, bp[2]);                                        \
            fma2(acc2[i][3], ai, bp[3]);                                        \
        }                                                                       \
    } }

    LOADG(0);
    STORES(0);
    __syncthreads();
    int buf = 0;
    for (int k0 = 16; k0 < K; k0 += 16) {
        LOADG(k0);
        COMPUTE(buf);
        STORES(buf ^ 1);
        __syncthreads();
        buf ^= 1;
    }
    COMPUTE(buf);

#undef LOADG
#undef STORES
#undef COMPUTE

    float acc[8][8];
    #pragma unroll
    for (int i = 0; i < 8; i++)
        #pragma unroll
        for (int jp = 0; jp < 4; jp++) {
            float2 v = unpack2(acc2[i][jp]);
            acc[i][2 * jp + 0] = thrf(v.x, scale, th);
            acc[i][2 * jp + 1] = thrf(v.y, scale, th);
        }

    #pragma unroll
    for (int i = 0; i < 8; i++) {
        #pragma unroll
        for (int j = 0; j < 8; j += 4) {
            float4 v = make_float4(acc[i][j], acc[i][j+1], acc[i][j+2], acc[i][j+3]);
            *(float4*)(C + (size_t)(m0 + ry + i) * N + (n0 + rx + j)) = v;
        }
    }
    if (bx > by) {
        #pragma unroll
        for (int j = 0; j < 8; j++) {
            #pragma unroll
            for (int i = 0; i < 8; i += 4) {
                float4 v = make_float4(acc[i][j], acc[i+1][j], acc[i+2][j], acc[i+3][j]);
                *(float4*)(C + (size_t)(n0 + rx + j) * N + (m0 + ry + i)) = v;
            }
        }
    }

    if (csPart) {
        __syncthreads();
        float* red = (float*)As;
        #pragma unroll
        for (int jj = 0; jj < 8; jj++) {
            float s = 0.f;
            #pragma unroll
            for (int i = 0; i < 8; i++) s += acc[i][jj];
            red[ty * 128 + rx + jj] = s;
        }
        __syncthreads();
        if (tid < 128) {
            float s = 0.f;
            #pragma unroll
            for (int p = 0; p < 16; p++) s += red[p * 128 + tid];
            csPart[(size_t)by * N + n0 + tid] = s;
        }
        if (bx > by) {
            __syncthreads();
            #pragma unroll
            for (int ii = 0; ii < 8; ii++) {
                float s = 0.f;
                #pragma unroll
                for (int j = 0; j < 8; j++) s += acc[ii][j];
                red[tx * 128 + ry + ii] = s;
            }
            __syncthreads();
            if (tid < 128) {
                float s = 0.f;
                #pragma unroll
                for (int p = 0; p < 16; p++) s += red[p * 128 + tid];
                csPart[(size_t)bx * N + m0 + tid] = s;
            }
        }
    }
}

// Deterministic ballot-compacted nonzero index list; 4 warps scan disjoint
// segments, merged in segment order (same ascending result as 1-warp scan).
__global__ void build_idx_kernel(const float* __restrict__ adj, int col_off, int NR,
                                 int* __restrict__ idx, int* __restrict__ cnt)
{
    __shared__ int sidx[4][CAP];
    __shared__ int scnt[4];
    int i = blockIdx.x;
    const float* r = adj + (size_t)i * NALL + col_off;
    int w = threadIdx.x >> 5, lane = threadIdx.x & 31;
    int seg = NR >> 2;
    int b0  = w * seg;
    int count = 0;
    for (int base = b0; base < b0 + seg; base += 32) {
        float v = r[base + lane];
        unsigned m = __ballot_sync(0xffffffffu, v != 0.f);
        int pre = __popc(m & ((1u << lane) - 1u));
        if (v != 0.f && (count + pre) < CAP) sidx[w][count + pre] = base + lane;
        count += __popc(m);
    }
    if (lane == 0) scnt[w] = min(count, CAP);
    __syncthreads();
    int myoff = 0, tot = 0;
    #pragma unroll
    for (int p = 0; p < 4; p++) {
        if (p < w) myoff += scnt[p];
        tot += scnt[p];
    }
    for (int t = lane; t < scnt[w]; t += 32) {
        int pos = myoff + t;
        if (pos < CAP) idx[(size_t)i * CAP + pos] = sidx[w][t];
    }
    if (threadIdx.x == 0) cnt[i] = min(tot, CAP);
}

__global__ void gather_sum_kernel(const float* __restrict__ src, int lds,
                                  const int* __restrict__ idx, const int* __restrict__ cnt,
                                  float* __restrict__ out, int ldo)
{
    int i = blockIdx.y;
    int j = ((blockIdx.x * blockDim.x + threadIdx.x) << 2);
    int c = cnt[i];
    const int* ip = idx + (size_t)i * CAP;
    float4 s = make_float4(0.f, 0.f, 0.f, 0.f);
    for (int t = 0; t < c; t++) {
        float4 v = *(const float4*)(src + (size_t)ip[t] * lds + j);
        s.x += v.x; s.y += v.y; s.z += v.z; s.w += v.w;
    }
    *(float4*)(out + (size_t)i * ldo + j) = s;
}

__global__ void gather64b_kernel(const float* __restrict__ src,
                                 const int* __restrict__ idx, const int* __restrict__ cnt,
                                 const float* __restrict__ bias, float* __restrict__ out)
{
    int i = blockIdx.x;
    int c = threadIdx.x;
    int n = cnt[i];
    const int* ip = idx + (size_t)i * CAP;
    float s = 0.f;
    for (int t = 0; t < n; t++) s += src[(size_t)ip[t] * 64 + c];
    out[(size_t)i * 64 + c] = s + bias[c];
}

// C[M,64] = A[M,K] @ B[K,64] (+bias) (optional relu)
__global__ void __launch_bounds__(256)
gemm_n64_kernel(const float* __restrict__ A, const float* __restrict__ B,
                const float* __restrict__ bias, float* __restrict__ C,
                int M, int K, int relu)
{
    __shared__ float As[32][64];
    __shared__ float Bs[32][64];
    int tid = threadIdx.x;
    int m0  = blockIdx.x * 64;
    int ar  = tid >> 3;
    int ac  = (tid & 7) << 2;
    int br  = tid >> 4;
    int bc  = (tid & 15) << 2;
    int wrp = tid >> 5, ln = tid & 31;
    int ty  = ((wrp >> 1) << 2) | (ln >> 3);
    int tx  = ((wrp & 1) << 3) | (ln & 7);

    u64t acc2[4][2];
    #pragma unroll
    for (int i = 0; i < 4; i++) { acc2[i][0] = 0ull; acc2[i][1] = 0ull; }

    for (int k0 = 0; k0 < K; k0 += 32) {
        float4 a0 = *(const float4*)(A + (size_t)(m0 + ar)      * K + k0 + ac);
        float4 a1 = *(const float4*)(A + (size_t)(m0 + ar + 32) * K + k0 + ac);
        float4 b0 = *(const float4*)(B + (size_t)(k0 + br)      * 64 + bc);
        float4 b1 = *(const float4*)(B + (size_t)(k0 + br + 16) * 64 + bc);
        __syncthreads();
        As[ac+0][ar]    = a0.x; As[ac+1][ar]    = a0.y; As[ac+2][ar]    = a0.z; As[ac+3][ar]    = a0.w;
        As[ac+0][ar+32] = a1.x; As[ac+1][ar+32] = a1.y; As[ac+2][ar+32] = a1.z; As[ac+3][ar+32] = a1.w;
        *(float4*)&Bs[br][bc]      = b0;
        *(float4*)&Bs[br + 16][bc] = b1;
        __syncthreads();
        #pragma unroll
        for (int k = 0; k < 32; k++) {
            float4 av = *(const float4*)&As[k][ty << 2];
            float4 bv = *(const float4*)&Bs[k][tx << 2];
            u64t bp0 = ((const u64t*)&bv)[0], bp1 = ((const u64t*)&bv)[1];
            float a[4] = {av.x, av.y, av.z, av.w};
            #pragma unroll
            for (int i = 0; i < 4; i++) {
                u64t ai = bcast2(a[i]);
                fma2(acc2[i][0], ai, bp0);
                fma2(acc2[i][1], ai, bp1);
            }
        }
    }
    int r = m0 + (ty << 2), c = tx << 2;
    #pragma unroll
    for (int i = 0; i < 4; i++) {
        float2 v0 = unpack2(acc2[i][0]);
        float2 v1 = unpack2(acc2[i][1]);
        float vv[4] = {v0.x, v0.y, v1.x, v1.y};
        #pragma unroll
        for (int j = 0; j < 4; j++) {
            float v = vv[j] + (bias ? bias[c + j] : 0.f);
            if (relu) v = fmaxf(v, 0.f);
            C[(size_t)(r + i) * 64 + c + j] = v;
        }
    }
}

// split-K variant: grid (M/64, S)
__global__ void __launch_bounds__(256)
gemm_n64_splitk_kernel(const float* __restrict__ A, const float* __restrict__ B,
                       float* __restrict__ part, int M, int K, int Kc)
{
    __shared__ float As[32][64];
    __shared__ float Bs[32][64];
    int tid = threadIdx.x;
    int m0  = blockIdx.x * 64;
    int s   = blockIdx.y;
    int kb  = s * Kc, ke = kb + Kc;
    int ar  = tid >> 3;
    int ac  = (tid & 7) << 2;
    int br  = tid >> 4;
    int bc  = (tid & 15) << 2;
    int wrp = tid >> 5, ln = tid & 31;
    int ty  = ((wrp >> 1) << 2) | (ln >> 3);
    int tx  = ((wrp & 1) << 3) | (ln & 7);

    u64t acc2[4][2];
    #pragma unroll
    for (int i = 0; i < 4; i++) { acc2[i][0] = 0ull; acc2[i][1] = 0ull; }

    for (int k0 = kb; k0 < ke; k0 += 32) {
        float4 a0 = *(const float4*)(A + (size_t)(m0 + ar)      * K + k0 + ac);
        float4 a1 = *(const float4*)(A + (size_t)(m0 + ar + 32) * K + k0 + ac);
        float4 b0 = *(const float4*)(B + (size_t)(k0 + br)      * 64 + bc);
        float4 b1 = *(const float4*)(B + (size_t)(k0 + br + 16) * 64 + bc);
        __syncthreads();
        As[ac+0][ar]    = a0.x; As[ac+1][ar]    = a0.y; As[ac+2][ar]    = a0.z; As[ac+3][ar]    = a0.w;
        As[ac+0][ar+32] = a1.x; As[ac+1][ar+32] = a1.y; As[ac+2][ar+32] = a1.z; As[ac+3][ar+32] = a1.w;
        *(float4*)&Bs[br][bc]      = b0;
        *(float4*)&Bs[br + 16][bc] = b1;
        __syncthreads();
        #pragma unroll
        for (int k = 0; k < 32; k++) {
            float4 av = *(const float4*)&As[k][ty << 2];
            float4 bv = *(const float4*)&Bs[k][tx << 2];
            u64t bp0 = ((const u64t*)&bv)[0], bp1 = ((const u64t*)&bv)[1];
            float a[4] = {av.x, av.y, av.z, av.w};
            #pragma unroll
            for (int i = 0; i < 4; i++) {
                u64t ai = bcast2(a[i]);
                fma2(acc2[i][0], ai, bp0);
                fma2(acc2[i][1], ai, bp1);
            }
        }
    }
    int r = m0 + (ty << 2), c = tx << 2;
    #pragma unroll
    for (int i = 0; i < 4; i++) {
        float2 v0 = unpack2(acc2[i][0]);
        float2 v1 = unpack2(acc2[i][1]);
        float vv[4] = {v0.x, v0.y, v1.x, v1.y};
        #pragma unroll
        for (int j = 0; j < 4; j++)
            part[(size_t)s * M * 64 + (size_t)(r + i) * 64 + c + j] = vv[j];
    }
}

__global__ void splitk_reduce_kernel(const float* __restrict__ part, const float* __restrict__ bias,
                                     float* __restrict__ C, int M, int S, int relu)
{
    int idx = blockIdx.x * 256 + threadIdx.x;
    if (idx >= M * 64) return;
    float s = 0.f;
    for (int p = 0; p < S; p++) s += part[(size_t)p * M * 64 + idx];
    if (bias) s += bias[idx & 63];
    if (relu) s = fmaxf(s, 0.f);
    C[idx] = s;
}

__global__ void cs_reduce_kernel(const float* __restrict__ CSP, float* __restrict__ CS)
{
    int m = blockIdx.y;
    int j = blockIdx.x * 256 + threadIdx.x;
    float s = 0.f;
    #pragma unroll
    for (int p = 0; p < 32; p++) s += CSP[((size_t)m * 32 + p) * NT + j];
    CS[m * NT + j] = s;
}

__global__ void coefs_kernel(const float* __restrict__ sgw, const float* __restrict__ ffw,
                             const float* __restrict__ f4w,
                             const float* __restrict__ cs, float* __restrict__ coef,
                             float* __restrict__ ct0)
{
    int j = blockIdx.x * 256 + threadIdx.x;
    float m2 = fmaxf(sgw[0], sgw[1]);
    float e0 = expf(sgw[0] - m2), e1 = expf(sgw[1] - m2);
    float sa0 = e0 / (e0 + e1), sa1 = e1 / (e0 + e1);
    float mf = fmaxf(ffw[0], ffw[1]);
    float f0 = expf(ffw[0] - mf), f1 = expf(ffw[1] - mf);
    float fa0 = f0 / (f0 + f1), fa1 = f1 / (f0 + f1);
    float m4 = fmaxf(fmaxf(f4w[0], f4w[1]), fmaxf(f4w[2], f4w[3]));
    float w0 = expf(f4w[0] - m4), w1 = expf(f4w[1] - m4), w2 = expf(f4w[2] - m4), w3 = expf(f4w[3] - m4);
    float ws = w0 + w1 + w2 + w3;
    w0 /= ws; w1 /= ws; w2 /= ws; w3 /= ws;

    float csv[7], cf[7];
    #pragma unroll
    for (int m = 0; m < 7; m++) csv[m] = cs[m * NT + j];
    float uP  = (csv[1] > 0.05f) ? 1.f : 0.f;
    float uQ  = (csv[2] > 0.05f) ? 1.f : 0.f;
    float uFA = (csv[3] > 0.05f) ? 1.f : 0.f;
    float uFS = (csv[4] > 0.05f) ? 1.f : 0.f;
    float uSA = (csv[5] > 0.05f) ? 1.f : 0.f;
    float uSS = (csv[6] > 0.05f) ? 1.f : 0.f;
    float dSem = fmaxf(sa0 * uP  + sa1 * uQ,  1e-12f);
    float dFp  = fmaxf(fa0 * uFA + fa1 * uFS, 1e-12f);
    float dSt  = fmaxf(fa0 * uSA + fa1 * uSS, 1e-12f);

    cf[0] = w0 / fmaxf(csv[0], 1e-12f);
    cf[1] = w1 * sa0 / (fmaxf(csv[1], 1e-12f) * dSem);
    cf[2] = w1 * sa1 / (fmaxf(csv[2], 1e-12f) * dSem);
    cf[3] = w2 * fa0 / (fmaxf(csv[3], 1e-12f) * dFp);
    cf[4] = w2 * fa1 / (fmaxf(csv[4], 1e-12f) * dFp);
    cf[5] = w3 * fa0 / (fmaxf(csv[5], 1e-12f) * dSt);
    cf[6] = w3 * fa1 / (fmaxf(csv[6], 1e-12f) * dSt);

    float c0 = 0.f;
    #pragma unroll
    for (int m = 0; m < 7; m++) { coef[m * NT + j] = cf[m]; c0 += cf[m] * csv[m]; }
    ct0[j] = c0;
}

__global__ void combine_kernel(const float* __restrict__ G,  const float* __restrict__ P,
                               const float* __restrict__ Q,  const float* __restrict__ FA,
                               const float* __restrict__ FS, const float* __restrict__ SA,
                               const float* __restrict__ SS, const float* __restrict__ coef,
                               float* __restrict__ out, float* __restrict__ rowp)
{
    int b = blockIdx.x;
    size_t e = ((size_t)b * 256 + threadIdx.x) << 2;
    int j = (int)(e & (NT - 1));
    float4 r = make_float4(0.f, 0.f, 0.f, 0.f);
#define ACC(buf, m) { float4 v = *(const float4*)((buf) + e);                 \
                      float4 k = *(const float4*)(coef + (m) * NT + j);       \
                      r.x = fmaf(k.x, v.x, r.x); r.y = fmaf(k.y, v.y, r.y);   \
                      r.z = fmaf(k.z, v.z, r.z); r.w = fmaf(k.w, v.w, r.w); }
    ACC(G, 0) ACC(P, 1) ACC(Q, 2) ACC(FA, 3) ACC(FS, 4) ACC(SA, 5) ACC(SS, 6)
#undef ACC
    *(float4*)(out + e) = r;

    float s = r.x + r.y + r.z + r.w;
    #pragma unroll
    for (int o = 16; o; o >>= 1) s += __shfl_xor_sync(0xffffffffu, s, o);
    __shared__ float ws[8];
    int w = threadIdx.x >> 5;
    if ((threadIdx.x & 31) == 0) ws[w] = s;
    __syncthreads();
    if (threadIdx.x == 0) {
        float t = 0.f;
        #pragma unroll
        for (int p = 0; p < 8; p++) t += ws[p];
        rowp[(size_t)(b >> 2) * 4 + (b & 3)] = t;
    }
}

__global__ void ct_final_kernel(const float* __restrict__ ct0, const float* __restrict__ rowp,
                                float* __restrict__ ct)
{
    int j = blockIdx.x * 256 + threadIdx.x;
    ct[j] = ct0[j] + rowp[j * 4 + 0] + rowp[j * 4 + 1] + rowp[j * 4 + 2] + rowp[j * 4 + 3];
}

__global__ void symscale_kernel(float* __restrict__ A, const float* __restrict__ ct)
{
    const int nb = 128;
    int idx = blockIdx.x;
    float nb2 = nb + 0.5f;
    int bi = (int)(nb2 - sqrtf(fmaxf(nb2 * nb2 - 2.0f * idx, 0.f)));
    if (bi < 0) bi = 0;
    if (bi > nb - 1) bi = nb - 1;
    while (bi > 0 && (bi * nb - (bi * (bi - 1)) / 2) > idx) bi--;
    while (((bi + 1) * nb - ((bi + 1) * bi) / 2) <= idx) bi++;
    int bj = bi + (idx - (bi * nb - (bi * (bi - 1)) / 2));

    __shared__ float T1[32][33], T2[32][33];
    int x = threadIdx.x, y0 = threadIdx.y;
    for (int y = y0; y < 32; y += 8) T1[y][x] = A[(size_t)(bi * 32 + y) * NT + bj * 32 + x];
    if (bi != bj)
        for (int y = y0; y < 32; y += 8) T2[y][x] = A[(size_t)(bj * 32 + y) * NT + bi * 32 + x];
    __syncthreads();
    float cj = fmaxf(ct[bj * 32 + x], 1e-12f);
    if (bi == bj) {
        for (int y = y0; y < 32; y += 8)
            A[(size_t)(bi * 32 + y) * NT + bj * 32 + x] = (T1[y][x] + T1[x][y]) / cj;
    } else {
        float ci = fmaxf(ct[bi * 32 + x], 1e-12f);
        for (int y = y0; y < 32; y += 8)
            A[(size_t)(bi * 32 + y) * NT + bj * 32 + x] = (T1[y][x] + T2[x][y]) / cj;
        for (int y = y0; y < 32; y += 8)
            A[(size_t)(bj * 32 + y) * NT + bi * 32 + x] = (T2[y][x] + T1[x][y]) / ci;
    }
}

__global__ void x1w2_kernel(const float* __restrict__ X1, const float* __restrict__ W2,
                            float* __restrict__ H2)
{
    int i = blockIdx.x * 256 + threadIdx.x;
    if (i >= NT) return;
    float s0 = 0.f, s1 = 0.f, s2 = 0.f;
    #pragma unroll 8
    for (int k = 0; k < COM; k++) {
        float x = X1[(size_t)i * COM + k];
        s0 = fmaf(x, W2[k * 3 + 0], s0);
        s1 = fmaf(x, W2[k * 3 + 1], s1);
        s2 = fmaf(x, W2[k * 3 + 2], s2);
    }
    H2[i * 3 + 0] = s0; H2[i * 3 + 1] = s1; H2[i * 3 + 2] = s2;
}

__global__ void logits_kernel(const float* __restrict__ A, const float* __restrict__ H2,
                              const float* __restrict__ b2, float* __restrict__ out)
{
    int i = blockIdx.x, tid = threadIdx.x;
    const float* row = A + (size_t)i * NT;
    float s0 = 0.f, s1 = 0.f, s2 = 0.f;
    for (int k = tid; k < NT; k += 256) {
        float a = row[k];
        s0 = fmaf(a, H2[k * 3 + 0], s0);
        s1 = fmaf(a, H2[k * 3 + 1], s1);
        s2 = fmaf(a, H2[k * 3 + 2], s2);
    }
    #pragma unroll
    for (int o = 16; o; o >>= 1) {
        s0 += __shfl_xor_sync(0xffffffffu, s0, o);
        s1 += __shfl_xor_sync(0xffffffffu, s1, o);
        s2 += __shfl_xor_sync(0xffffffffu, s2, o);
    }
    __shared__ float sh[3][8];
    int w = tid >> 5, l = tid & 31;
    if (l == 0) { sh[0][w] = s0; sh[1][w] = s1; sh[2][w] = s2; }
    __syncthreads();
    if (tid == 0) {
        float x0 = 0.f, x1 = 0.f, x2 = 0.f;
        #pragma unroll
        for (int t = 0; t < 8; t++) { x0 += sh[0][t]; x1 += sh[1][t]; x2 += sh[2][t]; }
        x0 += b2[0]; x1 += b2[1]; x2 += b2[2];
        float m  = fmaxf(x0, fmaxf(x1, x2));
        float ls = logf(expf(x0 - m) + expf(x1 - m) + expf(x2 - m));
        out[i * 3 + 0] = x0 - m - ls;
        out[i * 3 + 1] = x1 - m - ls;
        out[i * 3 + 2] = x2 - m - ls;
    }
}

// ---------------- host orchestration (single stream) -------------------------

extern "C" void kernel_launch(void* const* d_in, const int* in_sizes, int n_in,
                              void* d_out, int out_size)
{
    const float* features  = (const float*)d_in[0];
    const float* adj_ori   = (const float*)d_in[1];
    const float* mp_pap    = (const float*)d_in[2];
    const float* mp_psp    = (const float*)d_in[3];
    const float* fgo_w     = (const float*)d_in[6];
    const float* fpo_w     = (const float*)d_in[7];
    const float* sgg_pap_w = (const float*)d_in[8];
    const float* sgg_psp_w = (const float*)d_in[9];
    const float* sg_agg_w  = (const float*)d_in[10];
    const float* f_agg_f_w = (const float*)d_in[11];
    const float* f_agg_w   = (const float*)d_in[12];
    const float* topo_W_a  = (const float*)d_in[13];
    const float* topo_b_a  = (const float*)d_in[14];
    const float* topo_W_s  = (const float*)d_in[15];
    const float* topo_b_s  = (const float*)d_in[16];
    const float* fgt_w_a   = (const float*)d_in[17];
    const float* fgt_w_s   = (const float*)d_in[18];
    const float* gcn_W1    = (const float*)d_in[19];
    const float* gcn_b1    = (const float*)d_in[20];
    const float* gcn_W2    = (const float*)d_in[21];
    const float* gcn_b2    = (const float*)d_in[22];
    (void)in_sizes; (void)n_in; (void)out_size;

    float* out   = (float*)d_out;
    float* NAdj  = out + (size_t)NT * NCLS;

    float* big = nullptr; float* sm = nullptr; int* ib = nullptr;
    cudaGetSymbolAddress((void**)&big, g_big);
    cudaGetSymbolAddress((void**)&sm,  g_small);
    cudaGetSymbolAddress((void**)&ib,  g_ibuf);

    float* G   = big + 0ll * NT * NT;
    float* P   = big + 1ll * NT * NT;
    float* Q   = big + 2ll * NT * NT;
    float* FAb = big + 3ll * NT * NT;
    float* FSb = big + 4ll * NT * NT;
    float* SAb = big + 5ll * NT * NT;   // sim_r_A, then s_h_A
    float* SSb = big + 6ll * NT * NT;

    float* XN0   = sm + OFF_XN0;
    float* XN1   = sm + OFF_XN1;
    float* XN2   = sm + OFF_XN2;
    float* XN3   = sm + OFF_XN3;
    float* XN4   = sm + OFF_XN4;
    float* SIMS  = sm + OFF_SIMS;
    float* FPA   = sm + OFF_FPA;
    float* FPS   = sm + OFF_FPS;
    float* THA   = sm + OFF_THA;
    float* THS   = sm + OFF_THS;
    float* SWA   = sm + OFF_SWA;
    float* SWS   = sm + OFF_SWS;
    float* H0    = sm + OFF_H0;
    float* X1    = sm + OFF_X1;
    float* H2    = sm + OFF_H2;
    float* CS    = sm + OFF_CS;
    float* COEF  = sm + OFF_COEF;
    float* CT0   = sm + OFF_CT0;
    float* CT    = sm + OFF_CT;
    float* ROWP  = sm + OFF_ROWP;
    float* CSP   = sm + OFF_CSP;
    float* SPART = sm + OFF_SPART;

    int* IDXA = ib + OFF_IDXA; int* CNTA = ib + OFF_CNTA;
    int* IDXS = ib + OFF_IDXS; int* CNTS = ib + OFF_CNTS;

    const int TRI32 = 32 * 33 / 2;   // 528
    const int TRI8  = 8 * 9 / 2;     // 36
    dim3 bSym(32, 8);
    dim3 gSim2(TRI32, 2), gSimS(TRI8, 1);

    // ---- batch 1: g_targ & sim_r_A (K=256, th=0.1) ----
    prep_norm_kernel<<<NT / 4, 128>>>(features, fgo_w, XN0, NT, FEAT, 2);
    prep_norm_kernel<<<NT / 4, 128>>>(features + (size_t)NT * FEAT, fgo_w, XN1, NAr, FEAT, 2);
    simgemm_kernel<<<gSim2, 256>>>(XN0, G, CSP + 0ll * 32 * NT,
                                   XN1, SAb, nullptr, NT, 256, 0.5f, 0.1f, 32);

    // ---- batch 2: sem_pap & sem_psp (K=128, th=0.1) ----
    prep_norm_kernel<<<NT / 4, 128>>>(mp_pap, sgg_pap_w, XN2, NT, MPD, 2);
    prep_norm_kernel<<<NT / 4, 128>>>(mp_psp, sgg_psp_w, XN3, NT, MPD, 2);
    simgemm_kernel<<<gSim2, 256>>>(XN2, P, CSP + 1ll * 32 * NT,
                                   XN3, Q, CSP + 2ll * 32 * NT, NT, 128, 0.5f, 0.1f, 32);

    // ---- A-relation topo pieces ----
    build_idx_kernel<<<NT, 128>>>(adj_ori, NT, NAr, IDXA, CNTA);
    gemm_n64_splitk_kernel<<<dim3(NT / 64, 8), 256>>>(SAb, topo_W_a, SPART, NT, NAr, NAr / 8);
    splitk_reduce_kernel<<<(NT * 64) / 256, 256>>>(SPART, nullptr, SWA, NT, 8, 0);
    gather64b_kernel<<<NT, 64>>>(SWA, IDXA, CNTA, topo_b_a, THA);
    gather_sum_kernel<<<dim3(1, NT), 32>>>(features + (size_t)NT * FEAT, FEAT, IDXA, CNTA, FPA, FEAT);

    // ---- S-relation topo pieces ----
    build_idx_kernel<<<NT, 128>>>(adj_ori, NT + NAr, NSr, IDXS, CNTS);
    prep_norm_kernel<<<NSr / 4, 128>>>(features + (size_t)(NT + NAr) * FEAT, fgo_w, XN4, NSr, FEAT, 2);
    simgemm_kernel<<<gSimS, 256>>>(XN4, SIMS, nullptr,
                                   nullptr, nullptr, nullptr, NSr, 256, 0.5f, 0.1f, 8);
    gemm_n64_splitk_kernel<<<dim3(NSr / 64, 8), 256>>>(SIMS, topo_W_s, SPART, NSr, NSr, NSr / 8);
    splitk_reduce_kernel<<<(NSr * 64) / 256, 256>>>(SPART, nullptr, SWS, NSr, 8, 0);
    gather64b_kernel<<<NT, 64>>>(SWS, IDXS, CNTS, topo_b_s, THS);
    gather_sum_kernel<<<dim3(1, NT), 32>>>(features + (size_t)(NT + NAr) * FEAT, FEAT, IDXS, CNTS, FPS, FEAT);

    // ---- batch 3: f_h_A & f_h_S (K=256, th=0.2) ----
    prep_norm_kernel<<<NT / 4, 128>>>(FPA, fpo_w, XN0, NT, FEAT, 2);
    prep_norm_kernel<<<NT / 4, 128>>>(FPS, fpo_w, XN1, NT, FEAT, 2);
    simgemm_kernel<<<gSim2, 256>>>(XN0, FAb, CSP + 3ll * 32 * NT,
                                   XN1, FSb, CSP + 4ll * 32 * NT, NT, 256, 0.5f, 0.2f, 32);

    // ---- batch 4: s_h_A & s_h_S (K=128, th=0.1) ----
    prep_norm_kernel<<<NT / 4, 128>>>(THA, fgt_w_a, XN2, NT, COM, 2);
    prep_norm_kernel<<<NT / 4, 128>>>(THS, fgt_w_s, XN3, NT, COM, 2);
    simgemm_kernel<<<gSim2, 256>>>(XN2, SAb, CSP + 5ll * 32 * NT,
                                   XN3, SSb, CSP + 6ll * 32 * NT, NT, 128, 0.5f, 0.1f, 32);

    // ---- GCN first half (independent) ----
    gemm_n64_kernel<<<NT / 64, 256>>>(features, gcn_W1, nullptr, H0, NT, FEAT, 0);

    // ---- fused channel attention ----
    cs_reduce_kernel<<<dim3(NT / 256, 7), 256>>>(CSP, CS);
    coefs_kernel<<<NT / 256, 256>>>(sg_agg_w, f_agg_f_w, f_agg_w, CS, COEF, CT0);
    combine_kernel<<<(NT * NT) / 1024, 256>>>(G, P, Q, FAb, FSb, SAb, SSb, COEF, NAdj, ROWP);
    ct_final_kernel<<<NT / 256, 256>>>(CT0, ROWP, CT);
    symscale_kernel<<<128 * 129 / 2, bSym>>>(NAdj, CT);

    // ---- GCN second half ----
    gemm_n64_splitk_kernel<<<dim3(NT / 64, 8), 256>>>(NAdj, H0, SPART, NT, NT, NT / 8);
    splitk_reduce_kernel<<<(NT * 64) / 256, 256>>>(SPART, gcn_b1, X1, NT, 8, 1);
    x1w2_kernel<<<NT / 256, 256>>>(X1, gcn_W2, H2);
    logits_kernel<<<NT, 256>>>(NAdj, H2, gcn_b2, out);
}

// round 10
// speedup vs baseline: 1.2550x; 1.0565x over previous
#include <cuda_runtime.h>
#include <math.h>

#define NT   4096
#define NAr  4096
#define NSr  1024
#define NALL 9216
#define FEAT 128
#define COM  64
#define MPD  64
#define NCLS 3
#define CAP  128   // max nnz per adjacency row (expected ~20, p=0.005)

// ---------------- static device scratch (no allocations allowed) -------------
__device__ float g_big[7ll * NT * NT];

#define OFF_XN0   0
#define OFF_XN1   (OFF_XN0  + NT*256)
#define OFF_XN2   (OFF_XN1  + NT*256)
#define OFF_XN3   (OFF_XN2  + NT*256)
#define OFF_XN4   (OFF_XN3  + NT*256)
#define OFF_SIMS  (OFF_XN4  + NT*256)       // 1024*1024
#define OFF_FPA   (OFF_SIMS + NSr*NSr)      // 4096*128
#define OFF_FPS   (OFF_FPA  + NT*FEAT)      // 4096*128
#define OFF_THA   (OFF_FPS  + NT*FEAT)      // 4096*64
#define OFF_THS   (OFF_THA  + NT*COM)       // 4096*64
#define OFF_SWA   (OFF_THS  + NT*COM)       // 4096*64
#define OFF_SWS   (OFF_SWA  + NT*COM)       // 1024*64
#define OFF_H0    (OFF_SWS  + NSr*COM)      // 4096*64
#define OFF_X1    (OFF_H0   + NT*COM)       // 4096*64
#define OFF_H2    (OFF_X1   + NT*COM)       // 4096*3
#define OFF_CS    (OFF_H2   + NT*NCLS)      // 7*4096
#define OFF_COEF  (OFF_CS   + 7*NT)         // 7*4096
#define OFF_CT    (OFF_COEF + 7*NT)         // 4096
#define OFF_ROWP  (OFF_CT   + NT)           // 4096*4
#define OFF_CSP   (OFF_ROWP + 4*NT)         // 7*32*4096
#define OFF_SPART (OFF_CSP  + 7*32*NT)      // 8*4096*64
#define SMALL_TOT (OFF_SPART + 8*NT*64)
__device__ float g_small[SMALL_TOT];

#define OFF_IDXA 0
#define OFF_CNTA (OFF_IDXA + NT*CAP)
#define OFF_IDXS (OFF_CNTA + NT)
#define OFF_CNTS (OFF_IDXS + NT*CAP)
#define IBUF_TOT (OFF_CNTS + NT)
__device__ int g_ibuf[IBUF_TOT];

// ---------------- packed f32x2 helpers (bit-identical IEEE fp32 per lane) ----
typedef unsigned long long u64t;

__device__ __forceinline__ u64t bcast2(float a)
{
    u64t r;
    asm("mov.b64 %0, {%1, %1};" : "=l"(r) : "r"(__float_as_uint(a)));
    return r;
}
__device__ __forceinline__ void fma2(u64t& acc, u64t a, u64t b)
{
    asm("fma.rn.f32x2 %0, %1, %2, %0;" : "+l"(acc) : "l"(a), "l"(b));
}
__device__ __forceinline__ float2 unpack2(u64t v)
{
    unsigned int lo, hi;
    asm("mov.b64 {%0, %1}, %2;" : "=r"(lo), "=r"(hi) : "l"(v));
    return make_float2(__uint_as_float(lo), __uint_as_float(hi));
}

// ---------------- job structs (passed by value as kernel args) ---------------
struct PrepJob { const float* src; const float* w; float* dst; int N; int D; };
struct PrepJobs { PrepJob j[5]; };
struct SimJob  { const float* X; float* C; float* cs; int N; int K; int nBlk; float th; };
struct SimJobs { SimJob j[5]; };

// ---------------- kernels ----------------------------------------------------

// Multi-job per-head weighted + L2-row-normalized features: dst[N, H*D], H=2.
__global__ void prep_norm_multi_kernel(PrepJobs jobs)
{
    PrepJob jb = jobs.j[blockIdx.y];
    int row  = blockIdx.x * (blockDim.x >> 5) + (threadIdx.x >> 5);
    int lane = threadIdx.x & 31;
    if (row >= jb.N) return;
    const float* src = jb.src;
    const float* w   = jb.w;
    float* dst = jb.dst;
    int D = jb.D;
    int HD = 2 * D;
    for (int h = 0; h < 2; h++) {
        float ss = 0.f;
        for (int d = lane; d < D; d += 32) {
            float v = src[(size_t)row * D + d] * w[h * D + d];
            ss += v * v;
        }
        #pragma unroll
        for (int o = 16; o; o >>= 1) ss += __shfl_xor_sync(0xffffffffu, ss, o);
        float inv = 1.f / fmaxf(sqrtf(ss), 1e-12f);
        for (int d = lane; d < D; d += 32)
            dst[(size_t)row * HD + h * D + d] = src[(size_t)row * D + d] * w[h * D + d] * inv;
    }
}

__device__ __forceinline__ float thrf(float v, float scale, float th)
{
    v *= scale;
    return (v < th) ? 0.f : v;
}

// Multi-job C = threshold(0.5 * X @ X^T), row-major X[N,K]. blockIdx.y selects job.
// Triangular grid over blockIdx.x (dead blocks for smaller jobs exit early).
// Inner loop / per-element accumulation order identical to the round-5 kernel.
__global__ void __launch_bounds__(256, 2)
simgemm_multi_kernel(SimJobs jobs)
{
    SimJob jb = jobs.j[blockIdx.y];
    const int nBlk = jb.nBlk;
    int idx = blockIdx.x;
    if (idx >= nBlk * (nBlk + 1) / 2) return;
    const float* X = jb.X;
    float* C       = jb.C;
    float* csPart  = jb.cs;
    const int N = jb.N, K = jb.K;
    const float th = jb.th;

    float nb2 = nBlk + 0.5f;
    int by = (int)(nb2 - sqrtf(fmaxf(nb2 * nb2 - 2.0f * idx, 0.f)));
    if (by < 0) by = 0;
    if (by > nBlk - 1) by = nBlk - 1;
    while (by > 0 && (by * nBlk - (by * (by - 1)) / 2) > idx) by--;
    while (((by + 1) * nBlk - ((by + 1) * by) / 2) <= idx) by++;
    int bx = by + (idx - (by * nBlk - (by * (by - 1)) / 2));

    const int m0 = by * 128, n0 = bx * 128;

    __shared__ float As[2][16][128];
    __shared__ float Bs[2][16][128];

    const int tid = threadIdx.x;
    const int ldr = tid >> 2;
    const int ldc = (tid & 3) << 2;
    const int wrp = tid >> 5;
    const int ln  = tid & 31;
    const int ty  = ((wrp >> 1) << 2) | (ln >> 3);   // 0..15
    const int tx  = ((wrp & 1) << 3) | (ln & 7);     // 0..15
    const int ry  = ty << 3;
    const int rx  = tx << 3;

    u64t acc2[8][4];
    #pragma unroll
    for (int i = 0; i < 8; i++)
        #pragma unroll
        for (int j = 0; j < 4; j++) acc2[i][j] = 0ull;

    float4 a0, a1, b0, b1;

#define LOADG(k0) {                                                             \
    a0 = *(const float4*)(X + (size_t)(m0 + ldr)      * K + (k0) + ldc);        \
    a1 = *(const float4*)(X + (size_t)(m0 + ldr + 64) * K + (k0) + ldc);        \
    b0 = *(const float4*)(X + (size_t)(n0 + ldr)      * K + (k0) + ldc);        \
    b1 = *(const float4*)(X + (size_t)(n0 + ldr + 64) * K + (k0) + ldc); }

#define STORES(bf) {                                                            \
    As[bf][ldc+0][ldr]    = a0.x; As[bf][ldc+1][ldr]    = a0.y;                 \
    As[bf][ldc+2][ldr]    = a0.z; As[bf][ldc+3][ldr]    = a0.w;                 \
    As[bf][ldc+0][ldr+64] = a1.x; As[bf][ldc+1][ldr+64] = a1.y;                 \
    As[bf][ldc+2][ldr+64] = a1.z; As[bf][ldc+3][ldr+64] = a1.w;                 \
    Bs[bf][ldc+0][ldr]    = b0.x; Bs[bf][ldc+1][ldr]    = b0.y;                 \
    Bs[bf][ldc+2][ldr]    = b0.z; Bs[bf][ldc+3][ldr]    = b0.w;                 \
    Bs[bf][ldc+0][ldr+64] = b1.x; Bs[bf][ldc+1][ldr+64] = b1.y;                 \
    Bs[bf][ldc+2][ldr+64] = b1.z; Bs[bf][ldc+3][ldr+64] = b1.w; }

#define COMPUTE(bf) {                                                           \
    _Pragma("unroll")                                                           \
    for (int k = 0; k < 16; k++) {                                              \
        float4 av0 = *(const float4*)&As[bf][k][ry];                            \
        float4 av1 = *(const float4*)&As[bf][k][ry + 4];                        \
        float4 bv0 = *(const float4*)&Bs[bf][k][rx];                            \
        float4 bv1 = *(const float4*)&Bs[bf][k][rx + 4];                        \
        u64t bp[4];                                                             \
        bp[0] = ((const u64t*)&bv0)[0]; bp[1] = ((const u64t*)&bv0)[1];         \
        bp[2] = ((const u64t*)&bv1)[0]; bp[3] = ((const u64t*)&bv1)[1];         \
        float a[8] = {av0.x,av0.y,av0.z,av0.w,av1.x,av1.y,av1.z,av1.w};         \
        _Pragma("unroll")                                                       \
        for (int i = 0; i < 8; i++) {                                           \
            u64t ai = bcast2(a[i]);                                             \
            fma2(acc2[i][0], ai, bp[0]);                                        \
            fma2(acc2[i][1], ai, bp[1]);                                        \
            fma2(acc2[i][2], ai, bp[2]);                                        \
            fma2(acc2[i][3], ai, bp[3]);                                        \
        }                                                                       \
    } }

    LOADG(0);
    STORES(0);
    __syncthreads();
    int buf = 0;
    for (int k0 = 16; k0 < K; k0 += 16) {
        LOADG(k0);
        COMPUTE(buf);
        STORES(buf ^ 1);
        __syncthreads();
        buf ^= 1;
    }
    COMPUTE(buf);

#undef LOADG
#undef STORES
#undef COMPUTE

    float acc[8][8];
    #pragma unroll
    for (int i = 0; i < 8; i++)
        #pragma unroll
        for (int jp = 0; jp < 4; jp++) {
            float2 v = unpack2(acc2[i][jp]);
            acc[i][2 * jp + 0] = thrf(v.x, 0.5f, th);
            acc[i][2 * jp + 1] = thrf(v.y, 0.5f, th);
        }

    #pragma unroll
    for (int i = 0; i < 8; i++) {
        #pragma unroll
        for (int j = 0; j < 8; j += 4) {
            float4 v = make_float4(acc[i][j], acc[i][j+1], acc[i][j+2], acc[i][j+3]);
            *(float4*)(C + (size_t)(m0 + ry + i) * N + (n0 + rx + j)) = v;
        }
    }
    if (bx > by) {
        #pragma unroll
        for (int j = 0; j < 8; j++) {
            #pragma unroll
            for (int i = 0; i < 8; i += 4) {
                float4 v = make_float4(acc[i][j], acc[i+1][j], acc[i+2][j], acc[i+3][j]);
                *(float4*)(C + (size_t)(n0 + rx + j) * N + (m0 + ry + i)) = v;
            }
        }
    }

    if (csPart) {
        __syncthreads();
        float* red = (float*)As;
        #pragma unroll
        for (int jj = 0; jj < 8; jj++) {
            float s = 0.f;
            #pragma unroll
            for (int i = 0; i < 8; i++) s += acc[i][jj];
            red[ty * 128 + rx + jj] = s;
        }
        __syncthreads();
        if (tid < 128) {
            float s = 0.f;
            #pragma unroll
            for (int p = 0; p < 16; p++) s += red[p * 128 + tid];
            csPart[(size_t)by * N + n0 + tid] = s;
        }
        if (bx > by) {
            __syncthreads();
            #pragma unroll
            for (int ii = 0; ii < 8; ii++) {
                float s = 0.f;
                #pragma unroll
                for (int j = 0; j < 8; j++) s += acc[ii][j];
                red[tx * 128 + ry + ii] = s;
            }
            __syncthreads();
            if (tid < 128) {
                float s = 0.f;
                #pragma unroll
                for (int p = 0; p < 16; p++) s += red[p * 128 + tid];
                csPart[(size_t)bx * N + m0 + tid] = s;
            }
        }
    }
}

// Deterministic ballot-compacted nonzero index list; 4 warps scan disjoint
// segments, merged in segment order.
__global__ void build_idx_kernel(const float* __restrict__ adj, int col_off, int NR,
                                 int* __restrict__ idx, int* __restrict__ cnt)
{
    __shared__ int sidx[4][CAP];
    __shared__ int scnt[4];
    int i = blockIdx.x;
    const float* r = adj + (size_t)i * NALL + col_off;
    int w = threadIdx.x >> 5, lane = threadIdx.x & 31;
    int seg = NR >> 2;
    int b0  = w * seg;
    int count = 0;
    for (int base = b0; base < b0 + seg; base += 32) {
        float v = r[base + lane];
        unsigned m = __ballot_sync(0xffffffffu, v != 0.f);
        int pre = __popc(m & ((1u << lane) - 1u));
        if (v != 0.f && (count + pre) < CAP) sidx[w][count + pre] = base + lane;
        count += __popc(m);
    }
    if (lane == 0) scnt[w] = min(count, CAP);
    __syncthreads();
    int myoff = 0, tot = 0;
    #pragma unroll
    for (int p = 0; p < 4; p++) {
        if (p < w) myoff += scnt[p];
        tot += scnt[p];
    }
    for (int t = lane; t < scnt[w]; t += 32) {
        int pos = myoff + t;
        if (pos < CAP) idx[(size_t)i * CAP + pos] = sidx[w][t];
    }
    if (threadIdx.x == 0) cnt[i] = min(tot, CAP);
}

__global__ void gather_sum_kernel(const float* __restrict__ src, int lds,
                                  const int* __restrict__ idx, const int* __restrict__ cnt,
                                  float* __restrict__ out, int ldo)
{
    int i = blockIdx.y;
    int j = ((blockIdx.x * blockDim.x + threadIdx.x) << 2);
    int c = cnt[i];
    const int* ip = idx + (size_t)i * CAP;
    float4 s = make_float4(0.f, 0.f, 0.f, 0.f);
    for (int t = 0; t < c; t++) {
        float4 v = *(const float4*)(src + (size_t)ip[t] * lds + j);
        s.x += v.x; s.y += v.y; s.z += v.z; s.w += v.w;
    }
    *(float4*)(out + (size_t)i * ldo + j) = s;
}

__global__ void gather64b_kernel(const float* __restrict__ src,
                                 const int* __restrict__ idx, const int* __restrict__ cnt,
                                 const float* __restrict__ bias, float* __restrict__ out)
{
    int i = blockIdx.x;
    int c = threadIdx.x;
    int n = cnt[i];
    const int* ip = idx + (size_t)i * CAP;
    float s = 0.f;
    for (int t = 0; t < n; t++) s += src[(size_t)ip[t] * 64 + c];
    out[(size_t)i * 64 + c] = s + bias[c];
}

// C[M,64] = A[M,K] @ B[K,64] (+bias) (optional relu)
__global__ void __launch_bounds__(256)
gemm_n64_kernel(const float* __restrict__ A, const float* __restrict__ B,
                const float* __restrict__ bias, float* __restrict__ C,
                int M, int K, int relu)
{
    __shared__ float As[32][64];
    __shared__ float Bs[32][64];
    int tid = threadIdx.x;
    int m0  = blockIdx.x * 64;
    int ar  = tid >> 3;
    int ac  = (tid & 7) << 2;
    int br  = tid >> 4;
    int bc  = (tid & 15) << 2;
    int wrp = tid >> 5, ln = tid & 31;
    int ty  = ((wrp >> 1) << 2) | (ln >> 3);
    int tx  = ((wrp & 1) << 3) | (ln & 7);

    u64t acc2[4][2];
    #pragma unroll
    for (int i = 0; i < 4; i++) { acc2[i][0] = 0ull; acc2[i][1] = 0ull; }

    for (int k0 = 0; k0 < K; k0 += 32) {
        float4 a0 = *(const float4*)(A + (size_t)(m0 + ar)      * K + k0 + ac);
        float4 a1 = *(const float4*)(A + (size_t)(m0 + ar + 32) * K + k0 + ac);
        float4 b0 = *(const float4*)(B + (size_t)(k0 + br)      * 64 + bc);
        float4 b1 = *(const float4*)(B + (size_t)(k0 + br + 16) * 64 + bc);
        __syncthreads();
        As[ac+0][ar]    = a0.x; As[ac+1][ar]    = a0.y; As[ac+2][ar]    = a0.z; As[ac+3][ar]    = a0.w;
        As[ac+0][ar+32] = a1.x; As[ac+1][ar+32] = a1.y; As[ac+2][ar+32] = a1.z; As[ac+3][ar+32] = a1.w;
        *(float4*)&Bs[br][bc]      = b0;
        *(float4*)&Bs[br + 16][bc] = b1;
        __syncthreads();
        #pragma unroll
        for (int k = 0; k < 32; k++) {
            float4 av = *(const float4*)&As[k][ty << 2];
            float4 bv = *(const float4*)&Bs[k][tx << 2];
            u64t bp0 = ((const u64t*)&bv)[0], bp1 = ((const u64t*)&bv)[1];
            float a[4] = {av.x, av.y, av.z, av.w};
            #pragma unroll
            for (int i = 0; i < 4; i++) {
                u64t ai = bcast2(a[i]);
                fma2(acc2[i][0], ai, bp0);
                fma2(acc2[i][1], ai, bp1);
            }
        }
    }
    int r = m0 + (ty << 2), c = tx << 2;
    #pragma unroll
    for (int i = 0; i < 4; i++) {
        float2 v0 = unpack2(acc2[i][0]);
        float2 v1 = unpack2(acc2[i][1]);
        float vv[4] = {v0.x, v0.y, v1.x, v1.y};
        #pragma unroll
        for (int j = 0; j < 4; j++) {
            float v = vv[j] + (bias ? bias[c + j] : 0.f);
            if (relu) v = fmaxf(v, 0.f);
            C[(size_t)(r + i) * 64 + c + j] = v;
        }
    }
}

// split-K variant: grid (M/64, S)
__global__ void __launch_bounds__(256)
gemm_n64_splitk_kernel(const float* __restrict__ A, const float* __restrict__ B,
                       float* __restrict__ part, int M, int K, int Kc)
{
    __shared__ float As[32][64];
    __shared__ float Bs[32][64];
    int tid = threadIdx.x;
    int m0  = blockIdx.x * 64;
    int s   = blockIdx.y;
    int kb  = s * Kc, ke = kb + Kc;
    int ar  = tid >> 3;
    int ac  = (tid & 7) << 2;
    int br  = tid >> 4;
    int bc  = (tid & 15) << 2;
    int wrp = tid >> 5, ln = tid & 31;
    int ty  = ((wrp >> 1) << 2) | (ln >> 3);
    int tx  = ((wrp & 1) << 3) | (ln & 7);

    u64t acc2[4][2];
    #pragma unroll
    for (int i = 0; i < 4; i++) { acc2[i][0] = 0ull; acc2[i][1] = 0ull; }

    for (int k0 = kb; k0 < ke; k0 += 32) {
        float4 a0 = *(const float4*)(A + (size_t)(m0 + ar)      * K + k0 + ac);
        float4 a1 = *(const float4*)(A + (size_t)(m0 + ar + 32) * K + k0 + ac);
        float4 b0 = *(const float4*)(B + (size_t)(k0 + br)      * 64 + bc);
        float4 b1 = *(const float4*)(B + (size_t)(k0 + br + 16) * 64 + bc);
        __syncthreads();
        As[ac+0][ar]    = a0.x; As[ac+1][ar]    = a0.y; As[ac+2][ar]    = a0.z; As[ac+3][ar]    = a0.w;
        As[ac+0][ar+32] = a1.x; As[ac+1][ar+32] = a1.y; As[ac+2][ar+32] = a1.z; As[ac+3][ar+32] = a1.w;
        *(float4*)&Bs[br][bc]      = b0;
        *(float4*)&Bs[br + 16][bc] = b1;
        __syncthreads();
        #pragma unroll
        for (int k = 0; k < 32; k++) {
            float4 av = *(const float4*)&As[k][ty << 2];
            float4 bv = *(const float4*)&Bs[k][tx << 2];
            u64t bp0 = ((const u64t*)&bv)[0], bp1 = ((const u64t*)&bv)[1];
            float a[4] = {av.x, av.y, av.z, av.w};
            #pragma unroll
            for (int i = 0; i < 4; i++) {
                u64t ai = bcast2(a[i]);
                fma2(acc2[i][0], ai, bp0);
                fma2(acc2[i][1], ai, bp1);
            }
        }
    }
    int r = m0 + (ty << 2), c = tx << 2;
    #pragma unroll
    for (int i = 0; i < 4; i++) {
        float2 v0 = unpack2(acc2[i][0]);
        float2 v1 = unpack2(acc2[i][1]);
        float vv[4] = {v0.x, v0.y, v1.x, v1.y};
        #pragma unroll
        for (int j = 0; j < 4; j++)
            part[(size_t)s * M * 64 + (size_t)(r + i) * 64 + c + j] = vv[j];
    }
}

__global__ void splitk_reduce_kernel(const float* __restrict__ part, const float* __restrict__ bias,
                                     float* __restrict__ C, int M, int S, int relu)
{
    int idx = blockIdx.x * 256 + threadIdx.x;
    if (idx >= M * 64) return;
    float s = 0.f;
    for (int p = 0; p < S; p++) s += part[(size_t)p * M * 64 + idx];
    if (bias) s += bias[idx & 63];
    if (relu) s = fmaxf(s, 0.f);
    C[idx] = s;
}

__global__ void cs_reduce_kernel(const float* __restrict__ CSP, float* __restrict__ CS)
{
    int m = blockIdx.y;
    int j = blockIdx.x * 256 + threadIdx.x;
    float s = 0.f;
    #pragma unroll
    for (int p = 0; p < 32; p++) s += CSP[((size_t)m * 32 + p) * NT + j];
    CS[m * NT + j] = s;
}

// per-column combine coefficients (handles all-zero columns of base matrices)
__global__ void coefs_kernel(const float* __restrict__ sgw, const float* __restrict__ ffw,
                             const float* __restrict__ f4w,
                             const float* __restrict__ cs, float* __restrict__ coef)
{
    int j = blockIdx.x * 256 + threadIdx.x;
    float m2 = fmaxf(sgw[0], sgw[1]);
    float e0 = expf(sgw[0] - m2), e1 = expf(sgw[1] - m2);
    float sa0 = e0 / (e0 + e1), sa1 = e1 / (e0 + e1);
    float mf = fmaxf(ffw[0], ffw[1]);
    float f0 = expf(ffw[0] - mf), f1 = expf(ffw[1] - mf);
    float fa0 = f0 / (f0 + f1), fa1 = f1 / (f0 + f1);
    float m4 = fmaxf(fmaxf(f4w[0], f4w[1]), fmaxf(f4w[2], f4w[3]));
    float w0 = expf(f4w[0] - m4), w1 = expf(f4w[1] - m4), w2 = expf(f4w[2] - m4), w3 = expf(f4w[3] - m4);
    float ws = w0 + w1 + w2 + w3;
    w0 /= ws; w1 /= ws; w2 /= ws; w3 /= ws;

    float csv[7];
    #pragma unroll
    for (int m = 0; m < 7; m++) csv[m] = cs[m * NT + j];
    float uP  = (csv[1] > 0.05f) ? 1.f : 0.f;
    float uQ  = (csv[2] > 0.05f) ? 1.f : 0.f;
    float uFA = (csv[3] > 0.05f) ? 1.f : 0.f;
    float uFS = (csv[4] > 0.05f) ? 1.f : 0.f;
    float uSA = (csv[5] > 0.05f) ? 1.f : 0.f;
    float uSS = (csv[6] > 0.05f) ? 1.f : 0.f;
    float dSem = fmaxf(sa0 * uP  + sa1 * uQ,  1e-12f);
    float dFp  = fmaxf(fa0 * uFA + fa1 * uFS, 1e-12f);
    float dSt  = fmaxf(fa0 * uSA + fa1 * uSS, 1e-12f);

    coef[0 * NT + j] = w0 / fmaxf(csv[0], 1e-12f);
    coef[1 * NT + j] = w1 * sa0 / (fmaxf(csv[1], 1e-12f) * dSem);
    coef[2 * NT + j] = w1 * sa1 / (fmaxf(csv[2], 1e-12f) * dSem);
    coef[3 * NT + j] = w2 * fa0 / (fmaxf(csv[3], 1e-12f) * dFp);
    coef[4 * NT + j] = w2 * fa1 / (fmaxf(csv[4], 1e-12f) * dFp);
    coef[5 * NT + j] = w3 * fa0 / (fmaxf(csv[5], 1e-12f) * dSt);
    coef[6 * NT + j] = w3 * fa1 / (fmaxf(csv[6], 1e-12f) * dSt);
}

// Symmetric combine: all 7 base matrices are bit-symmetric, so
//   S[i][j] = pre[i][j] + pre[j][i] = sum_m (cf_m[i]+cf_m[j]) * M_m[i,j].
// Emits quarter-row partial sums; since S is symmetric, colsum == rowsum.
__global__ void combine_sym_kernel(const float* __restrict__ G,  const float* __restrict__ P,
                                   const float* __restrict__ Q,  const float* __restrict__ FA,
                                   const float* __restrict__ FS, const float* __restrict__ SA,
                                   const float* __restrict__ SS, const float* __restrict__ coef,
                                   float* __restrict__ out, float* __restrict__ rowp)
{
    int b = blockIdx.x;
    size_t e = ((size_t)b * 256 + threadIdx.x) << 2;
    int j = (int)(e & (NT - 1));
    int i = (int)(e >> 12);
    float cfi[7];
    #pragma unroll
    for (int m = 0; m < 7; m++) cfi[m] = coef[m * NT + i];

    float4 r = make_float4(0.f, 0.f, 0.f, 0.f);
#define ACC(buf, m) { float4 v = *(const float4*)((buf) + e);                     \
                      float4 k = *(const float4*)(coef + (m) * NT + j);           \
                      r.x = fmaf(k.x + cfi[m], v.x, r.x);                         \
                      r.y = fmaf(k.y + cfi[m], v.y, r.y);                         \
                      r.z = fmaf(k.z + cfi[m], v.z, r.z);                         \
                      r.w = fmaf(k.w + cfi[m], v.w, r.w); }
    ACC(G, 0) ACC(P, 1) ACC(Q, 2) ACC(FA, 3) ACC(FS, 4) ACC(SA, 5) ACC(SS, 6)
#undef ACC
    *(float4*)(out + e) = r;

    float s = r.x + r.y + r.z + r.w;
    #pragma unroll
    for (int o = 16; o; o >>= 1) s += __shfl_xor_sync(0xffffffffu, s, o);
    __shared__ float ws[8];
    int w = threadIdx.x >> 5;
    if ((threadIdx.x & 31) == 0) ws[w] = s;
    __syncthreads();
    if (threadIdx.x == 0) {
        float t = 0.f;
        #pragma unroll
        for (int p = 0; p < 8; p++) t += ws[p];
        rowp[(size_t)(b >> 2) * 4 + (b & 3)] = t;
    }
}

__global__ void ct_final_kernel(const float* __restrict__ rowp, float* __restrict__ ct)
{
    int j = blockIdx.x * 256 + threadIdx.x;
    ct[j] = rowp[j * 4 + 0] + rowp[j * 4 + 1] + rowp[j * 4 + 2] + rowp[j * 4 + 3];
}

__global__ void scale_cols_kernel(float* __restrict__ A, const float* __restrict__ ct)
{
    size_t e = ((size_t)blockIdx.x * 256 + threadIdx.x) << 2;
    int j = (int)(e & (NT - 1));
    float4 v = *(float4*)(A + e);
    float4 c = *(const float4*)(ct + j);
    v.x /= fmaxf(c.x, 1e-12f); v.y /= fmaxf(c.y, 1e-12f);
    v.z /= fmaxf(c.z, 1e-12f); v.w /= fmaxf(c.w, 1e-12f);
    *(float4*)(A + e) = v;
}

__global__ void x1w2_kernel(const float* __restrict__ X1, const float* __restrict__ W2,
                            float* __restrict__ H2)
{
    int i = blockIdx.x * 256 + threadIdx.x;
    if (i >= NT) return;
    float s0 = 0.f, s1 = 0.f, s2 = 0.f;
    #pragma unroll 8
    for (int k = 0; k < COM; k++) {
        float x = X1[(size_t)i * COM + k];
        s0 = fmaf(x, W2[k * 3 + 0], s0);
        s1 = fmaf(x, W2[k * 3 + 1], s1);
        s2 = fmaf(x, W2[k * 3 + 2], s2);
    }
    H2[i * 3 + 0] = s0; H2[i * 3 + 1] = s1; H2[i * 3 + 2] = s2;
}

__global__ void logits_kernel(const float* __restrict__ A, const float* __restrict__ H2,
                              const float* __restrict__ b2, float* __restrict__ out)
{
    int i = blockIdx.x, tid = threadIdx.x;
    const float* row = A + (size_t)i * NT;
    float s0 = 0.f, s1 = 0.f, s2 = 0.f;
    for (int k = tid; k < NT; k += 256) {
        float a = row[k];
        s0 = fmaf(a, H2[k * 3 + 0], s0);
        s1 = fmaf(a, H2[k * 3 + 1], s1);
        s2 = fmaf(a, H2[k * 3 + 2], s2);
    }
    #pragma unroll
    for (int o = 16; o; o >>= 1) {
        s0 += __shfl_xor_sync(0xffffffffu, s0, o);
        s1 += __shfl_xor_sync(0xffffffffu, s1, o);
        s2 += __shfl_xor_sync(0xffffffffu, s2, o);
    }
    __shared__ float sh[3][8];
    int w = tid >> 5, l = tid & 31;
    if (l == 0) { sh[0][w] = s0; sh[1][w] = s1; sh[2][w] = s2; }
    __syncthreads();
    if (tid == 0) {
        float x0 = 0.f, x1 = 0.f, x2 = 0.f;
        #pragma unroll
        for (int t = 0; t < 8; t++) { x0 += sh[0][t]; x1 += sh[1][t]; x2 += sh[2][t]; }
        x0 += b2[0]; x1 += b2[1]; x2 += b2[2];
        float m  = fmaxf(x0, fmaxf(x1, x2));
        float ls = logf(expf(x0 - m) + expf(x1 - m) + expf(x2 - m));
        out[i * 3 + 0] = x0 - m - ls;
        out[i * 3 + 1] = x1 - m - ls;
        out[i * 3 + 2] = x2 - m - ls;
    }
}

// ---------------- host orchestration (single stream) -------------------------

extern "C" void kernel_launch(void* const* d_in, const int* in_sizes, int n_in,
                              void* d_out, int out_size)
{
    const float* features  = (const float*)d_in[0];
    const float* adj_ori   = (const float*)d_in[1];
    const float* mp_pap    = (const float*)d_in[2];
    const float* mp_psp    = (const float*)d_in[3];
    const float* fgo_w     = (const float*)d_in[6];
    const float* fpo_w     = (const float*)d_in[7];
    const float* sgg_pap_w = (const float*)d_in[8];
    const float* sgg_psp_w = (const float*)d_in[9];
    const float* sg_agg_w  = (const float*)d_in[10];
    const float* f_agg_f_w = (const float*)d_in[11];
    const float* f_agg_w   = (const float*)d_in[12];
    const float* topo_W_a  = (const float*)d_in[13];
    const float* topo_b_a  = (const float*)d_in[14];
    const float* topo_W_s  = (const float*)d_in[15];
    const float* topo_b_s  = (const float*)d_in[16];
    const float* fgt_w_a   = (const float*)d_in[17];
    const float* fgt_w_s   = (const float*)d_in[18];
    const float* gcn_W1    = (const float*)d_in[19];
    const float* gcn_b1    = (const float*)d_in[20];
    const float* gcn_W2    = (const float*)d_in[21];
    const float* gcn_b2    = (const float*)d_in[22];
    (void)in_sizes; (void)n_in; (void)out_size;

    float* out   = (float*)d_out;
    float* NAdj  = out + (size_t)NT * NCLS;

    float* big = nullptr; float* sm = nullptr; int* ib = nullptr;
    cudaGetSymbolAddress((void**)&big, g_big);
    cudaGetSymbolAddress((void**)&sm,  g_small);
    cudaGetSymbolAddress((void**)&ib,  g_ibuf);

    float* G   = big + 0ll * NT * NT;
    float* P   = big + 1ll * NT * NT;
    float* Q   = big + 2ll * NT * NT;
    float* FAb = big + 3ll * NT * NT;
    float* FSb = big + 4ll * NT * NT;
    float* SAb = big + 5ll * NT * NT;   // sim_r_A, then s_h_A
    float* SSb = big + 6ll * NT * NT;

    float* XN0   = sm + OFF_XN0;
    float* XN1   = sm + OFF_XN1;
    float* XN2   = sm + OFF_XN2;
    float* XN3   = sm + OFF_XN3;
    float* XN4   = sm + OFF_XN4;
    float* SIMS  = sm + OFF_SIMS;
    float* FPA   = sm + OFF_FPA;
    float* FPS   = sm + OFF_FPS;
    float* THA   = sm + OFF_THA;
    float* THS   = sm + OFF_THS;
    float* SWA   = sm + OFF_SWA;
    float* SWS   = sm + OFF_SWS;
    float* H0    = sm + OFF_H0;
    float* X1    = sm + OFF_X1;
    float* H2    = sm + OFF_H2;
    float* CS    = sm + OFF_CS;
    float* COEF  = sm + OFF_COEF;
    float* CT    = sm + OFF_CT;
    float* ROWP  = sm + OFF_ROWP;
    float* CSP   = sm + OFF_CSP;
    float* SPART = sm + OFF_SPART;

    int* IDXA = ib + OFF_IDXA; int* CNTA = ib + OFF_CNTA;
    int* IDXS = ib + OFF_IDXS; int* CNTS = ib + OFF_CNTS;

    const int TRI32 = 32 * 33 / 2;   // 528

    // ---- adjacency index lists (independent of everything else) ----
    build_idx_kernel<<<NT, 128>>>(adj_ori, NT, NAr, IDXA, CNTA);
    build_idx_kernel<<<NT, 128>>>(adj_ori, NT + NAr, NSr, IDXS, CNTS);

    // ---- prep batch A: 5 jobs ----
    {
        PrepJobs pj;
        pj.j[0] = {features,                              fgo_w,     XN0, NT,  FEAT};
        pj.j[1] = {features + (size_t)NT * FEAT,          fgo_w,     XN1, NAr, FEAT};
        pj.j[2] = {mp_pap,                                sgg_pap_w, XN2, NT,  MPD};
        pj.j[3] = {mp_psp,                                sgg_psp_w, XN3, NT,  MPD};
        pj.j[4] = {features + (size_t)(NT + NAr) * FEAT,  fgo_w,     XN4, NSr, FEAT};
        prep_norm_multi_kernel<<<dim3(NT / 4, 5), 128>>>(pj);
    }

    // ---- sim batch 1: G, sim_r_A, P, Q, sim_r_S ----
    {
        SimJobs sj;
        sj.j[0] = {XN0, G,    CSP + 0ll * 32 * NT, NT,  256, 32, 0.1f};
        sj.j[1] = {XN1, SAb,  nullptr,             NT,  256, 32, 0.1f};
        sj.j[2] = {XN2, P,    CSP + 1ll * 32 * NT, NT,  128, 32, 0.1f};
        sj.j[3] = {XN3, Q,    CSP + 2ll * 32 * NT, NT,  128, 32, 0.1f};
        sj.j[4] = {XN4, SIMS, nullptr,             NSr, 256, 8,  0.1f};
        simgemm_multi_kernel<<<dim3(TRI32, 5), 256>>>(sj);
    }

    // ---- A-relation topo pieces ----
    gemm_n64_splitk_kernel<<<dim3(NT / 64, 8), 256>>>(SAb, topo_W_a, SPART, NT, NAr, NAr / 8);
    splitk_reduce_kernel<<<(NT * 64) / 256, 256>>>(SPART, nullptr, SWA, NT, 8, 0);
    gather64b_kernel<<<NT, 64>>>(SWA, IDXA, CNTA, topo_b_a, THA);
    gather_sum_kernel<<<dim3(1, NT), 32>>>(features + (size_t)NT * FEAT, FEAT, IDXA, CNTA, FPA, FEAT);

    // ---- S-relation topo pieces ----
    gemm_n64_splitk_kernel<<<dim3(NSr / 64, 8), 256>>>(SIMS, topo_W_s, SPART, NSr, NSr, NSr / 8);
    splitk_reduce_kernel<<<(NSr * 64) / 256, 256>>>(SPART, nullptr, SWS, NSr, 8, 0);
    gather64b_kernel<<<NT, 64>>>(SWS, IDXS, CNTS, topo_b_s, THS);
    gather_sum_kernel<<<dim3(1, NT), 32>>>(features + (size_t)(NT + NAr) * FEAT, FEAT, IDXS, CNTS, FPS, FEAT);

    // ---- prep batch B: 4 jobs ----
    {
        PrepJobs pj;
        pj.j[0] = {FPA, fpo_w,   XN0, NT, FEAT};
        pj.j[1] = {FPS, fpo_w,   XN1, NT, FEAT};
        pj.j[2] = {THA, fgt_w_a, XN2, NT, COM};
        pj.j[3] = {THS, fgt_w_s, XN3, NT, COM};
        pj.j[4] = {FPA, fpo_w,   XN0, 0,  FEAT};   // unused slot (N=0 -> all blocks exit)
        prep_norm_multi_kernel<<<dim3(NT / 4, 4), 128>>>(pj);
    }

    // ---- sim batch 2: f_h_A, f_h_S, s_h_A, s_h_S ----
    {
        SimJobs sj;
        sj.j[0] = {XN0, FAb, CSP + 3ll * 32 * NT, NT, 256, 32, 0.2f};
        sj.j[1] = {XN1, FSb, CSP + 4ll * 32 * NT, NT, 256, 32, 0.2f};
        sj.j[2] = {XN2, SAb, CSP + 5ll * 32 * NT, NT, 128, 32, 0.1f};
        sj.j[3] = {XN3, SSb, CSP + 6ll * 32 * NT, NT, 128, 32, 0.1f};
        sj.j[4] = {XN0, FAb, nullptr, 0, 16, 0, 0.1f};   // unused slot
        simgemm_multi_kernel<<<dim3(TRI32, 4), 256>>>(sj);
    }

    // ---- GCN first half (independent) ----
    gemm_n64_kernel<<<NT / 64, 256>>>(features, gcn_W1, nullptr, H0, NT, FEAT, 0);

    // ---- fused channel attention (symmetric combine) ----
    cs_reduce_kernel<<<dim3(NT / 256, 7), 256>>>(CSP, CS);
    coefs_kernel<<<NT / 256, 256>>>(sg_agg_w, f_agg_f_w, f_agg_w, CS, COEF);
    combine_sym_kernel<<<(NT * NT) / 1024, 256>>>(G, P, Q, FAb, FSb, SAb, SSb, COEF, NAdj, ROWP);
    ct_final_kernel<<<NT / 256, 256>>>(ROWP, CT);
    scale_cols_kernel<<<(NT * NT) / 1024, 256>>>(NAdj, CT);

    // ---- GCN second half ----
    gemm_n64_splitk_kernel<<<dim3(NT / 64, 8), 256>>>(NAdj, H0, SPART, NT, NT, NT / 8);
    splitk_reduce_kernel<<<(NT * 64) / 256, 256>>>(SPART, gcn_b1, X1, NT, 8, 1);
    x1w2_kernel<<<NT / 256, 256>>>(X1, gcn_W2, H2);
    logits_kernel<<<NT, 256>>>(NAdj, H2, gcn_b2, out);
}

// round 11
// speedup vs baseline: 1.2950x; 1.0318x over previous
#include <cuda_runtime.h>
#include <math.h>

#define NT   4096
#define NAr  4096
#define NSr  1024
#define NALL 9216
#define FEAT 128
#define COM  64
#define MPD  64
#define NCLS 3
#define CAP  128   // max nnz per adjacency row (expected ~20, p=0.005)

// ---------------- static device scratch (no allocations allowed) -------------
__device__ float g_big[7ll * NT * NT];

#define OFF_XN0   0
#define OFF_XN1   (OFF_XN0  + NT*256)
#define OFF_XN2   (OFF_XN1  + NT*256)
#define OFF_XN3   (OFF_XN2  + NT*256)
#define OFF_XN4   (OFF_XN3  + NT*256)
#define OFF_XN5   (OFF_XN4  + NT*256)
#define OFF_XN6   (OFF_XN5  + NT*256)
#define OFF_SIMS  (OFF_XN6  + NT*256)       // 1024*1024
#define OFF_FPA   (OFF_SIMS + NSr*NSr)      // 4096*128
#define OFF_FPS   (OFF_FPA  + NT*FEAT)      // 4096*128
#define OFF_THA   (OFF_FPS  + NT*FEAT)      // 4096*64
#define OFF_THS   (OFF_THA  + NT*COM)       // 4096*64
#define OFF_SWA   (OFF_THS  + NT*COM)       // 4096*64
#define OFF_SWS   (OFF_SWA  + NT*COM)       // 1024*64
#define OFF_H0    (OFF_SWS  + NSr*COM)      // 4096*64
#define OFF_X1    (OFF_H0   + NT*COM)       // 4096*64
#define OFF_H2    (OFF_X1   + NT*COM)       // 4096*3
#define OFF_CS    (OFF_H2   + NT*NCLS)      // 7*4096
#define OFF_COEF  (OFF_CS   + 7*NT)         // 7*4096
#define OFF_CT    (OFF_COEF + 7*NT)         // 4096
#define OFF_ROWP  (OFF_CT   + NT)           // 4096*4
#define OFF_CSP   (OFF_ROWP + 4*NT)         // 7*32*4096
#define OFF_SPART (OFF_CSP  + 7*32*NT)      // 8*4096*64
#define SMALL_TOT (OFF_SPART + 8*NT*64)
__device__ float g_small[SMALL_TOT];

#define OFF_IDXA 0
#define OFF_CNTA (OFF_IDXA + NT*CAP)
#define OFF_IDXS (OFF_CNTA + NT)
#define OFF_CNTS (OFF_IDXS + NT*CAP)
#define IBUF_TOT (OFF_CNTS + NT)
__device__ int g_ibuf[IBUF_TOT];

// ---------------- packed f32x2 helpers (bit-identical IEEE fp32 per lane) ----
typedef unsigned long long u64t;

__device__ __forceinline__ u64t bcast2(float a)
{
    u64t r;
    asm("mov.b64 %0, {%1, %1};" : "=l"(r) : "r"(__float_as_uint(a)));
    return r;
}
__device__ __forceinline__ void fma2(u64t& acc, u64t a, u64t b)
{
    asm("fma.rn.f32x2 %0, %1, %2, %0;" : "+l"(acc) : "l"(a), "l"(b));
}
__device__ __forceinline__ float2 unpack2(u64t v)
{
    unsigned int lo, hi;
    asm("mov.b64 {%0, %1}, %2;" : "=r"(lo), "=r"(hi) : "l"(v));
    return make_float2(__uint_as_float(lo), __uint_as_float(hi));
}

// ---------------- job structs (passed by value as kernel args) ---------------
struct PrepJob { const float* src; const float* w; float* dst; int N; int D; };
struct PrepJobs { PrepJob j[7]; };
struct SimJob  { const float* X; float* C; float* cs; int N; int K; int nBlk; float th; };
struct SimJobs { SimJob j[7]; };

// ---------------- kernels ----------------------------------------------------

// Multi-job per-head weighted + L2-row-normalized features: dst[N, H*D], H=2.
__global__ void prep_norm_multi_kernel(PrepJobs jobs)
{
    PrepJob jb = jobs.j[blockIdx.y];
    int row  = blockIdx.x * (blockDim.x >> 5) + (threadIdx.x >> 5);
    int lane = threadIdx.x & 31;
    if (row >= jb.N) return;
    const float* src = jb.src;
    const float* w   = jb.w;
    float* dst = jb.dst;
    int D = jb.D;
    int HD = 2 * D;
    for (int h = 0; h < 2; h++) {
        float ss = 0.f;
        for (int d = lane; d < D; d += 32) {
            float v = src[(size_t)row * D + d] * w[h * D + d];
            ss += v * v;
        }
        #pragma unroll
        for (int o = 16; o; o >>= 1) ss += __shfl_xor_sync(0xffffffffu, ss, o);
        float inv = 1.f / fmaxf(sqrtf(ss), 1e-12f);
        for (int d = lane; d < D; d += 32)
            dst[(size_t)row * HD + h * D + d] = src[(size_t)row * D + d] * w[h * D + d] * inv;
    }
}

__device__ __forceinline__ float thrf(float v, float scale, float th)
{
    v *= scale;
    return (v < th) ? 0.f : v;
}

// Multi-job C = threshold(0.5 * X @ X^T), row-major X[N,K]. blockIdx.y selects job.
__global__ void __launch_bounds__(256, 2)
simgemm_multi_kernel(SimJobs jobs)
{
    SimJob jb = jobs.j[blockIdx.y];
    const int nBlk = jb.nBlk;
    int idx = blockIdx.x;
    if (idx >= nBlk * (nBlk + 1) / 2) return;
    const float* X = jb.X;
    float* C       = jb.C;
    float* csPart  = jb.cs;
    const int N = jb.N, K = jb.K;
    const float th = jb.th;

    float nb2 = nBlk + 0.5f;
    int by = (int)(nb2 - sqrtf(fmaxf(nb2 * nb2 - 2.0f * idx, 0.f)));
    if (by < 0) by = 0;
    if (by > nBlk - 1) by = nBlk - 1;
    while (by > 0 && (by * nBlk - (by * (by - 1)) / 2) > idx) by--;
    while (((by + 1) * nBlk - ((by + 1) * by) / 2) <= idx) by++;
    int bx = by + (idx - (by * nBlk - (by * (by - 1)) / 2));

    const int m0 = by * 128, n0 = bx * 128;

    __shared__ float As[2][16][128];
    __shared__ float Bs[2][16][128];

    const int tid = threadIdx.x;
    const int ldr = tid >> 2;
    const int ldc = (tid & 3) << 2;
    const int wrp = tid >> 5;
    const int ln  = tid & 31;
    const int ty  = ((wrp >> 1) << 2) | (ln >> 3);   // 0..15
    const int tx  = ((wrp & 1) << 3) | (ln & 7);     // 0..15
    const int ry  = ty << 3;
    const int rx  = tx << 3;

    u64t acc2[8][4];
    #pragma unroll
    for (int i = 0; i < 8; i++)
        #pragma unroll
        for (int j = 0; j < 4; j++) acc2[i][j] = 0ull;

    float4 a0, a1, b0, b1;

#define LOADG(k0) {                                                             \
    a0 = *(const float4*)(X + (size_t)(m0 + ldr)      * K + (k0) + ldc);        \
    a1 = *(const float4*)(X + (size_t)(m0 + ldr + 64) * K + (k0) + ldc);        \
    b0 = *(const float4*)(X + (size_t)(n0 + ldr)      * K + (k0) + ldc);        \
    b1 = *(const float4*)(X + (size_t)(n0 + ldr + 64) * K + (k0) + ldc); }

#define STORES(bf) {                                                            \
    As[bf][ldc+0][ldr]    = a0.x; As[bf][ldc+1][ldr]    = a0.y;                 \
    As[bf][ldc+2][ldr]    = a0.z; As[bf][ldc+3][ldr]    = a0.w;                 \
    As[bf][ldc+0][ldr+64] = a1.x; As[bf][ldc+1][ldr+64] = a1.y;                 \
    As[bf][ldc+2][ldr+64] = a1.z; As[bf][ldc+3][ldr+64] = a1.w;                 \
    Bs[bf][ldc+0][ldr]    = b0.x; Bs[bf][ldc+1][ldr]    = b0.y;                 \
    Bs[bf][ldc+2][ldr]    = b0.z; Bs[bf][ldc+3][ldr]    = b0.w;                 \
    Bs[bf][ldc+0][ldr+64] = b1.x; Bs[bf][ldc+1][ldr+64] = b1.y;                 \
    Bs[bf][ldc+2][ldr+64] = b1.z; Bs[bf][ldc+3][ldr+64] = b1.w; }

#define COMPUTE(bf) {                                                           \
    _Pragma("unroll")                                                           \
    for (int k = 0; k < 16; k++) {                                              \
        float4 av0 = *(const float4*)&As[bf][k][ry];                            \
        float4 av1 = *(const float4*)&As[bf][k][ry + 4];                        \
        float4 bv0 = *(const float4*)&Bs[bf][k][rx];                            \
        float4 bv1 = *(const float4*)&Bs[bf][k][rx + 4];                        \
        u64t bp[4];                                                             \
        bp[0] = ((const u64t*)&bv0)[0]; bp[1] = ((const u64t*)&bv0)[1];         \
        bp[2] = ((const u64t*)&bv1)[0]; bp[3] = ((const u64t*)&bv1)[1];         \
        float a[8] = {av0.x,av0.y,av0.z,av0.w,av1.x,av1.y,av1.z,av1.w};         \
        _Pragma("unroll")                                                       \
        for (int i = 0; i < 8; i++) {                                           \
            u64t ai = bcast2(a[i]);                                             \
            fma2(acc2[i][0], ai, bp[0]);                                        \
            fma2(acc2[i][1], ai, bp[1]);                                        \
            fma2(acc2[i][2], ai, bp[2]);                                        \
            fma2(acc2[i][3], ai, bp[3]);                                        \
        }                                                                       \
    } }

    LOADG(0);
    STORES(0);
    __syncthreads();
    int buf = 0;
    for (int k0 = 16; k0 < K; k0 += 16) {
        LOADG(k0);
        COMPUTE(buf);
        STORES(buf ^ 1);
        __syncthreads();
        buf ^= 1;
    }
    COMPUTE(buf);

#undef LOADG
#undef STORES
#undef COMPUTE

    float acc[8][8];
    #pragma unroll
    for (int i = 0; i < 8; i++)
        #pragma unroll
        for (int jp = 0; jp < 4; jp++) {
            float2 v = unpack2(acc2[i][jp]);
            acc[i][2 * jp + 0] = thrf(v.x, 0.5f, th);
            acc[i][2 * jp + 1] = thrf(v.y, 0.5f, th);
        }

    #pragma unroll
    for (int i = 0; i < 8; i++) {
        #pragma unroll
        for (int j = 0; j < 8; j += 4) {
            float4 v = make_float4(acc[i][j], acc[i][j+1], acc[i][j+2], acc[i][j+3]);
            *(float4*)(C + (size_t)(m0 + ry + i) * N + (n0 + rx + j)) = v;
        }
    }
    if (bx > by) {
        #pragma unroll
        for (int j = 0; j < 8; j++) {
            #pragma unroll
            for (int i = 0; i < 8; i += 4) {
                float4 v = make_float4(acc[i][j], acc[i+1][j], acc[i+2][j], acc[i+3][j]);
                *(float4*)(C + (size_t)(n0 + rx + j) * N + (m0 + ry + i)) = v;
            }
        }
    }

    if (csPart) {
        __syncthreads();
        float* red = (float*)As;
        #pragma unroll
        for (int jj = 0; jj < 8; jj++) {
            float s = 0.f;
            #pragma unroll
            for (int i = 0; i < 8; i++) s += acc[i][jj];
            red[ty * 128 + rx + jj] = s;
        }
        __syncthreads();
        if (tid < 128) {
            float s = 0.f;
            #pragma unroll
            for (int p = 0; p < 16; p++) s += red[p * 128 + tid];
            csPart[(size_t)by * N + n0 + tid] = s;
        }
        if (bx > by) {
            __syncthreads();
            #pragma unroll
            for (int ii = 0; ii < 8; ii++) {
                float s = 0.f;
                #pragma unroll
                for (int j = 0; j < 8; j++) s += acc[ii][j];
                red[tx * 128 + ry + ii] = s;
            }
            __syncthreads();
            if (tid < 128) {
                float s = 0.f;
                #pragma unroll
                for (int p = 0; p < 16; p++) s += red[p * 128 + tid];
                csPart[(size_t)bx * N + m0 + tid] = s;
            }
        }
    }
}

// Deterministic ballot-compacted nonzero index list; 4 warps scan disjoint
// segments, merged in segment order.
__global__ void build_idx_kernel(const float* __restrict__ adj, int col_off, int NR,
                                 int* __restrict__ idx, int* __restrict__ cnt)
{
    __shared__ int sidx[4][CAP];
    __shared__ int scnt[4];
    int i = blockIdx.x;
    const float* r = adj + (size_t)i * NALL + col_off;
    int w = threadIdx.x >> 5, lane = threadIdx.x & 31;
    int seg = NR >> 2;
    int b0  = w * seg;
    int count = 0;
    for (int base = b0; base < b0 + seg; base += 32) {
        float v = r[base + lane];
        unsigned m = __ballot_sync(0xffffffffu, v != 0.f);
        int pre = __popc(m & ((1u << lane) - 1u));
        if (v != 0.f && (count + pre) < CAP) sidx[w][count + pre] = base + lane;
        count += __popc(m);
    }
    if (lane == 0) scnt[w] = min(count, CAP);
    __syncthreads();
    int myoff = 0, tot = 0;
    #pragma unroll
    for (int p = 0; p < 4; p++) {
        if (p < w) myoff += scnt[p];
        tot += scnt[p];
    }
    for (int t = lane; t < scnt[w]; t += 32) {
        int pos = myoff + t;
        if (pos < CAP) idx[(size_t)i * CAP + pos] = sidx[w][t];
    }
    if (threadIdx.x == 0) cnt[i] = min(tot, CAP);
}

__global__ void gather_sum_kernel(const float* __restrict__ src, int lds,
                                  const int* __restrict__ idx, const int* __restrict__ cnt,
                                  float* __restrict__ out, int ldo)
{
    int i = blockIdx.y;
    int j = ((blockIdx.x * blockDim.x + threadIdx.x) << 2);
    int c = cnt[i];
    const int* ip = idx + (size_t)i * CAP;
    float4 s = make_float4(0.f, 0.f, 0.f, 0.f);
    for (int t = 0; t < c; t++) {
        float4 v = *(const float4*)(src + (size_t)ip[t] * lds + j);
        s.x += v.x; s.y += v.y; s.z += v.z; s.w += v.w;
    }
    *(float4*)(out + (size_t)i * ldo + j) = s;
}

__global__ void gather64b_kernel(const float* __restrict__ src,
                                 const int* __restrict__ idx, const int* __restrict__ cnt,
                                 const float* __restrict__ bias, float* __restrict__ out)
{
    int i = blockIdx.x;
    int c = threadIdx.x;
    int n = cnt[i];
    const int* ip = idx + (size_t)i * CAP;
    float s = 0.f;
    for (int t = 0; t < n; t++) s += src[(size_t)ip[t] * 64 + c];
    out[(size_t)i * 64 + c] = s + bias[c];
}

// C[M,64] = A[M,K] @ B[K,64] (+bias) (optional relu) — 64x64 tile, for small K
__global__ void __launch_bounds__(256)
gemm_n64_kernel(const float* __restrict__ A, const float* __restrict__ B,
                const float* __restrict__ bias, float* __restrict__ C,
                int M, int K, int relu)
{
    __shared__ float As[32][64];
    __shared__ float Bs[32][64];
    int tid = threadIdx.x;
    int m0  = blockIdx.x * 64;
    int ar  = tid >> 3;
    int ac  = (tid & 7) << 2;
    int br  = tid >> 4;
    int bc  = (tid & 15) << 2;
    int wrp = tid >> 5, ln = tid & 31;
    int ty  = ((wrp >> 1) << 2) | (ln >> 3);
    int tx  = ((wrp & 1) << 3) | (ln & 7);

    u64t acc2[4][2];
    #pragma unroll
    for (int i = 0; i < 4; i++) { acc2[i][0] = 0ull; acc2[i][1] = 0ull; }

    for (int k0 = 0; k0 < K; k0 += 32) {
        float4 a0 = *(const float4*)(A + (size_t)(m0 + ar)      * K + k0 + ac);
        float4 a1 = *(const float4*)(A + (size_t)(m0 + ar + 32) * K + k0 + ac);
        float4 b0 = *(const float4*)(B + (size_t)(k0 + br)      * 64 + bc);
        float4 b1 = *(const float4*)(B + (size_t)(k0 + br + 16) * 64 + bc);
        __syncthreads();
        As[ac+0][ar]    = a0.x; As[ac+1][ar]    = a0.y; As[ac+2][ar]    = a0.z; As[ac+3][ar]    = a0.w;
        As[ac+0][ar+32] = a1.x; As[ac+1][ar+32] = a1.y; As[ac+2][ar+32] = a1.z; As[ac+3][ar+32] = a1.w;
        *(float4*)&Bs[br][bc]      = b0;
        *(float4*)&Bs[br + 16][bc] = b1;
        __syncthreads();
        #pragma unroll
        for (int k = 0; k < 32; k++) {
            float4 av = *(const float4*)&As[k][ty << 2];
            float4 bv = *(const float4*)&Bs[k][tx << 2];
            u64t bp0 = ((const u64t*)&bv)[0], bp1 = ((const u64t*)&bv)[1];
            float a[4] = {av.x, av.y, av.z, av.w};
            #pragma unroll
            for (int i = 0; i < 4; i++) {
                u64t ai = bcast2(a[i]);
                fma2(acc2[i][0], ai, bp0);
                fma2(acc2[i][1], ai, bp1);
            }
        }
    }
    int r = m0 + (ty << 2), c = tx << 2;
    #pragma unroll
    for (int i = 0; i < 4; i++) {
        float2 v0 = unpack2(acc2[i][0]);
        float2 v1 = unpack2(acc2[i][1]);
        float vv[4] = {v0.x, v0.y, v1.x, v1.y};
        #pragma unroll
        for (int j = 0; j < 4; j++) {
            float v = vv[j] + (bias ? bias[c + j] : 0.f);
            if (relu) v = fmaxf(v, 0.f);
            C[(size_t)(r + i) * 64 + c + j] = v;
        }
    }
}

// split-K GEMM, 128x64 tile, 8x4 per thread. grid (M/128, S).
// Per-element sequential-k fma2 order identical to the old 64x64 kernel.
__global__ void __launch_bounds__(256)
gemm128_splitk_kernel(const float* __restrict__ A, const float* __restrict__ B,
                      float* __restrict__ part, int M, int K, int Kc)
{
    __shared__ float As[32][128];
    __shared__ float Bs[32][64];
    int tid = threadIdx.x;
    int m0  = blockIdx.x * 128;
    int s   = blockIdx.y;
    int kb  = s * Kc, ke = kb + Kc;
    int ar  = tid >> 1;            // 0..127
    int ac  = (tid & 1) << 4;      // 0 or 16
    int br  = tid >> 3;            // 0..31
    int bc  = (tid & 7) << 2;      // 0..28
    int wrp = tid >> 5, ln = tid & 31;
    int ty  = ((wrp >> 1) << 2) | (ln >> 3);   // 0..15
    int tx  = ((wrp & 1) << 3) | (ln & 7);     // 0..15
    int ry  = ty << 3;            // 0..120
    int rxc = tx << 2;            // 0..60

    u64t acc2[8][2];
    #pragma unroll
    for (int i = 0; i < 8; i++) { acc2[i][0] = 0ull; acc2[i][1] = 0ull; }

    for (int k0 = kb; k0 < ke; k0 += 32) {
        float4 a[4];
        #pragma unroll
        for (int c = 0; c < 4; c++)
            a[c] = *(const float4*)(A + (size_t)(m0 + ar) * K + k0 + ac + (c << 2));
        float4 b0 = *(const float4*)(B + (size_t)(k0 + br) * 64 + bc);
        float4 b1 = *(const float4*)(B + (size_t)(k0 + br) * 64 + bc + 32);
        __syncthreads();
        #pragma unroll
        for (int c = 0; c < 4; c++) {
            As[ac + (c << 2) + 0][ar] = a[c].x;
            As[ac + (c << 2) + 1][ar] = a[c].y;
            As[ac + (c << 2) + 2][ar] = a[c].z;
            As[ac + (c << 2) + 3][ar] = a[c].w;
        }
        *(float4*)&Bs[br][bc]      = b0;
        *(float4*)&Bs[br][bc + 32] = b1;
        __syncthreads();
        #pragma unroll
        for (int k = 0; k < 32; k++) {
            float4 av0 = *(const float4*)&As[k][ry];
            float4 av1 = *(const float4*)&As[k][ry + 4];
            float4 bv  = *(const float4*)&Bs[k][rxc];
            u64t bp0 = ((const u64t*)&bv)[0], bp1 = ((const u64t*)&bv)[1];
            float aa[8] = {av0.x, av0.y, av0.z, av0.w, av1.x, av1.y, av1.z, av1.w};
            #pragma unroll
            for (int i = 0; i < 8; i++) {
                u64t ai = bcast2(aa[i]);
                fma2(acc2[i][0], ai, bp0);
                fma2(acc2[i][1], ai, bp1);
            }
        }
    }
    int r = m0 + ry;
    #pragma unroll
    for (int i = 0; i < 8; i++) {
        float2 v0 = unpack2(acc2[i][0]);
        float2 v1 = unpack2(acc2[i][1]);
        float4 v = make_float4(v0.x, v0.y, v1.x, v1.y);
        *(float4*)(part + (size_t)s * M * 64 + (size_t)(r + i) * 64 + rxc) = v;
    }
}

__global__ void splitk_reduce_kernel(const float* __restrict__ part, const float* __restrict__ bias,
                                     float* __restrict__ C, int M, int S, int relu)
{
    int idx = blockIdx.x * 256 + threadIdx.x;
    if (idx >= M * 64) return;
    float s = 0.f;
    for (int p = 0; p < S; p++) s += part[(size_t)p * M * 64 + idx];
    if (bias) s += bias[idx & 63];
    if (relu) s = fmaxf(s, 0.f);
    C[idx] = s;
}

__global__ void cs_reduce_kernel(const float* __restrict__ CSP, float* __restrict__ CS)
{
    int m = blockIdx.y;
    int j = blockIdx.x * 256 + threadIdx.x;
    float s = 0.f;
    #pragma unroll
    for (int p = 0; p < 32; p++) s += CSP[((size_t)m * 32 + p) * NT + j];
    CS[m * NT + j] = s;
}

// per-column combine coefficients (handles all-zero columns of base matrices)
__global__ void coefs_kernel(const float* __restrict__ sgw, const float* __restrict__ ffw,
                             const float* __restrict__ f4w,
                             const float* __restrict__ cs, float* __restrict__ coef)
{
    int j = blockIdx.x * 256 + threadIdx.x;
    float m2 = fmaxf(sgw[0], sgw[1]);
    float e0 = expf(sgw[0] - m2), e1 = expf(sgw[1] - m2);
    float sa0 = e0 / (e0 + e1), sa1 = e1 / (e0 + e1);
    float mf = fmaxf(ffw[0], ffw[1]);
    float f0 = expf(ffw[0] - mf), f1 = expf(ffw[1] - mf);
    float fa0 = f0 / (f0 + f1), fa1 = f1 / (f0 + f1);
    float m4 = fmaxf(fmaxf(f4w[0], f4w[1]), fmaxf(f4w[2], f4w[3]));
    float w0 = expf(f4w[0] - m4), w1 = expf(f4w[1] - m4), w2 = expf(f4w[2] - m4), w3 = expf(f4w[3] - m4);
    float ws = w0 + w1 + w2 + w3;
    w0 /= ws; w1 /= ws; w2 /= ws; w3 /= ws;

    float csv[7];
    #pragma unroll
    for (int m = 0; m < 7; m++) csv[m] = cs[m * NT + j];
    float uP  = (csv[1] > 0.05f) ? 1.f : 0.f;
    float uQ  = (csv[2] > 0.05f) ? 1.f : 0.f;
    float uFA = (csv[3] > 0.05f) ? 1.f : 0.f;
    float uFS = (csv[4] > 0.05f) ? 1.f : 0.f;
    float uSA = (csv[5] > 0.05f) ? 1.f : 0.f;
    float uSS = (csv[6] > 0.05f) ? 1.f : 0.f;
    float dSem = fmaxf(sa0 * uP  + sa1 * uQ,  1e-12f);
    float dFp  = fmaxf(fa0 * uFA + fa1 * uFS, 1e-12f);
    float dSt  = fmaxf(fa0 * uSA + fa1 * uSS, 1e-12f);

    coef[0 * NT + j] = w0 / fmaxf(csv[0], 1e-12f);
    coef[1 * NT + j] = w1 * sa0 / (fmaxf(csv[1], 1e-12f) * dSem);
    coef[2 * NT + j] = w1 * sa1 / (fmaxf(csv[2], 1e-12f) * dSem);
    coef[3 * NT + j] = w2 * fa0 / (fmaxf(csv[3], 1e-12f) * dFp);
    coef[4 * NT + j] = w2 * fa1 / (fmaxf(csv[4], 1e-12f) * dFp);
    coef[5 * NT + j] = w3 * fa0 / (fmaxf(csv[5], 1e-12f) * dSt);
    coef[6 * NT + j] = w3 * fa1 / (fmaxf(csv[6], 1e-12f) * dSt);
}

// Symmetric combine: S[i][j] = sum_m (cf_m[i]+cf_m[j]) * M_m[i,j]; rowsums emitted.
__global__ void combine_sym_kernel(const float* __restrict__ G,  const float* __restrict__ P,
                                   const float* __restrict__ Q,  const float* __restrict__ FA,
                                   const float* __restrict__ FS, const float* __restrict__ SA,
                                   const float* __restrict__ SS, const float* __restrict__ coef,
                                   float* __restrict__ out, float* __restrict__ rowp)
{
    int b = blockIdx.x;
    size_t e = ((size_t)b * 256 + threadIdx.x) << 2;
    int j = (int)(e & (NT - 1));
    int i = (int)(e >> 12);
    float cfi[7];
    #pragma unroll
    for (int m = 0; m < 7; m++) cfi[m] = coef[m * NT + i];

    float4 r = make_float4(0.f, 0.f, 0.f, 0.f);
#define ACC(buf, m) { float4 v = *(const float4*)((buf) + e);                     \
                      float4 k = *(const float4*)(coef + (m) * NT + j);           \
                      r.x = fmaf(k.x + cfi[m], v.x, r.x);                         \
                      r.y = fmaf(k.y + cfi[m], v.y, r.y);                         \
                      r.z = fmaf(k.z + cfi[m], v.z, r.z);                         \
                      r.w = fmaf(k.w + cfi[m], v.w, r.w); }
    ACC(G, 0) ACC(P, 1) ACC(Q, 2) ACC(FA, 3) ACC(FS, 4) ACC(SA, 5) ACC(SS, 6)
#undef ACC
    *(float4*)(out + e) = r;

    float s = r.x + r.y + r.z + r.w;
    #pragma unroll
    for (int o = 16; o; o >>= 1) s += __shfl_xor_sync(0xffffffffu, s, o);
    __shared__ float ws[8];
    int w = threadIdx.x >> 5;
    if ((threadIdx.x & 31) == 0) ws[w] = s;
    __syncthreads();
    if (threadIdx.x == 0) {
        float t = 0.f;
        #pragma unroll
        for (int p = 0; p < 8; p++) t += ws[p];
        rowp[(size_t)(b >> 2) * 4 + (b & 3)] = t;
    }
}

__global__ void ct_final_kernel(const float* __restrict__ rowp, float* __restrict__ ct)
{
    int j = blockIdx.x * 256 + threadIdx.x;
    ct[j] = rowp[j * 4 + 0] + rowp[j * 4 + 1] + rowp[j * 4 + 2] + rowp[j * 4 + 3];
}

__global__ void scale_cols_kernel(float* __restrict__ A, const float* __restrict__ ct)
{
    size_t e = ((size_t)blockIdx.x * 256 + threadIdx.x) << 2;
    int j = (int)(e & (NT - 1));
    float4 v = *(float4*)(A + e);
    float4 c = *(const float4*)(ct + j);
    v.x /= fmaxf(c.x, 1e-12f); v.y /= fmaxf(c.y, 1e-12f);
    v.z /= fmaxf(c.z, 1e-12f); v.w /= fmaxf(c.w, 1e-12f);
    *(float4*)(A + e) = v;
}

__global__ void x1w2_kernel(const float* __restrict__ X1, const float* __restrict__ W2,
                            float* __restrict__ H2)
{
    int i = blockIdx.x * 256 + threadIdx.x;
    if (i >= NT) return;
    float s0 = 0.f, s1 = 0.f, s2 = 0.f;
    #pragma unroll 8
    for (int k = 0; k < COM; k++) {
        float x = X1[(size_t)i * COM + k];
        s0 = fmaf(x, W2[k * 3 + 0], s0);
        s1 = fmaf(x, W2[k * 3 + 1], s1);
        s2 = fmaf(x, W2[k * 3 + 2], s2);
    }
    H2[i * 3 + 0] = s0; H2[i * 3 + 1] = s1; H2[i * 3 + 2] = s2;
}

__global__ void logits_kernel(const float* __restrict__ A, const float* __restrict__ H2,
                              const float* __restrict__ b2, float* __restrict__ out)
{
    int i = blockIdx.x, tid = threadIdx.x;
    const float* row = A + (size_t)i * NT;
    float s0 = 0.f, s1 = 0.f, s2 = 0.f;
    for (int k = tid; k < NT; k += 256) {
        float a = row[k];
        s0 = fmaf(a, H2[k * 3 + 0], s0);
        s1 = fmaf(a, H2[k * 3 + 1], s1);
        s2 = fmaf(a, H2[k * 3 + 2], s2);
    }
    #pragma unroll
    for (int o = 16; o; o >>= 1) {
        s0 += __shfl_xor_sync(0xffffffffu, s0, o);
        s1 += __shfl_xor_sync(0xffffffffu, s1, o);
        s2 += __shfl_xor_sync(0xffffffffu, s2, o);
    }
    __shared__ float sh[3][8];
    int w = tid >> 5, l = tid & 31;
    if (l == 0) { sh[0][w] = s0; sh[1][w] = s1; sh[2][w] = s2; }
    __syncthreads();
    if (tid == 0) {
        float x0 = 0.f, x1 = 0.f, x2 = 0.f;
        #pragma unroll
        for (int t = 0; t < 8; t++) { x0 += sh[0][t]; x1 += sh[1][t]; x2 += sh[2][t]; }
        x0 += b2[0]; x1 += b2[1]; x2 += b2[2];
        float m  = fmaxf(x0, fmaxf(x1, x2));
        float ls = logf(expf(x0 - m) + expf(x1 - m) + expf(x2 - m));
        out[i * 3 + 0] = x0 - m - ls;
        out[i * 3 + 1] = x1 - m - ls;
        out[i * 3 + 2] = x2 - m - ls;
    }
}

// ---------------- host orchestration (single stream) -------------------------

extern "C" void kernel_launch(void* const* d_in, const int* in_sizes, int n_in,
                              void* d_out, int out_size)
{
    const float* features  = (const float*)d_in[0];
    const float* adj_ori   = (const float*)d_in[1];
    const float* mp_pap    = (const float*)d_in[2];
    const float* mp_psp    = (const float*)d_in[3];
    const float* fgo_w     = (const float*)d_in[6];
    const float* fpo_w     = (const float*)d_in[7];
    const float* sgg_pap_w = (const float*)d_in[8];
    const float* sgg_psp_w = (const float*)d_in[9];
    const float* sg_agg_w  = (const float*)d_in[10];
    const float* f_agg_f_w = (const float*)d_in[11];
    const float* f_agg_w   = (const float*)d_in[12];
    const float* topo_W_a  = (const float*)d_in[13];
    const float* topo_b_a  = (const float*)d_in[14];
    const float* topo_W_s  = (const float*)d_in[15];
    const float* topo_b_s  = (const float*)d_in[16];
    const float* fgt_w_a   = (const float*)d_in[17];
    const float* fgt_w_s   = (const float*)d_in[18];
    const float* gcn_W1    = (const float*)d_in[19];
    const float* gcn_b1    = (const float*)d_in[20];
    const float* gcn_W2    = (const float*)d_in[21];
    const float* gcn_b2    = (const float*)d_in[22];
    (void)in_sizes; (void)n_in; (void)out_size;

    float* out   = (float*)d_out;
    float* NAdj  = out + (size_t)NT * NCLS;

    float* big = nullptr; float* sm = nullptr; int* ib = nullptr;
    cudaGetSymbolAddress((void**)&big, g_big);
    cudaGetSymbolAddress((void**)&sm,  g_small);
    cudaGetSymbolAddress((void**)&ib,  g_ibuf);

    float* G   = big + 0ll * NT * NT;
    float* P   = big + 1ll * NT * NT;
    float* Q   = big + 2ll * NT * NT;
    float* FAb = big + 3ll * NT * NT;
    float* FSb = big + 4ll * NT * NT;
    float* SAb = big + 5ll * NT * NT;   // sim_r_A, then s_h_A
    float* SSb = big + 6ll * NT * NT;

    float* XN0   = sm + OFF_XN0;
    float* XN1   = sm + OFF_XN1;
    float* XN2   = sm + OFF_XN2;
    float* XN3   = sm + OFF_XN3;
    float* XN4   = sm + OFF_XN4;
    float* XN5   = sm + OFF_XN5;
    float* XN6   = sm + OFF_XN6;
    float* SIMS  = sm + OFF_SIMS;
    float* FPA   = sm + OFF_FPA;
    float* FPS   = sm + OFF_FPS;
    float* THA   = sm + OFF_THA;
    float* THS   = sm + OFF_THS;
    float* SWA   = sm + OFF_SWA;
    float* SWS   = sm + OFF_SWS;
    float* H0    = sm + OFF_H0;
    float* X1    = sm + OFF_X1;
    float* H2    = sm + OFF_H2;
    float* CS    = sm + OFF_CS;
    float* COEF  = sm + OFF_COEF;
    float* CT    = sm + OFF_CT;
    float* ROWP  = sm + OFF_ROWP;
    float* CSP   = sm + OFF_CSP;
    float* SPART = sm + OFF_SPART;

    int* IDXA = ib + OFF_IDXA; int* CNTA = ib + OFF_CNTA;
    int* IDXS = ib + OFF_IDXS; int* CNTS = ib + OFF_CNTS;

    const int TRI32 = 32 * 33 / 2;   // 528

    // ---- adjacency index lists + feature propagation (independent of sims) ----
    build_idx_kernel<<<NT, 128>>>(adj_ori, NT, NAr, IDXA, CNTA);
    build_idx_kernel<<<NT, 128>>>(adj_ori, NT + NAr, NSr, IDXS, CNTS);
    gather_sum_kernel<<<dim3(1, NT), 32>>>(features + (size_t)NT * FEAT, FEAT, IDXA, CNTA, FPA, FEAT);
    gather_sum_kernel<<<dim3(1, NT), 32>>>(features + (size_t)(NT + NAr) * FEAT, FEAT, IDXS, CNTS, FPS, FEAT);

    // ---- prep batch A: 7 jobs ----
    {
        PrepJobs pj;
        pj.j[0] = {features,                              fgo_w,     XN0, NT,  FEAT};
        pj.j[1] = {features + (size_t)NT * FEAT,          fgo_w,     XN1, NAr, FEAT};
        pj.j[2] = {mp_pap,                                sgg_pap_w, XN2, NT,  MPD};
        pj.j[3] = {mp_psp,                                sgg_psp_w, XN3, NT,  MPD};
        pj.j[4] = {features + (size_t)(NT + NAr) * FEAT,  fgo_w,     XN4, NSr, FEAT};
        pj.j[5] = {FPA,                                   fpo_w,     XN5, NT,  FEAT};
        pj.j[6] = {FPS,                                   fpo_w,     XN6, NT,  FEAT};
        prep_norm_multi_kernel<<<dim3(NT / 4, 7), 128>>>(pj);
    }

    // ---- sim batch 1: G, sim_r_A, P, Q, sim_r_S, f_h_A, f_h_S ----
    {
        SimJobs sj;
        sj.j[0] = {XN0, G,    CSP + 0ll * 32 * NT, NT,  256, 32, 0.1f};
        sj.j[1] = {XN1, SAb,  nullptr,             NT,  256, 32, 0.1f};
        sj.j[2] = {XN2, P,    CSP + 1ll * 32 * NT, NT,  128, 32, 0.1f};
        sj.j[3] = {XN3, Q,    CSP + 2ll * 32 * NT, NT,  128, 32, 0.1f};
        sj.j[4] = {XN4, SIMS, nullptr,             NSr, 256, 8,  0.1f};
        sj.j[5] = {XN5, FAb,  CSP + 3ll * 32 * NT, NT,  256, 32, 0.2f};
        sj.j[6] = {XN6, FSb,  CSP + 4ll * 32 * NT, NT,  256, 32, 0.2f};
        simgemm_multi_kernel<<<dim3(TRI32, 7), 256>>>(sj);
    }

    // ---- topo chains (A then S) ----
    gemm128_splitk_kernel<<<dim3(NT / 128, 8), 256>>>(SAb, topo_W_a, SPART, NT, NAr, NAr / 8);
    splitk_reduce_kernel<<<(NT * 64) / 256, 256>>>(SPART, nullptr, SWA, NT, 8, 0);
    gather64b_kernel<<<NT, 64>>>(SWA, IDXA, CNTA, topo_b_a, THA);
    gemm128_splitk_kernel<<<dim3(NSr / 128, 8), 256>>>(SIMS, topo_W_s, SPART, NSr, NSr, NSr / 8);
    splitk_reduce_kernel<<<(NSr * 64) / 256, 256>>>(SPART, nullptr, SWS, NSr, 8, 0);
    gather64b_kernel<<<NT, 64>>>(SWS, IDXS, CNTS, topo_b_s, THS);

    // ---- prep batch B: 2 jobs ----
    {
        PrepJobs pj;
        pj.j[0] = {THA, fgt_w_a, XN2, NT, COM};
        pj.j[1] = {THS, fgt_w_s, XN3, NT, COM};
        for (int t = 2; t < 7; t++) pj.j[t] = {THA, fgt_w_a, XN2, 0, COM};
        prep_norm_multi_kernel<<<dim3(NT / 4, 2), 128>>>(pj);
    }

    // ---- sim batch 2: s_h_A, s_h_S ----
    {
        SimJobs sj;
        sj.j[0] = {XN2, SAb, CSP + 5ll * 32 * NT, NT, 128, 32, 0.1f};
        sj.j[1] = {XN3, SSb, CSP + 6ll * 32 * NT, NT, 128, 32, 0.1f};
        for (int t = 2; t < 7; t++) sj.j[t] = {XN2, SAb, nullptr, 0, 16, 0, 0.1f};
        simgemm_multi_kernel<<<dim3(TRI32, 2), 256>>>(sj);
    }

    // ---- GCN first half (independent) ----
    gemm_n64_kernel<<<NT / 64, 256>>>(features, gcn_W1, nullptr, H0, NT, FEAT, 0);

    // ---- fused channel attention (symmetric combine) ----
    cs_reduce_kernel<<<dim3(NT / 256, 7), 256>>>(CSP, CS);
    coefs_kernel<<<NT / 256, 256>>>(sg_agg_w, f_agg_f_w, f_agg_w, CS, COEF);
    combine_sym_kernel<<<(NT * NT) / 1024, 256>>>(G, P, Q, FAb, FSb, SAb, SSb, COEF, NAdj, ROWP);
    ct_final_kernel<<<NT / 256, 256>>>(ROWP, CT);
    scale_cols_kernel<<<(NT * NT) / 1024, 256>>>(NAdj, CT);

    // ---- GCN second half ----
    gemm128_splitk_kernel<<<dim3(NT / 128, 8), 256>>>(NAdj, H0, SPART, NT, NT, NT / 8);
    splitk_reduce_kernel<<<(NT * 64) / 256, 256>>>(SPART, gcn_b1, X1, NT, 8, 1);
    x1w2_kernel<<<NT / 256, 256>>>(X1, gcn_W2, H2);
    logits_kernel<<<NT, 256>>>(NAdj, H2, gcn_b2, out);
}

// round 12
// speedup vs baseline: 1.3481x; 1.0410x over previous
#include <cuda_runtime.h>
#include <math.h>

#define NT   4096
#define NAr  4096
#define NSr  1024
#define NALL 9216
#define FEAT 128
#define COM  64
#define MPD  64
#define NCLS 3
#define CAP  128   // max nnz per adjacency row (expected ~20, p=0.005)

// ---------------- static device scratch (no allocations allowed) -------------
__device__ float g_big[7ll * NT * NT];

#define OFF_XN0   0
#define OFF_XN1   (OFF_XN0  + NT*256)
#define OFF_XN2   (OFF_XN1  + NT*256)
#define OFF_XN3   (OFF_XN2  + NT*256)
#define OFF_XN4   (OFF_XN3  + NT*256)
#define OFF_XN5   (OFF_XN4  + NT*256)
#define OFF_XN6   (OFF_XN5  + NT*256)
#define OFF_SIMS  (OFF_XN6  + NT*256)       // 1024*1024
#define OFF_FPA   (OFF_SIMS + NSr*NSr)      // 4096*128
#define OFF_FPS   (OFF_FPA  + NT*FEAT)      // 4096*128
#define OFF_THA   (OFF_FPS  + NT*FEAT)      // 4096*64
#define OFF_THS   (OFF_THA  + NT*COM)       // 4096*64
#define OFF_SWA   (OFF_THS  + NT*COM)       // 4096*64
#define OFF_SWS   (OFF_SWA  + NT*COM)       // 1024*64
#define OFF_H0    (OFF_SWS  + NSr*COM)      // 4096*64
#define OFF_X1    (OFF_H0   + NT*COM)       // 4096*64
#define OFF_H2    (OFF_X1   + NT*COM)       // 4096*3
#define OFF_CS    (OFF_H2   + NT*NCLS)      // 7*4096
#define OFF_COEF  (OFF_CS   + 7*NT)         // 7*4096
#define OFF_CT    (OFF_COEF + 7*NT)         // 4096
#define OFF_PART2 (OFF_CT   + NT)           // 64*4096 row partials
#define OFF_CSP   (OFF_PART2+ 64*NT)        // 7*32*4096
#define OFF_SPART (OFF_CSP  + 7*32*NT)      // 8*4096*64
#define SMALL_TOT (OFF_SPART + 8*NT*64)
__device__ float g_small[SMALL_TOT];

#define OFF_IDXA 0
#define OFF_CNTA (OFF_IDXA + NT*CAP)
#define OFF_IDXS (OFF_CNTA + NT)
#define OFF_CNTS (OFF_IDXS + NT*CAP)
#define IBUF_TOT (OFF_CNTS + NT)
__device__ int g_ibuf[IBUF_TOT];

// ---------------- packed f32x2 helpers (bit-identical IEEE fp32 per lane) ----
typedef unsigned long long u64t;

__device__ __forceinline__ u64t bcast2(float a)
{
    u64t r;
    asm("mov.b64 %0, {%1, %1};" : "=l"(r) : "r"(__float_as_uint(a)));
    return r;
}
__device__ __forceinline__ void fma2(u64t& acc, u64t a, u64t b)
{
    asm("fma.rn.f32x2 %0, %1, %2, %0;" : "+l"(acc) : "l"(a), "l"(b));
}
__device__ __forceinline__ float2 unpack2(u64t v)
{
    unsigned int lo, hi;
    asm("mov.b64 {%0, %1}, %2;" : "=r"(lo), "=r"(hi) : "l"(v));
    return make_float2(__uint_as_float(lo), __uint_as_float(hi));
}

// ---------------- job structs (passed by value as kernel args) ---------------
struct PrepJob { const float* src; const float* w; float* dst; int N; int D; };
struct PrepJobs { PrepJob j[7]; };
struct SimJob  { const float* X; float* C; float* cs; int N; int K; int nBlk; float th; int mirror; };
struct SimJobs { SimJob j[7]; };

// ---------------- kernels ----------------------------------------------------

__global__ void prep_norm_multi_kernel(PrepJobs jobs)
{
    PrepJob jb = jobs.j[blockIdx.y];
    int row  = blockIdx.x * (blockDim.x >> 5) + (threadIdx.x >> 5);
    int lane = threadIdx.x & 31;
    if (row >= jb.N) return;
    const float* src = jb.src;
    const float* w   = jb.w;
    float* dst = jb.dst;
    int D = jb.D;
    int HD = 2 * D;
    for (int h = 0; h < 2; h++) {
        float ss = 0.f;
        for (int d = lane; d < D; d += 32) {
            float v = src[(size_t)row * D + d] * w[h * D + d];
            ss += v * v;
        }
        #pragma unroll
        for (int o = 16; o; o >>= 1) ss += __shfl_xor_sync(0xffffffffu, ss, o);
        float inv = 1.f / fmaxf(sqrtf(ss), 1e-12f);
        for (int d = lane; d < D; d += 32)
            dst[(size_t)row * HD + h * D + d] = src[(size_t)row * D + d] * w[h * D + d] * inv;
    }
}

__device__ __forceinline__ float thrf(float v, float scale, float th)
{
    v *= scale;
    return (v < th) ? 0.f : v;
}

// Multi-job C = threshold(0.5 * X @ X^T). Mirror tile store optional per job
// (skipped for matrices consumed only by the triangular combine).
__global__ void __launch_bounds__(256, 2)
simgemm_multi_kernel(SimJobs jobs)
{
    SimJob jb = jobs.j[blockIdx.y];
    const int nBlk = jb.nBlk;
    int idx = blockIdx.x;
    if (idx >= nBlk * (nBlk + 1) / 2) return;
    const float* X = jb.X;
    float* C       = jb.C;
    float* csPart  = jb.cs;
    const int N = jb.N, K = jb.K;
    const float th = jb.th;

    float nb2 = nBlk + 0.5f;
    int by = (int)(nb2 - sqrtf(fmaxf(nb2 * nb2 - 2.0f * idx, 0.f)));
    if (by < 0) by = 0;
    if (by > nBlk - 1) by = nBlk - 1;
    while (by > 0 && (by * nBlk - (by * (by - 1)) / 2) > idx) by--;
    while (((by + 1) * nBlk - ((by + 1) * by) / 2) <= idx) by++;
    int bx = by + (idx - (by * nBlk - (by * (by - 1)) / 2));

    const int m0 = by * 128, n0 = bx * 128;

    __shared__ float As[2][16][128];
    __shared__ float Bs[2][16][128];

    const int tid = threadIdx.x;
    const int ldr = tid >> 2;
    const int ldc = (tid & 3) << 2;
    const int wrp = tid >> 5;
    const int ln  = tid & 31;
    const int ty  = ((wrp >> 1) << 2) | (ln >> 3);   // 0..15
    const int tx  = ((wrp & 1) << 3) | (ln & 7);     // 0..15
    const int ry  = ty << 3;
    const int rx  = tx << 3;

    u64t acc2[8][4];
    #pragma unroll
    for (int i = 0; i < 8; i++)
        #pragma unroll
        for (int j = 0; j < 4; j++) acc2[i][j] = 0ull;

    float4 a0, a1, b0, b1;

#define LOADG(k0) {                                                             \
    a0 = *(const float4*)(X + (size_t)(m0 + ldr)      * K + (k0) + ldc);        \
    a1 = *(const float4*)(X + (size_t)(m0 + ldr + 64) * K + (k0) + ldc);        \
    b0 = *(const float4*)(X + (size_t)(n0 + ldr)      * K + (k0) + ldc);        \
    b1 = *(const float4*)(X + (size_t)(n0 + ldr + 64) * K + (k0) + ldc); }

#define STORES(bf) {                                                            \
    As[bf][ldc+0][ldr]    = a0.x; As[bf][ldc+1][ldr]    = a0.y;                 \
    As[bf][ldc+2][ldr]    = a0.z; As[bf][ldc+3][ldr]    = a0.w;                 \
    As[bf][ldc+0][ldr+64] = a1.x; As[bf][ldc+1][ldr+64] = a1.y;                 \
    As[bf][ldc+2][ldr+64] = a1.z; As[bf][ldc+3][ldr+64] = a1.w;                 \
    Bs[bf][ldc+0][ldr]    = b0.x; Bs[bf][ldc+1][ldr]    = b0.y;                 \
    Bs[bf][ldc+2][ldr]    = b0.z; Bs[bf][ldc+3][ldr]    = b0.w;                 \
    Bs[bf][ldc+0][ldr+64] = b1.x; Bs[bf][ldc+1][ldr+64] = b1.y;                 \
    Bs[bf][ldc+2][ldr+64] = b1.z; Bs[bf][ldc+3][ldr+64] = b1.w; }

#define COMPUTE(bf) {                                                           \
    _Pragma("unroll")                                                           \
    for (int k = 0; k < 16; k++) {                                              \
        float4 av0 = *(const float4*)&As[bf][k][ry];                            \
        float4 av1 = *(const float4*)&As[bf][k][ry + 4];                        \
        float4 bv0 = *(const float4*)&Bs[bf][k][rx];                            \
        float4 bv1 = *(const float4*)&Bs[bf][k][rx + 4];                        \
        u64t bp[4];                                                             \
        bp[0] = ((const u64t*)&bv0)[0]; bp[1] = ((const u64t*)&bv0)[1];         \
        bp[2] = ((const u64t*)&bv1)[0]; bp[3] = ((const u64t*)&bv1)[1];         \
        float a[8] = {av0.x,av0.y,av0.z,av0.w,av1.x,av1.y,av1.z,av1.w};         \
        _Pragma("unroll")                                                       \
        for (int i = 0; i < 8; i++) {                                           \
            u64t ai = bcast2(a[i]);                                             \
            fma2(acc2[i][0], ai, bp[0]);                                        \
            fma2(acc2[i][1], ai, bp[1]);                                        \
            fma2(acc2[i][2], ai, bp[2]);                                        \
            fma2(acc2[i][3], ai, bp[3]);                                        \
        }                                                                       \
    } }

    LOADG(0);
    STORES(0);
    __syncthreads();
    int buf = 0;
    for (int k0 = 16; k0 < K; k0 += 16) {
        LOADG(k0);
        COMPUTE(buf);
        STORES(buf ^ 1);
        __syncthreads();
        buf ^= 1;
    }
    COMPUTE(buf);

#undef LOADG
#undef STORES
#undef COMPUTE

    float acc[8][8];
    #pragma unroll
    for (int i = 0; i < 8; i++)
        #pragma unroll
        for (int jp = 0; jp < 4; jp++) {
            float2 v = unpack2(acc2[i][jp]);
            acc[i][2 * jp + 0] = thrf(v.x, 0.5f, th);
            acc[i][2 * jp + 1] = thrf(v.y, 0.5f, th);
        }

    #pragma unroll
    for (int i = 0; i < 8; i++) {
        #pragma unroll
        for (int j = 0; j < 8; j += 4) {
            float4 v = make_float4(acc[i][j], acc[i][j+1], acc[i][j+2], acc[i][j+3]);
            *(float4*)(C + (size_t)(m0 + ry + i) * N + (n0 + rx + j)) = v;
        }
    }
    if (bx > by && jb.mirror) {
        #pragma unroll
        for (int j = 0; j < 8; j++) {
            #pragma unroll
            for (int i = 0; i < 8; i += 4) {
                float4 v = make_float4(acc[i][j], acc[i+1][j], acc[i+2][j], acc[i+3][j]);
                *(float4*)(C + (size_t)(n0 + rx + j) * N + (m0 + ry + i)) = v;
            }
        }
    }

    if (csPart) {
        __syncthreads();
        float* red = (float*)As;
        #pragma unroll
        for (int jj = 0; jj < 8; jj++) {
            float s = 0.f;
            #pragma unroll
            for (int i = 0; i < 8; i++) s += acc[i][jj];
            red[ty * 128 + rx + jj] = s;
        }
        __syncthreads();
        if (tid < 128) {
            float s = 0.f;
            #pragma unroll
            for (int p = 0; p < 16; p++) s += red[p * 128 + tid];
            csPart[(size_t)by * N + n0 + tid] = s;
        }
        if (bx > by) {
            __syncthreads();
            #pragma unroll
            for (int ii = 0; ii < 8; ii++) {
                float s = 0.f;
                #pragma unroll
                for (int j = 0; j < 8; j++) s += acc[ii][j];
                red[tx * 128 + ry + ii] = s;
            }
            __syncthreads();
            if (tid < 128) {
                float s = 0.f;
                #pragma unroll
                for (int p = 0; p < 16; p++) s += red[p * 128 + tid];
                csPart[(size_t)bx * N + m0 + tid] = s;
            }
        }
    }
}

__global__ void build_idx_kernel(const float* __restrict__ adj, int col_off, int NR,
                                 int* __restrict__ idx, int* __restrict__ cnt)
{
    __shared__ int sidx[4][CAP];
    __shared__ int scnt[4];
    int i = blockIdx.x;
    const float* r = adj + (size_t)i * NALL + col_off;
    int w = threadIdx.x >> 5, lane = threadIdx.x & 31;
    int seg = NR >> 2;
    int b0  = w * seg;
    int count = 0;
    for (int base = b0; base < b0 + seg; base += 32) {
        float v = r[base + lane];
        unsigned m = __ballot_sync(0xffffffffu, v != 0.f);
        int pre = __popc(m & ((1u << lane) - 1u));
        if (v != 0.f && (count + pre) < CAP) sidx[w][count + pre] = base + lane;
        count += __popc(m);
    }
    if (lane == 0) scnt[w] = min(count, CAP);
    __syncthreads();
    int myoff = 0, tot = 0;
    #pragma unroll
    for (int p = 0; p < 4; p++) {
        if (p < w) myoff += scnt[p];
        tot += scnt[p];
    }
    for (int t = lane; t < scnt[w]; t += 32) {
        int pos = myoff + t;
        if (pos < CAP) idx[(size_t)i * CAP + pos] = sidx[w][t];
    }
    if (threadIdx.x == 0) cnt[i] = min(tot, CAP);
}

__global__ void gather_sum_kernel(const float* __restrict__ src, int lds,
                                  const int* __restrict__ idx, const int* __restrict__ cnt,
                                  float* __restrict__ out, int ldo)
{
    int i = blockIdx.y;
    int j = ((blockIdx.x * blockDim.x + threadIdx.x) << 2);
    int c = cnt[i];
    const int* ip = idx + (size_t)i * CAP;
    float4 s = make_float4(0.f, 0.f, 0.f, 0.f);
    for (int t = 0; t < c; t++) {
        float4 v = *(const float4*)(src + (size_t)ip[t] * lds + j);
        s.x += v.x; s.y += v.y; s.z += v.z; s.w += v.w;
    }
    *(float4*)(out + (size_t)i * ldo + j) = s;
}

__global__ void gather64b_kernel(const float* __restrict__ src,
                                 const int* __restrict__ idx, const int* __restrict__ cnt,
                                 const float* __restrict__ bias, float* __restrict__ out)
{
    int i = blockIdx.x;
    int c = threadIdx.x;
    int n = cnt[i];
    const int* ip = idx + (size_t)i * CAP;
    float s = 0.f;
    for (int t = 0; t < n; t++) s += src[(size_t)ip[t] * 64 + c];
    out[(size_t)i * 64 + c] = s + bias[c];
}

// C[M,64] = A[M,K] @ B[K,64] (+bias) (optional relu) — 64x64 tile, for small K
__global__ void __launch_bounds__(256)
gemm_n64_kernel(const float* __restrict__ A, const float* __restrict__ B,
                const float* __restrict__ bias, float* __restrict__ C,
                int M, int K, int relu)
{
    __shared__ float As[32][64];
    __shared__ float Bs[32][64];
    int tid = threadIdx.x;
    int m0  = blockIdx.x * 64;
    int ar  = tid >> 3;
    int ac  = (tid & 7) << 2;
    int br  = tid >> 4;
    int bc  = (tid & 15) << 2;
    int wrp = tid >> 5, ln = tid & 31;
    int ty  = ((wrp >> 1) << 2) | (ln >> 3);
    int tx  = ((wrp & 1) << 3) | (ln & 7);

    u64t acc2[4][2];
    #pragma unroll
    for (int i = 0; i < 4; i++) { acc2[i][0] = 0ull; acc2[i][1] = 0ull; }

    for (int k0 = 0; k0 < K; k0 += 32) {
        float4 a0 = *(const float4*)(A + (size_t)(m0 + ar)      * K + k0 + ac);
        float4 a1 = *(const float4*)(A + (size_t)(m0 + ar + 32) * K + k0 + ac);
        float4 b0 = *(const float4*)(B + (size_t)(k0 + br)      * 64 + bc);
        float4 b1 = *(const float4*)(B + (size_t)(k0 + br + 16) * 64 + bc);
        __syncthreads();
        As[ac+0][ar]    = a0.x; As[ac+1][ar]    = a0.y; As[ac+2][ar]    = a0.z; As[ac+3][ar]    = a0.w;
        As[ac+0][ar+32] = a1.x; As[ac+1][ar+32] = a1.y; As[ac+2][ar+32] = a1.z; As[ac+3][ar+32] = a1.w;
        *(float4*)&Bs[br][bc]      = b0;
        *(float4*)&Bs[br + 16][bc] = b1;
        __syncthreads();
        #pragma unroll
        for (int k = 0; k < 32; k++) {
            float4 av = *(const float4*)&As[k][ty << 2];
            float4 bv = *(const float4*)&Bs[k][tx << 2];
            u64t bp0 = ((const u64t*)&bv)[0], bp1 = ((const u64t*)&bv)[1];
            float a[4] = {av.x, av.y, av.z, av.w};
            #pragma unroll
            for (int i = 0; i < 4; i++) {
                u64t ai = bcast2(a[i]);
                fma2(acc2[i][0], ai, bp0);
                fma2(acc2[i][1], ai, bp1);
            }
        }
    }
    int r = m0 + (ty << 2), c = tx << 2;
    #pragma unroll
    for (int i = 0; i < 4; i++) {
        float2 v0 = unpack2(acc2[i][0]);
        float2 v1 = unpack2(acc2[i][1]);
        float vv[4] = {v0.x, v0.y, v1.x, v1.y};
        #pragma unroll
        for (int j = 0; j < 4; j++) {
            float v = vv[j] + (bias ? bias[c + j] : 0.f);
            if (relu) v = fmaxf(v, 0.f);
            C[(size_t)(r + i) * 64 + c + j] = v;
        }
    }
}

// split-K GEMM, 128x64 tile, 8x4 per thread. grid (M/128, S).
__global__ void __launch_bounds__(256)
gemm128_splitk_kernel(const float* __restrict__ A, const float* __restrict__ B,
                      float* __restrict__ part, int M, int K, int Kc)
{
    __shared__ float As[32][128];
    __shared__ float Bs[32][64];
    int tid = threadIdx.x;
    int m0  = blockIdx.x * 128;
    int s   = blockIdx.y;
    int kb  = s * Kc, ke = kb + Kc;
    int ar  = tid >> 1;
    int ac  = (tid & 1) << 4;
    int br  = tid >> 3;
    int bc  = (tid & 7) << 2;
    int wrp = tid >> 5, ln = tid & 31;
    int ty  = ((wrp >> 1) << 2) | (ln >> 3);
    int tx  = ((wrp & 1) << 3) | (ln & 7);
    int ry  = ty << 3;
    int rxc = tx << 2;

    u64t acc2[8][2];
    #pragma unroll
    for (int i = 0; i < 8; i++) { acc2[i][0] = 0ull; acc2[i][1] = 0ull; }

    for (int k0 = kb; k0 < ke; k0 += 32) {
        float4 a[4];
        #pragma unroll
        for (int c = 0; c < 4; c++)
            a[c] = *(const float4*)(A + (size_t)(m0 + ar) * K + k0 + ac + (c << 2));
        float4 b0 = *(const float4*)(B + (size_t)(k0 + br) * 64 + bc);
        float4 b1 = *(const float4*)(B + (size_t)(k0 + br) * 64 + bc + 32);
        __syncthreads();
        #pragma unroll
        for (int c = 0; c < 4; c++) {
            As[ac + (c << 2) + 0][ar] = a[c].x;
            As[ac + (c << 2) + 1][ar] = a[c].y;
            As[ac + (c << 2) + 2][ar] = a[c].z;
            As[ac + (c << 2) + 3][ar] = a[c].w;
        }
        *(float4*)&Bs[br][bc]      = b0;
        *(float4*)&Bs[br][bc + 32] = b1;
        __syncthreads();
        #pragma unroll
        for (int k = 0; k < 32; k++) {
            float4 av0 = *(const float4*)&As[k][ry];
            float4 av1 = *(const float4*)&As[k][ry + 4];
            float4 bv  = *(const float4*)&Bs[k][rxc];
            u64t bp0 = ((const u64t*)&bv)[0], bp1 = ((const u64t*)&bv)[1];
            float aa[8] = {av0.x, av0.y, av0.z, av0.w, av1.x, av1.y, av1.z, av1.w};
            #pragma unroll
            for (int i = 0; i < 8; i++) {
                u64t ai = bcast2(aa[i]);
                fma2(acc2[i][0], ai, bp0);
                fma2(acc2[i][1], ai, bp1);
            }
        }
    }
    int r = m0 + ry;
    #pragma unroll
    for (int i = 0; i < 8; i++) {
        float2 v0 = unpack2(acc2[i][0]);
        float2 v1 = unpack2(acc2[i][1]);
        float4 v = make_float4(v0.x, v0.y, v1.x, v1.y);
        *(float4*)(part + (size_t)s * M * 64 + (size_t)(r + i) * 64 + rxc) = v;
    }
}

__global__ void splitk_reduce_kernel(const float* __restrict__ part, const float* __restrict__ bias,
                                     float* __restrict__ C, int M, int S, int relu)
{
    int idx = blockIdx.x * 256 + threadIdx.x;
    if (idx >= M * 64) return;
    float s = 0.f;
    for (int p = 0; p < S; p++) s += part[(size_t)p * M * 64 + idx];
    if (bias) s += bias[idx & 63];
    if (relu) s = fmaxf(s, 0.f);
    C[idx] = s;
}

__global__ void cs_reduce_kernel(const float* __restrict__ CSP, float* __restrict__ CS)
{
    int m = blockIdx.y;
    int j = blockIdx.x * 256 + threadIdx.x;
    float s = 0.f;
    #pragma unroll
    for (int p = 0; p < 32; p++) s += CSP[((size_t)m * 32 + p) * NT + j];
    CS[m * NT + j] = s;
}

__global__ void coefs_kernel(const float* __restrict__ sgw, const float* __restrict__ ffw,
                             const float* __restrict__ f4w,
                             const float* __restrict__ cs, float* __restrict__ coef)
{
    int j = blockIdx.x * 256 + threadIdx.x;
    float m2 = fmaxf(sgw[0], sgw[1]);
    float e0 = expf(sgw[0] - m2), e1 = expf(sgw[1] - m2);
    float sa0 = e0 / (e0 + e1), sa1 = e1 / (e0 + e1);
    float mf = fmaxf(ffw[0], ffw[1]);
    float f0 = expf(ffw[0] - mf), f1 = expf(ffw[1] - mf);
    float fa0 = f0 / (f0 + f1), fa1 = f1 / (f0 + f1);
    float m4 = fmaxf(fmaxf(f4w[0], f4w[1]), fmaxf(f4w[2], f4w[3]));
    float w0 = expf(f4w[0] - m4), w1 = expf(f4w[1] - m4), w2 = expf(f4w[2] - m4), w3 = expf(f4w[3] - m4);
    float ws = w0 + w1 + w2 + w3;
    w0 /= ws; w1 /= ws; w2 /= ws; w3 /= ws;

    float csv[7];
    #pragma unroll
    for (int m = 0; m < 7; m++) csv[m] = cs[m * NT + j];
    float uP  = (csv[1] > 0.05f) ? 1.f : 0.f;
    float uQ  = (csv[2] > 0.05f) ? 1.f : 0.f;
    float uFA = (csv[3] > 0.05f) ? 1.f : 0.f;
    float uFS = (csv[4] > 0.05f) ? 1.f : 0.f;
    float uSA = (csv[5] > 0.05f) ? 1.f : 0.f;
    float uSS = (csv[6] > 0.05f) ? 1.f : 0.f;
    float dSem = fmaxf(sa0 * uP  + sa1 * uQ,  1e-12f);
    float dFp  = fmaxf(fa0 * uFA + fa1 * uFS, 1e-12f);
    float dSt  = fmaxf(fa0 * uSA + fa1 * uSS, 1e-12f);

    coef[0 * NT + j] = w0 / fmaxf(csv[0], 1e-12f);
    coef[1 * NT + j] = w1 * sa0 / (fmaxf(csv[1], 1e-12f) * dSem);
    coef[2 * NT + j] = w1 * sa1 / (fmaxf(csv[2], 1e-12f) * dSem);
    coef[3 * NT + j] = w2 * fa0 / (fmaxf(csv[3], 1e-12f) * dFp);
    coef[4 * NT + j] = w2 * fa1 / (fmaxf(csv[4], 1e-12f) * dFp);
    coef[5 * NT + j] = w3 * fa0 / (fmaxf(csv[5], 1e-12f) * dSt);
    coef[6 * NT + j] = w3 * fa1 / (fmaxf(csv[6], 1e-12f) * dSt);
}

// Triangular symmetric combine: processes 64x64 tiles with bi<=bj only; the
// base matrices are symmetric (only their upper tiles are stored), and
// S[i][j] = sum_m (cf_m[i]+cf_m[j]) * M_m[i,j] = S[j][i], so the computed tile
// is written to both (bi,bj) and smem-transposed to (bj,bi). Row-sum partials
// go to part[otherBlock][globalRow] (each slot written by exactly one tile).
__global__ void __launch_bounds__(256)
combine_tri_kernel(const float* __restrict__ G,  const float* __restrict__ P,
                   const float* __restrict__ Q,  const float* __restrict__ FA,
                   const float* __restrict__ FS, const float* __restrict__ SA,
                   const float* __restrict__ SS, const float* __restrict__ coef,
                   float* __restrict__ out, float* __restrict__ part)
{
    const int nb = 64;
    int idx = blockIdx.x;
    float nb2 = nb + 0.5f;
    int bi = (int)(nb2 - sqrtf(fmaxf(nb2 * nb2 - 2.0f * idx, 0.f)));
    if (bi < 0) bi = 0;
    if (bi > nb - 1) bi = nb - 1;
    while (bi > 0 && (bi * nb - (bi * (bi - 1)) / 2) > idx) bi--;
    while (((bi + 1) * nb - ((bi + 1) * bi) / 2) <= idx) bi++;
    int bj = bi + (idx - (bi * nb - (bi * (bi - 1)) / 2));

    __shared__ float S[64][65];
    int row = threadIdx.x >> 2;          // 0..63
    int cc  = (threadIdx.x & 3) << 4;    // 0,16,32,48
    int gi  = bi * 64 + row;
    int gj  = bj * 64 + cc;

    float cfi[7];
    #pragma unroll
    for (int m = 0; m < 7; m++) cfi[m] = coef[m * NT + gi];

    float rsum = 0.f;
    #pragma unroll
    for (int c4 = 0; c4 < 16; c4 += 4) {
        size_t e = (size_t)gi * NT + gj + c4;
        float4 r = make_float4(0.f, 0.f, 0.f, 0.f);
#define ACC(buf, m) { float4 v = *(const float4*)((buf) + e);                     \
                      float4 k = *(const float4*)(coef + (m) * NT + gj + c4);     \
                      r.x = fmaf(k.x + cfi[m], v.x, r.x);                         \
                      r.y = fmaf(k.y + cfi[m], v.y, r.y);                         \
                      r.z = fmaf(k.z + cfi[m], v.z, r.z);                         \
                      r.w = fmaf(k.w + cfi[m], v.w, r.w); }
        ACC(G, 0) ACC(P, 1) ACC(Q, 2) ACC(FA, 3) ACC(FS, 4) ACC(SA, 5) ACC(SS, 6)
#undef ACC
        *(float4*)(out + e) = r;
        S[row][cc + c4 + 0] = r.x;
        S[row][cc + c4 + 1] = r.y;
        S[row][cc + c4 + 2] = r.z;
        S[row][cc + c4 + 3] = r.w;
        rsum += r.x + r.y + r.z + r.w;
    }
    rsum += __shfl_xor_sync(0xffffffffu, rsum, 1);
    rsum += __shfl_xor_sync(0xffffffffu, rsum, 2);
    if ((threadIdx.x & 3) == 0)
        part[(size_t)bj * NT + gi] = rsum;

    if (bi != bj) {
        __syncthreads();
        float csum = 0.f;
        #pragma unroll
        for (int c4 = 0; c4 < 16; c4 += 4) {
            float4 v = make_float4(S[cc + c4 + 0][row], S[cc + c4 + 1][row],
                                   S[cc + c4 + 2][row], S[cc + c4 + 3][row]);
            *(float4*)(out + (size_t)(bj * 64 + row) * NT + bi * 64 + cc + c4) = v;
            csum += v.x + v.y + v.z + v.w;
        }
        csum += __shfl_xor_sync(0xffffffffu, csum, 1);
        csum += __shfl_xor_sync(0xffffffffu, csum, 2);
        if ((threadIdx.x & 3) == 0)
            part[(size_t)bi * NT + bj * 64 + row] = csum;
    }
}

__global__ void ct_reduce_kernel(const float* __restrict__ part, float* __restrict__ ct)
{
    int j = blockIdx.x * 256 + threadIdx.x;
    float s = 0.f;
    #pragma unroll
    for (int p = 0; p < 64; p++) s += part[(size_t)p * NT + j];
    ct[j] = s;
}

__global__ void scale_cols_kernel(float* __restrict__ A, const float* __restrict__ ct)
{
    size_t e = ((size_t)blockIdx.x * 256 + threadIdx.x) << 2;
    int j = (int)(e & (NT - 1));
    float4 v = *(float4*)(A + e);
    float4 c = *(const float4*)(ct + j);
    v.x /= fmaxf(c.x, 1e-12f); v.y /= fmaxf(c.y, 1e-12f);
    v.z /= fmaxf(c.z, 1e-12f); v.w /= fmaxf(c.w, 1e-12f);
    *(float4*)(A + e) = v;
}

__global__ void x1w2_kernel(const float* __restrict__ X1, const float* __restrict__ W2,
                            float* __restrict__ H2)
{
    int i = blockIdx.x * 256 + threadIdx.x;
    if (i >= NT) return;
    float s0 = 0.f, s1 = 0.f, s2 = 0.f;
    #pragma unroll 8
    for (int k = 0; k < COM; k++) {
        float x = X1[(size_t)i * COM + k];
        s0 = fmaf(x, W2[k * 3 + 0], s0);
        s1 = fmaf(x, W2[k * 3 + 1], s1);
        s2 = fmaf(x, W2[k * 3 + 2], s2);
    }
    H2[i * 3 + 0] = s0; H2[i * 3 + 1] = s1; H2[i * 3 + 2] = s2;
}

__global__ void logits_kernel(const float* __restrict__ A, const float* __restrict__ H2,
                              const float* __restrict__ b2, float* __restrict__ out)
{
    int i = blockIdx.x, tid = threadIdx.x;
    const float* row = A + (size_t)i * NT;
    float s0 = 0.f, s1 = 0.f, s2 = 0.f;
    for (int k = tid; k < NT; k += 256) {
        float a = row[k];
        s0 = fmaf(a, H2[k * 3 + 0], s0);
        s1 = fmaf(a, H2[k * 3 + 1], s1);
        s2 = fmaf(a, H2[k * 3 + 2], s2);
    }
    #pragma unroll
    for (int o = 16; o; o >>= 1) {
        s0 += __shfl_xor_sync(0xffffffffu, s0, o);
        s1 += __shfl_xor_sync(0xffffffffu, s1, o);
        s2 += __shfl_xor_sync(0xffffffffu, s2, o);
    }
    __shared__ float sh[3][8];
    int w = tid >> 5, l = tid & 31;
    if (l == 0) { sh[0][w] = s0; sh[1][w] = s1; sh[2][w] = s2; }
    __syncthreads();
    if (tid == 0) {
        float x0 = 0.f, x1 = 0.f, x2 = 0.f;
        #pragma unroll
        for (int t = 0; t < 8; t++) { x0 += sh[0][t]; x1 += sh[1][t]; x2 += sh[2][t]; }
        x0 += b2[0]; x1 += b2[1]; x2 += b2[2];
        float m  = fmaxf(x0, fmaxf(x1, x2));
        float ls = logf(expf(x0 - m) + expf(x1 - m) + expf(x2 - m));
        out[i * 3 + 0] = x0 - m - ls;
        out[i * 3 + 1] = x1 - m - ls;
        out[i * 3 + 2] = x2 - m - ls;
    }
}

// ---------------- host orchestration (single stream) -------------------------

extern "C" void kernel_launch(void* const* d_in, const int* in_sizes, int n_in,
                              void* d_out, int out_size)
{
    const float* features  = (const float*)d_in[0];
    const float* adj_ori   = (const float*)d_in[1];
    const float* mp_pap    = (const float*)d_in[2];
    const float* mp_psp    = (const float*)d_in[3];
    const float* fgo_w     = (const float*)d_in[6];
    const float* fpo_w     = (const float*)d_in[7];
    const float* sgg_pap_w = (const float*)d_in[8];
    const float* sgg_psp_w = (const float*)d_in[9];
    const float* sg_agg_w  = (const float*)d_in[10];
    const float* f_agg_f_w = (const float*)d_in[11];
    const float* f_agg_w   = (const float*)d_in[12];
    const float* topo_W_a  = (const float*)d_in[13];
    const float* topo_b_a  = (const float*)d_in[14];
    const float* topo_W_s  = (const float*)d_in[15];
    const float* topo_b_s  = (const float*)d_in[16];
    const float* fgt_w_a   = (const float*)d_in[17];
    const float* fgt_w_s   = (const float*)d_in[18];
    const float* gcn_W1    = (const float*)d_in[19];
    const float* gcn_b1    = (const float*)d_in[20];
    const float* gcn_W2    = (const float*)d_in[21];
    const float* gcn_b2    = (const float*)d_in[22];
    (void)in_sizes; (void)n_in; (void)out_size;

    float* out   = (float*)d_out;
    float* NAdj  = out + (size_t)NT * NCLS;

    float* big = nullptr; float* sm = nullptr; int* ib = nullptr;
    cudaGetSymbolAddress((void**)&big, g_big);
    cudaGetSymbolAddress((void**)&sm,  g_small);
    cudaGetSymbolAddress((void**)&ib,  g_ibuf);

    float* G   = big + 0ll * NT * NT;
    float* P   = big + 1ll * NT * NT;
    float* Q   = big + 2ll * NT * NT;
    float* FAb = big + 3ll * NT * NT;
    float* FSb = big + 4ll * NT * NT;
    float* SAb = big + 5ll * NT * NT;   // sim_r_A (full), then s_h_A (triangular)
    float* SSb = big + 6ll * NT * NT;

    float* XN0   = sm + OFF_XN0;
    float* XN1   = sm + OFF_XN1;
    float* XN2   = sm + OFF_XN2;
    float* XN3   = sm + OFF_XN3;
    float* XN4   = sm + OFF_XN4;
    float* XN5   = sm + OFF_XN5;
    float* XN6   = sm + OFF_XN6;
    float* SIMS  = sm + OFF_SIMS;
    float* FPA   = sm + OFF_FPA;
    float* FPS   = sm + OFF_FPS;
    float* THA   = sm + OFF_THA;
    float* THS   = sm + OFF_THS;
    float* SWA   = sm + OFF_SWA;
    float* SWS   = sm + OFF_SWS;
    float* H0    = sm + OFF_H0;
    float* X1    = sm + OFF_X1;
    float* H2    = sm + OFF_H2;
    float* CS    = sm + OFF_CS;
    float* COEF  = sm + OFF_COEF;
    float* CT    = sm + OFF_CT;
    float* PART2 = sm + OFF_PART2;
    float* CSP   = sm + OFF_CSP;
    float* SPART = sm + OFF_SPART;

    int* IDXA = ib + OFF_IDXA; int* CNTA = ib + OFF_CNTA;
    int* IDXS = ib + OFF_IDXS; int* CNTS = ib + OFF_CNTS;

    const int TRI32 = 32 * 33 / 2;   // 528
    const int TRI64 = 64 * 65 / 2;   // 2080

    // ---- adjacency index lists + feature propagation (independent of sims) ----
    build_idx_kernel<<<NT, 128>>>(adj_ori, NT, NAr, IDXA, CNTA);
    build_idx_kernel<<<NT, 128>>>(adj_ori, NT + NAr, NSr, IDXS, CNTS);
    gather_sum_kernel<<<dim3(1, NT), 32>>>(features + (size_t)NT * FEAT, FEAT, IDXA, CNTA, FPA, FEAT);
    gather_sum_kernel<<<dim3(1, NT), 32>>>(features + (size_t)(NT + NAr) * FEAT, FEAT, IDXS, CNTS, FPS, FEAT);

    // ---- prep batch A: 7 jobs ----
    {
        PrepJobs pj;
        pj.j[0] = {features,                              fgo_w,     XN0, NT,  FEAT};
        pj.j[1] = {features + (size_t)NT * FEAT,          fgo_w,     XN1, NAr, FEAT};
        pj.j[2] = {mp_pap,                                sgg_pap_w, XN2, NT,  MPD};
        pj.j[3] = {mp_psp,                                sgg_psp_w, XN3, NT,  MPD};
        pj.j[4] = {features + (size_t)(NT + NAr) * FEAT,  fgo_w,     XN4, NSr, FEAT};
        pj.j[5] = {FPA,                                   fpo_w,     XN5, NT,  FEAT};
        pj.j[6] = {FPS,                                   fpo_w,     XN6, NT,  FEAT};
        prep_norm_multi_kernel<<<dim3(NT / 4, 7), 128>>>(pj);
    }

    // ---- sim batch 1: G, sim_r_A, P, Q, sim_r_S, f_h_A, f_h_S ----
    {
        SimJobs sj;
        sj.j[0] = {XN0, G,    CSP + 0ll * 32 * NT, NT,  256, 32, 0.1f, 0};
        sj.j[1] = {XN1, SAb,  nullptr,             NT,  256, 32, 0.1f, 1};  // GEMM reads full
        sj.j[2] = {XN2, P,    CSP + 1ll * 32 * NT, NT,  128, 32, 0.1f, 0};
        sj.j[3] = {XN3, Q,    CSP + 2ll * 32 * NT, NT,  128, 32, 0.1f, 0};
        sj.j[4] = {XN4, SIMS, nullptr,             NSr, 256, 8,  0.1f, 1};  // GEMM reads full
        sj.j[5] = {XN5, FAb,  CSP + 3ll * 32 * NT, NT,  256, 32, 0.2f, 0};
        sj.j[6] = {XN6, FSb,  CSP + 4ll * 32 * NT, NT,  256, 32, 0.2f, 0};
        simgemm_multi_kernel<<<dim3(TRI32, 7), 256>>>(sj);
    }

    // ---- topo chains (A then S) ----
    gemm128_splitk_kernel<<<dim3(NT / 128, 8), 256>>>(SAb, topo_W_a, SPART, NT, NAr, NAr / 8);
    splitk_reduce_kernel<<<(NT * 64) / 256, 256>>>(SPART, nullptr, SWA, NT, 8, 0);
    gather64b_kernel<<<NT, 64>>>(SWA, IDXA, CNTA, topo_b_a, THA);
    gemm128_splitk_kernel<<<dim3(NSr / 128, 8), 256>>>(SIMS, topo_W_s, SPART, NSr, NSr, NSr / 8);
    splitk_reduce_kernel<<<(NSr * 64) / 256, 256>>>(SPART, nullptr, SWS, NSr, 8, 0);
    gather64b_kernel<<<NT, 64>>>(SWS, IDXS, CNTS, topo_b_s, THS);

    // ---- prep batch B: 2 jobs ----
    {
        PrepJobs pj;
        pj.j[0] = {THA, fgt_w_a, XN2, NT, COM};
        pj.j[1] = {THS, fgt_w_s, XN3, NT, COM};
        for (int t = 2; t < 7; t++) pj.j[t] = {THA, fgt_w_a, XN2, 0, COM};
        prep_norm_multi_kernel<<<dim3(NT / 4, 2), 128>>>(pj);
    }

    // ---- sim batch 2: s_h_A, s_h_S (triangular-only stores) ----
    {
        SimJobs sj;
        sj.j[0] = {XN2, SAb, CSP + 5ll * 32 * NT, NT, 128, 32, 0.1f, 0};
        sj.j[1] = {XN3, SSb, CSP + 6ll * 32 * NT, NT, 128, 32, 0.1f, 0};
        for (int t = 2; t < 7; t++) sj.j[t] = {XN2, SAb, nullptr, 0, 16, 0, 0.1f, 0};
        simgemm_multi_kernel<<<dim3(TRI32, 2), 256>>>(sj);
    }

    // ---- GCN first half (independent) ----
    gemm_n64_kernel<<<NT / 64, 256>>>(features, gcn_W1, nullptr, H0, NT, FEAT, 0);

    // ---- fused channel attention (triangular symmetric combine) ----
    cs_reduce_kernel<<<dim3(NT / 256, 7), 256>>>(CSP, CS);
    coefs_kernel<<<NT / 256, 256>>>(sg_agg_w, f_agg_f_w, f_agg_w, CS, COEF);
    combine_tri_kernel<<<TRI64, 256>>>(G, P, Q, FAb, FSb, SAb, SSb, COEF, NAdj, PART2);
    ct_reduce_kernel<<<NT / 256, 256>>>(PART2, CT);
    scale_cols_kernel<<<(NT * NT) / 1024, 256>>>(NAdj, CT);

    // ---- GCN second half ----
    gemm128_splitk_kernel<<<dim3(NT / 128, 8), 256>>>(NAdj, H0, SPART, NT, NT, NT / 8);
    splitk_reduce_kernel<<<(NT * 64) / 256, 256>>>(SPART, gcn_b1, X1, NT, 8, 1);
    x1w2_kernel<<<NT / 256, 256>>>(X1, gcn_W2, H2);
    logits_kernel<<<NT, 256>>>(NAdj, H2, gcn_b2, out);
}